// round 1
// baseline (speedup 1.0000x reference)
#include <cuda_runtime.h>
#include <math.h>

// Problem constants
#define B_SZ   2
#define L_SZ   2048
#define D_SZ   1024
#define H_SZ   16
#define DH_SZ  64
#define E3_SZ  3072                 // 3*D
#define MTOK   (B_SZ * L_SZ)        // 4096
#define BH_SZ  (B_SZ * H_SZ)        // 32

// Scratch (device globals; allocation is forbidden)
__device__ float g_qkv[(size_t)MTOK * E3_SZ];    // [4096, 3072]
__device__ float g_phase[(size_t)BH_SZ * L_SZ];  // [bh, l]
__device__ float g_o[(size_t)MTOK * D_SZ];       // [4096, 1024] (heads concat)

// ---------------------------------------------------------------------------
// Generic C[M,N] = A[M,K] * B[N,K]^T + bias[N]   (both operands K-major)
// 64x64 tile, KT=16, 256 threads, 4x4 per thread
// ---------------------------------------------------------------------------
__global__ __launch_bounds__(256) void gemm_abt_kernel(
    const float* __restrict__ A, const float* __restrict__ Bm,
    const float* __restrict__ bias, float* __restrict__ C,
    int M, int N, int K)
{
    __shared__ float As[64][17];
    __shared__ float Bs[64][17];

    const int tm = blockIdx.y * 64;
    const int tn = blockIdx.x * 64;
    const int tid = threadIdx.x;
    const int ty = tid >> 4;       // 0..15
    const int tx = tid & 15;       // 0..15

    float acc[4][4];
#pragma unroll
    for (int i = 0; i < 4; ++i)
#pragma unroll
        for (int j = 0; j < 4; ++j) acc[i][j] = 0.f;

    const int r  = tid >> 2;            // 0..63
    const int c4 = (tid & 3) << 2;      // 0,4,8,12

    for (int k0 = 0; k0 < K; k0 += 16) {
        float4 av = *(const float4*)(A  + (size_t)(tm + r) * K + k0 + c4);
        float4 bv = *(const float4*)(Bm + (size_t)(tn + r) * K + k0 + c4);
        As[r][c4 + 0] = av.x; As[r][c4 + 1] = av.y;
        As[r][c4 + 2] = av.z; As[r][c4 + 3] = av.w;
        Bs[r][c4 + 0] = bv.x; Bs[r][c4 + 1] = bv.y;
        Bs[r][c4 + 2] = bv.z; Bs[r][c4 + 3] = bv.w;
        __syncthreads();
#pragma unroll
        for (int kk = 0; kk < 16; ++kk) {
            float a0 = As[ty * 4 + 0][kk];
            float a1 = As[ty * 4 + 1][kk];
            float a2 = As[ty * 4 + 2][kk];
            float a3 = As[ty * 4 + 3][kk];
            float b0 = Bs[tx * 4 + 0][kk];
            float b1 = Bs[tx * 4 + 1][kk];
            float b2 = Bs[tx * 4 + 2][kk];
            float b3 = Bs[tx * 4 + 3][kk];
            acc[0][0] += a0 * b0; acc[0][1] += a0 * b1; acc[0][2] += a0 * b2; acc[0][3] += a0 * b3;
            acc[1][0] += a1 * b0; acc[1][1] += a1 * b1; acc[1][2] += a1 * b2; acc[1][3] += a1 * b3;
            acc[2][0] += a2 * b0; acc[2][1] += a2 * b1; acc[2][2] += a2 * b2; acc[2][3] += a2 * b3;
            acc[3][0] += a3 * b0; acc[3][1] += a3 * b1; acc[3][2] += a3 * b2; acc[3][3] += a3 * b3;
        }
        __syncthreads();
    }

    const float4 bb = *(const float4*)(bias + tn + tx * 4);
#pragma unroll
    for (int i = 0; i < 4; ++i) {
        float4 o;
        o.x = acc[i][0] + bb.x;
        o.y = acc[i][1] + bb.y;
        o.z = acc[i][2] + bb.z;
        o.w = acc[i][3] + bb.w;
        *(float4*)(C + (size_t)(tm + ty * 4 + i) * N + tn + tx * 4) = o;
    }
}

// ---------------------------------------------------------------------------
// phase_val[bh, l] = tanh(ps * (x[b,l,:] . phase_w[h,:] + phase_b[h]))
// one block per (b,l); 512 threads = 16 head-warps
// ---------------------------------------------------------------------------
__global__ __launch_bounds__(512) void phase_kernel(
    const float* __restrict__ x, const float* __restrict__ pw,
    const float* __restrict__ pb, const float* __restrict__ ps_ptr)
{
    const int bl = blockIdx.x;              // 0..4095
    const int b  = bl >> 11;
    const int l  = bl & 2047;
    __shared__ float xs[1024];
    const int tid = threadIdx.x;
    for (int i = tid; i < 1024; i += 512) xs[i] = x[(size_t)bl * 1024 + i];
    __syncthreads();
    const int h = tid >> 5, lane = tid & 31;
    float s = 0.f;
    const float* w = pw + (size_t)h * 1024;
    for (int d = lane; d < 1024; d += 32) s += xs[d] * w[d];
#pragma unroll
    for (int o = 16; o; o >>= 1) s += __shfl_xor_sync(0xffffffff, s, o);
    if (lane == 0) {
        float ps = *ps_ptr;
        g_phase[(size_t)(b * H_SZ + h) * L_SZ + l] = tanhf(ps * (s + pb[h]));
    }
}

// ---------------------------------------------------------------------------
// scores[bh, i, j] = (q_i . k_j)/8 - rs*(pv_i - pv_j)^2   (raw, pre-softmax)
// grid: (n_tile=32, m_tile=32, bh=32); 64x64 tile, K=dh=64 in one shot
// ---------------------------------------------------------------------------
__global__ __launch_bounds__(256) void scores_kernel(
    const float* __restrict__ rs_ptr, float* __restrict__ attn)
{
    const int bh = blockIdx.z;
    const int b  = bh >> 4, h = bh & 15;
    const int tm = blockIdx.y * 64;
    const int tn = blockIdx.x * 64;

    const float* qb = g_qkv + (size_t)b * L_SZ * E3_SZ + h * DH_SZ;
    const float* kb = qb + D_SZ;

    __shared__ float Qs[64][65];
    __shared__ float Ks[64][65];
    __shared__ float pq[64], pk[64];

    const int tid = threadIdx.x;
#pragma unroll
    for (int rr = 0; rr < 4; ++rr) {
        int f   = tid + rr * 256;
        int row = f >> 4;
        int c4  = (f & 15) << 2;
        float4 qv = *(const float4*)(qb + (size_t)(tm + row) * E3_SZ + c4);
        float4 kv = *(const float4*)(kb + (size_t)(tn + row) * E3_SZ + c4);
        Qs[row][c4 + 0] = qv.x; Qs[row][c4 + 1] = qv.y;
        Qs[row][c4 + 2] = qv.z; Qs[row][c4 + 3] = qv.w;
        Ks[row][c4 + 0] = kv.x; Ks[row][c4 + 1] = kv.y;
        Ks[row][c4 + 2] = kv.z; Ks[row][c4 + 3] = kv.w;
    }
    if (tid < 64)                 pq[tid]      = g_phase[(size_t)bh * L_SZ + tm + tid];
    else if (tid < 128)           pk[tid - 64] = g_phase[(size_t)bh * L_SZ + tn + tid - 64];
    __syncthreads();

    const int ty = tid >> 4, tx = tid & 15;
    float acc[4][4];
#pragma unroll
    for (int i = 0; i < 4; ++i)
#pragma unroll
        for (int j = 0; j < 4; ++j) acc[i][j] = 0.f;

#pragma unroll
    for (int d = 0; d < 64; ++d) {
        float a0 = Qs[ty * 4 + 0][d];
        float a1 = Qs[ty * 4 + 1][d];
        float a2 = Qs[ty * 4 + 2][d];
        float a3 = Qs[ty * 4 + 3][d];
        float b0 = Ks[tx * 4 + 0][d];
        float b1 = Ks[tx * 4 + 1][d];
        float b2 = Ks[tx * 4 + 2][d];
        float b3 = Ks[tx * 4 + 3][d];
        acc[0][0] += a0 * b0; acc[0][1] += a0 * b1; acc[0][2] += a0 * b2; acc[0][3] += a0 * b3;
        acc[1][0] += a1 * b0; acc[1][1] += a1 * b1; acc[1][2] += a1 * b2; acc[1][3] += a1 * b3;
        acc[2][0] += a2 * b0; acc[2][1] += a2 * b1; acc[2][2] += a2 * b2; acc[2][3] += a2 * b3;
        acc[3][0] += a3 * b0; acc[3][1] += a3 * b1; acc[3][2] += a3 * b2; acc[3][3] += a3 * b3;
    }

    const float rs = *rs_ptr;
    const float scale = 0.125f;    // 1/sqrt(64)
    float* outp = attn + ((size_t)bh * L_SZ + tm) * L_SZ + tn;
#pragma unroll
    for (int i = 0; i < 4; ++i) {
        float pvi = pq[ty * 4 + i];
        float4 o;
        float d0 = pvi - pk[tx * 4 + 0];
        float d1 = pvi - pk[tx * 4 + 1];
        float d2 = pvi - pk[tx * 4 + 2];
        float d3 = pvi - pk[tx * 4 + 3];
        o.x = acc[i][0] * scale - rs * d0 * d0;
        o.y = acc[i][1] * scale - rs * d1 * d1;
        o.z = acc[i][2] * scale - rs * d2 * d2;
        o.w = acc[i][3] * scale - rs * d3 * d3;
        *(float4*)(outp + (size_t)(ty * 4 + i) * L_SZ + tx * 4) = o;
    }
}

// ---------------------------------------------------------------------------
// In-place row softmax over 2048 elements; one block per row
// ---------------------------------------------------------------------------
__global__ __launch_bounds__(256) void softmax_kernel(float* __restrict__ attn)
{
    float* p = attn + (size_t)blockIdx.x * 2048;
    const int tid = threadIdx.x;
    float4 v0 = *(float4*)(p + tid * 8);
    float4 v1 = *(float4*)(p + tid * 8 + 4);

    __shared__ float red[256];
    float m = fmaxf(fmaxf(fmaxf(v0.x, v0.y), fmaxf(v0.z, v0.w)),
                    fmaxf(fmaxf(v1.x, v1.y), fmaxf(v1.z, v1.w)));
    red[tid] = m;
    __syncthreads();
    for (int s = 128; s > 0; s >>= 1) {
        if (tid < s) red[tid] = fmaxf(red[tid], red[tid + s]);
        __syncthreads();
    }
    const float bm = red[0];
    __syncthreads();

    v0.x = __expf(v0.x - bm); v0.y = __expf(v0.y - bm);
    v0.z = __expf(v0.z - bm); v0.w = __expf(v0.w - bm);
    v1.x = __expf(v1.x - bm); v1.y = __expf(v1.y - bm);
    v1.z = __expf(v1.z - bm); v1.w = __expf(v1.w - bm);
    float s8 = (v0.x + v0.y + v0.z + v0.w) + (v1.x + v1.y + v1.z + v1.w);
    red[tid] = s8;
    __syncthreads();
    for (int s = 128; s > 0; s >>= 1) {
        if (tid < s) red[tid] += red[tid + s];
        __syncthreads();
    }
    const float inv = 1.0f / red[0];

    v0.x *= inv; v0.y *= inv; v0.z *= inv; v0.w *= inv;
    v1.x *= inv; v1.y *= inv; v1.z *= inv; v1.w *= inv;
    *(float4*)(p + tid * 8)     = v0;
    *(float4*)(p + tid * 8 + 4) = v1;
}

// ---------------------------------------------------------------------------
// O[b, i, h*64+d] = sum_j P[bh,i,j] * V[bh,j,d]
// grid: (m_tile=32, bh=32); 64(m) x 64(n=dh) tile, k-step 64
// ---------------------------------------------------------------------------
__global__ __launch_bounds__(256) void av_kernel(const float* __restrict__ attn)
{
    const int bh = blockIdx.y;
    const int b  = bh >> 4, h = bh & 15;
    const int tm = blockIdx.x * 64;

    const float* P  = attn + (size_t)bh * L_SZ * L_SZ;
    const float* vb = g_qkv + (size_t)b * L_SZ * E3_SZ + 2 * D_SZ + h * DH_SZ;

    __shared__ float Ps[64][65];
    __shared__ float Vs[64][65];

    const int tid = threadIdx.x;
    const int ty = tid >> 4, tx = tid & 15;
    float acc[4][4];
#pragma unroll
    for (int i = 0; i < 4; ++i)
#pragma unroll
        for (int j = 0; j < 4; ++j) acc[i][j] = 0.f;

    for (int k0 = 0; k0 < L_SZ; k0 += 64) {
#pragma unroll
        for (int rr = 0; rr < 4; ++rr) {
            int f   = tid + rr * 256;
            int row = f >> 4;
            int c4  = (f & 15) << 2;
            float4 pv = *(const float4*)(P  + (size_t)(tm + row) * L_SZ + k0 + c4);
            float4 vv = *(const float4*)(vb + (size_t)(k0 + row) * E3_SZ + c4);
            Ps[row][c4 + 0] = pv.x; Ps[row][c4 + 1] = pv.y;
            Ps[row][c4 + 2] = pv.z; Ps[row][c4 + 3] = pv.w;
            Vs[row][c4 + 0] = vv.x; Vs[row][c4 + 1] = vv.y;
            Vs[row][c4 + 2] = vv.z; Vs[row][c4 + 3] = vv.w;
        }
        __syncthreads();
#pragma unroll
        for (int kk = 0; kk < 64; ++kk) {
            float a0 = Ps[ty * 4 + 0][kk];
            float a1 = Ps[ty * 4 + 1][kk];
            float a2 = Ps[ty * 4 + 2][kk];
            float a3 = Ps[ty * 4 + 3][kk];
            float b0 = Vs[kk][tx * 4 + 0];
            float b1 = Vs[kk][tx * 4 + 1];
            float b2 = Vs[kk][tx * 4 + 2];
            float b3 = Vs[kk][tx * 4 + 3];
            acc[0][0] += a0 * b0; acc[0][1] += a0 * b1; acc[0][2] += a0 * b2; acc[0][3] += a0 * b3;
            acc[1][0] += a1 * b0; acc[1][1] += a1 * b1; acc[1][2] += a1 * b2; acc[1][3] += a1 * b3;
            acc[2][0] += a2 * b0; acc[2][1] += a2 * b1; acc[2][2] += a2 * b2; acc[2][3] += a2 * b3;
            acc[3][0] += a3 * b0; acc[3][1] += a3 * b1; acc[3][2] += a3 * b2; acc[3][3] += a3 * b3;
        }
        __syncthreads();
    }

#pragma unroll
    for (int i = 0; i < 4; ++i) {
        float4 o;
        o.x = acc[i][0]; o.y = acc[i][1]; o.z = acc[i][2]; o.w = acc[i][3];
        *(float4*)(g_o + (size_t)(b * L_SZ + tm + ty * 4 + i) * D_SZ + h * DH_SZ + tx * 4) = o;
    }
}

// ---------------------------------------------------------------------------
extern "C" void kernel_launch(void* const* d_in, const int* in_sizes, int n_in,
                              void* d_out, int out_size)
{
    const float* x      = (const float*)d_in[0];
    const float* qkv_w  = (const float*)d_in[1];
    const float* qkv_b  = (const float*)d_in[2];
    const float* out_w  = (const float*)d_in[3];
    const float* out_b  = (const float*)d_in[4];
    const float* ph_w   = (const float*)d_in[5];
    const float* ph_b   = (const float*)d_in[6];
    const float* rs_ptr = (const float*)d_in[7];
    const float* ps_ptr = (const float*)d_in[8];

    float* out_proj = (float*)d_out;                                   // [2,2048,1024]
    float* attn     = out_proj + (size_t)MTOK * D_SZ;                  // [2,16,2048,2048]

    float *qkv_ptr, *o_ptr;
    cudaGetSymbolAddress((void**)&qkv_ptr, g_qkv);
    cudaGetSymbolAddress((void**)&o_ptr,  g_o);

    // 1) fused QKV projection: [4096,3072] = x[4096,1024] . qkv_w[3072,1024]^T + b
    gemm_abt_kernel<<<dim3(E3_SZ / 64, MTOK / 64), 256>>>(
        x, qkv_w, qkv_b, qkv_ptr, MTOK, E3_SZ, D_SZ);

    // 2) per-head phase values
    phase_kernel<<<MTOK, 512>>>(x, ph_w, ph_b, ps_ptr);

    // 3) raw biased scores into attn buffer
    scores_kernel<<<dim3(L_SZ / 64, L_SZ / 64, BH_SZ), 256>>>(rs_ptr, attn);

    // 4) row softmax in place
    softmax_kernel<<<BH_SZ * L_SZ, 256>>>(attn);

    // 5) AV -> concat-head O
    av_kernel<<<dim3(L_SZ / 64, BH_SZ), 256>>>(attn);

    // 6) output projection
    gemm_abt_kernel<<<dim3(D_SZ / 64, MTOK / 64), 256>>>(
        o_ptr, out_w, out_b, out_proj, MTOK, D_SZ, D_SZ);
}

// round 3
// speedup vs baseline: 1.8433x; 1.8433x over previous
#include <cuda_runtime.h>
#include <math.h>
#include <stdint.h>

// Problem constants
#define B_SZ   2
#define L_SZ   2048
#define D_SZ   1024
#define H_SZ   16
#define E3_SZ  3072
#define MTOK   (B_SZ * L_SZ)        // 4096
#define BH_SZ  (B_SZ * H_SZ)        // 32

// Scratch (device globals; allocation is forbidden)
__device__ float g_qkv[(size_t)MTOK * E3_SZ];    // [4096, 3072]
__device__ float g_phase[(size_t)BH_SZ * L_SZ];  // [bh, l]
__device__ float g_o[(size_t)MTOK * D_SZ];       // [4096, 1024]

// ---------------------------------------------------------------------------
// tf32 mma.sync helpers (arch-portable, sm_80+)
// ---------------------------------------------------------------------------
__device__ __forceinline__ uint32_t tf32r(float f) {
    uint32_t r;
    asm("cvt.rna.tf32.f32 %0, %1;" : "=r"(r) : "f"(f));
    return r;
}
__device__ __forceinline__ void mma_tf32(float c[4], const uint32_t a[4],
                                         const uint32_t b[2]) {
    asm volatile(
        "mma.sync.aligned.m16n8k8.row.col.f32.tf32.tf32.f32 "
        "{%0,%1,%2,%3}, {%4,%5,%6,%7}, {%8,%9}, {%0,%1,%2,%3};"
        : "+f"(c[0]), "+f"(c[1]), "+f"(c[2]), "+f"(c[3])
        : "r"(a[0]), "r"(a[1]), "r"(a[2]), "r"(a[3]), "r"(b[0]), "r"(b[1]));
}

// ===========================================================================
// GEMM: C[M,N] = A[M,K] @ B[N,K]^T + bias[N]   (tf32 tensor cores)
// CTA tile 128x128, 8 warps (4x2), warp tile 32x64, k-chunk 32, dbl-buffered.
// SMEM row stride 40 words -> conflict-free fragment LDS.
// ===========================================================================
#define GST 40
__global__ void __launch_bounds__(256) gemm_mma(
    const float* __restrict__ A, const float* __restrict__ Bm,
    const float* __restrict__ bias, float* __restrict__ C, int N, int K)
{
    extern __shared__ uint32_t sm[];
    const int tid = threadIdx.x, wid = tid >> 5, lane = tid & 31;
    const int gid = lane >> 2, tig = lane & 3;
    const int wy = wid >> 1, wx = wid & 1;
    const int tm = blockIdx.y * 128, tn = blockIdx.x * 128;

    // stage s: A @ s*10240, B @ s*10240 + 5120  (words)
    const int lr = tid >> 1, lc = (tid & 1) * 16;
    const float* ag = A  + (size_t)(tm + lr) * K + lc;
    const float* bg = Bm + (size_t)(tn + lr) * K + lc;

    float acc[2][8][4];
#pragma unroll
    for (int i = 0; i < 2; ++i)
#pragma unroll
        for (int j = 0; j < 8; ++j)
#pragma unroll
            for (int v = 0; v < 4; ++v) acc[i][j][v] = 0.f;

    const int T = K >> 5;

#define G_LOAD(t, s) do {                                                   \
    const float* _ap = ag + (t) * 32;                                       \
    const float* _bp = bg + (t) * 32;                                       \
    uint32_t* _ad = sm + (s) * 10240 + lr * GST + lc;                       \
    uint32_t* _bd = _ad + 5120;                                             \
    _Pragma("unroll")                                                       \
    for (int j = 0; j < 16; j += 4) {                                       \
        float4 _av = *(const float4*)(_ap + j);                             \
        float4 _bv = *(const float4*)(_bp + j);                             \
        uint4 _at = {tf32r(_av.x), tf32r(_av.y), tf32r(_av.z), tf32r(_av.w)};\
        uint4 _bt = {tf32r(_bv.x), tf32r(_bv.y), tf32r(_bv.z), tf32r(_bv.w)};\
        *(uint4*)(_ad + j) = _at;                                           \
        *(uint4*)(_bd + j) = _bt;                                           \
    }                                                                       \
} while (0)

    G_LOAD(0, 0);
    __syncthreads();

    for (int t = 0; t < T; ++t) {
        if (t + 1 < T) G_LOAD(t + 1, (t + 1) & 1);
        const uint32_t* as = sm + (t & 1) * 10240;
        const uint32_t* bs = as + 5120;
#pragma unroll
        for (int k8 = 0; k8 < 32; k8 += 8) {
            uint32_t a[2][4], b[8][2];
#pragma unroll
            for (int mi = 0; mi < 2; ++mi) {
                int r0 = wy * 32 + mi * 16 + gid;
                a[mi][0] = as[r0 * GST + k8 + tig];
                a[mi][1] = as[(r0 + 8) * GST + k8 + tig];
                a[mi][2] = as[r0 * GST + k8 + tig + 4];
                a[mi][3] = as[(r0 + 8) * GST + k8 + tig + 4];
            }
#pragma unroll
            for (int ni = 0; ni < 8; ++ni) {
                int c0 = wx * 64 + ni * 8 + gid;
                b[ni][0] = bs[c0 * GST + k8 + tig];
                b[ni][1] = bs[c0 * GST + k8 + tig + 4];
            }
#pragma unroll
            for (int mi = 0; mi < 2; ++mi)
#pragma unroll
                for (int ni = 0; ni < 8; ++ni)
                    mma_tf32(acc[mi][ni], a[mi], b[ni]);
        }
        __syncthreads();
    }

#pragma unroll
    for (int mi = 0; mi < 2; ++mi) {
        int row = tm + wy * 32 + mi * 16 + gid;
#pragma unroll
        for (int ni = 0; ni < 8; ++ni) {
            int col = tn + wx * 64 + ni * 8 + tig * 2;
            float b0 = bias[col], b1 = bias[col + 1];
            float2 o0 = {acc[mi][ni][0] + b0, acc[mi][ni][1] + b1};
            float2 o1 = {acc[mi][ni][2] + b0, acc[mi][ni][3] + b1};
            *(float2*)(C + (size_t)row * N + col)       = o0;
            *(float2*)(C + (size_t)(row + 8) * N + col) = o1;
        }
    }
}

// ===========================================================================
// Scores: attn_raw[bh,i,j] = (q_i.k_j)/8 - rs*(pv_i-pv_j)^2
// CTA: 128(q) x 128(k), dh=64 in one SMEM stage (stride 72, conflict-free).
// ===========================================================================
#define QST 72
__global__ void __launch_bounds__(256) scores_mma(
    const float* __restrict__ rs_ptr, float* __restrict__ attn)
{
    extern __shared__ uint32_t sm[];
    uint32_t* Qs = sm;                // 128*72
    uint32_t* Ks = sm + 9216;         // 128*72
    float* pq = (float*)(sm + 18432); // 128
    float* pk = pq + 128;             // 128

    const int tid = threadIdx.x, wid = tid >> 5, lane = tid & 31;
    const int gid = lane >> 2, tig = lane & 3;
    const int wy = wid >> 1, wx = wid & 1;
    const int bh = blockIdx.z, b = bh >> 4, h = bh & 15;
    const int tm = blockIdx.y * 128, tn = blockIdx.x * 128;

    const int lr = tid >> 1, lc = (tid & 1) * 32;
    const float* qg = g_qkv + (size_t)(b * L_SZ + tm + lr) * E3_SZ + h * 64 + lc;
    const float* kg = g_qkv + (size_t)(b * L_SZ + tn + lr) * E3_SZ + D_SZ + h * 64 + lc;
#pragma unroll
    for (int j = 0; j < 32; j += 4) {
        float4 qv = *(const float4*)(qg + j);
        float4 kv = *(const float4*)(kg + j);
        uint4 qt = {tf32r(qv.x), tf32r(qv.y), tf32r(qv.z), tf32r(qv.w)};
        uint4 kt = {tf32r(kv.x), tf32r(kv.y), tf32r(kv.z), tf32r(kv.w)};
        *(uint4*)(Qs + lr * QST + lc + j) = qt;
        *(uint4*)(Ks + lr * QST + lc + j) = kt;
    }
    if (tid < 128)      pq[tid]       = g_phase[(size_t)bh * L_SZ + tm + tid];
    else                pk[tid - 128] = g_phase[(size_t)bh * L_SZ + tn + tid - 128];
    __syncthreads();

    float acc[2][8][4];
#pragma unroll
    for (int i = 0; i < 2; ++i)
#pragma unroll
        for (int j = 0; j < 8; ++j)
#pragma unroll
            for (int v = 0; v < 4; ++v) acc[i][j][v] = 0.f;

#pragma unroll
    for (int k8 = 0; k8 < 64; k8 += 8) {
        uint32_t a[2][4], b2[8][2];
#pragma unroll
        for (int mi = 0; mi < 2; ++mi) {
            int r0 = wy * 32 + mi * 16 + gid;
            a[mi][0] = Qs[r0 * QST + k8 + tig];
            a[mi][1] = Qs[(r0 + 8) * QST + k8 + tig];
            a[mi][2] = Qs[r0 * QST + k8 + tig + 4];
            a[mi][3] = Qs[(r0 + 8) * QST + k8 + tig + 4];
        }
#pragma unroll
        for (int ni = 0; ni < 8; ++ni) {
            int c0 = wx * 64 + ni * 8 + gid;
            b2[ni][0] = Ks[c0 * QST + k8 + tig];
            b2[ni][1] = Ks[c0 * QST + k8 + tig + 4];
        }
#pragma unroll
        for (int mi = 0; mi < 2; ++mi)
#pragma unroll
            for (int ni = 0; ni < 8; ++ni)
                mma_tf32(acc[mi][ni], a[mi], b2[ni]);
    }

    const float rs = *rs_ptr;
#pragma unroll
    for (int mi = 0; mi < 2; ++mi) {
        int r0 = wy * 32 + mi * 16 + gid;
        float pq0 = pq[r0], pq1 = pq[r0 + 8];
#pragma unroll
        for (int ni = 0; ni < 8; ++ni) {
            int c0 = wx * 64 + ni * 8 + tig * 2;
            float k0 = pk[c0], k1 = pk[c0 + 1];
            float d00 = pq0 - k0, d01 = pq0 - k1;
            float d10 = pq1 - k0, d11 = pq1 - k1;
            float2 o0 = {acc[mi][ni][0] * 0.125f - rs * d00 * d00,
                         acc[mi][ni][1] * 0.125f - rs * d01 * d01};
            float2 o1 = {acc[mi][ni][2] * 0.125f - rs * d10 * d10,
                         acc[mi][ni][3] * 0.125f - rs * d11 * d11};
            float* base = attn + ((size_t)bh * L_SZ + tm + r0) * L_SZ + tn + c0;
            *(float2*)base                    = o0;
            *(float2*)(base + (size_t)8 * L_SZ) = o1;
        }
    }
}

// ===========================================================================
// AV: O[b, i, h*64+d] = sum_j P[bh,i,j] * V[bh,j,d]  (tf32 tensor cores)
// CTA: 128(m) x 64(d), k-chunk 32 over j, dbl-buffered.
// ===========================================================================
__global__ void __launch_bounds__(256) av_mma(const float* __restrict__ attn)
{
    extern __shared__ uint32_t sm[];
    // stage s: Ps @ s*5120 (128x40), Vs @ 10240 + s*2304 (32x72)
    const int tid = threadIdx.x, wid = tid >> 5, lane = tid & 31;
    const int gid = lane >> 2, tig = lane & 3;
    const int wy = wid >> 1, wx = wid & 1;
    const int bh = blockIdx.y, b = bh >> 4, h = bh & 15;
    const int tm = blockIdx.x * 128;

    const int lr = tid >> 1, lc = (tid & 1) * 16;
    const int vr = tid >> 3, vc = (tid & 7) * 8;
    const float* pg = attn + ((size_t)bh * L_SZ + tm + lr) * L_SZ + lc;
    const float* vg = g_qkv + (size_t)(b * L_SZ + vr) * E3_SZ + 2 * D_SZ + h * 64 + vc;

    float acc[2][4][4];
#pragma unroll
    for (int i = 0; i < 2; ++i)
#pragma unroll
        for (int j = 0; j < 4; ++j)
#pragma unroll
            for (int v = 0; v < 4; ++v) acc[i][j][v] = 0.f;

#define AV_LOAD(t, s) do {                                                  \
    const float* _pp = pg + (t) * 32;                                       \
    const float* _vp = vg + (size_t)(t) * 32 * E3_SZ;                       \
    uint32_t* _pd = sm + (s) * 5120 + lr * GST + lc;                        \
    uint32_t* _vd = sm + 10240 + (s) * 2304 + vr * QST + vc;                \
    _Pragma("unroll")                                                       \
    for (int j = 0; j < 16; j += 4) {                                       \
        float4 _pv = *(const float4*)(_pp + j);                             \
        uint4 _pt = {tf32r(_pv.x), tf32r(_pv.y), tf32r(_pv.z), tf32r(_pv.w)};\
        *(uint4*)(_pd + j) = _pt;                                           \
    }                                                                       \
    _Pragma("unroll")                                                       \
    for (int j = 0; j < 8; j += 4) {                                        \
        float4 _vv = *(const float4*)(_vp + j);                             \
        uint4 _vt = {tf32r(_vv.x), tf32r(_vv.y), tf32r(_vv.z), tf32r(_vv.w)};\
        *(uint4*)(_vd + j) = _vt;                                           \
    }                                                                       \
} while (0)

    AV_LOAD(0, 0);
    __syncthreads();

    for (int t = 0; t < 64; ++t) {
        if (t + 1 < 64) AV_LOAD(t + 1, (t + 1) & 1);
        const uint32_t* ps = sm + (t & 1) * 5120;
        const uint32_t* vs = sm + 10240 + (t & 1) * 2304;
#pragma unroll
        for (int k8 = 0; k8 < 32; k8 += 8) {
            uint32_t a[2][4], b2[4][2];
#pragma unroll
            for (int mi = 0; mi < 2; ++mi) {
                int r0 = wy * 32 + mi * 16 + gid;
                a[mi][0] = ps[r0 * GST + k8 + tig];
                a[mi][1] = ps[(r0 + 8) * GST + k8 + tig];
                a[mi][2] = ps[r0 * GST + k8 + tig + 4];
                a[mi][3] = ps[(r0 + 8) * GST + k8 + tig + 4];
            }
#pragma unroll
            for (int ni = 0; ni < 4; ++ni) {
                int c0 = wx * 32 + ni * 8 + gid;
                b2[ni][0] = vs[(k8 + tig) * QST + c0];
                b2[ni][1] = vs[(k8 + tig + 4) * QST + c0];
            }
#pragma unroll
            for (int mi = 0; mi < 2; ++mi)
#pragma unroll
                for (int ni = 0; ni < 4; ++ni)
                    mma_tf32(acc[mi][ni], a[mi], b2[ni]);
        }
        __syncthreads();
    }

#pragma unroll
    for (int mi = 0; mi < 2; ++mi) {
        int row = tm + wy * 32 + mi * 16 + gid;
#pragma unroll
        for (int ni = 0; ni < 4; ++ni) {
            int col = h * 64 + wx * 32 + ni * 8 + tig * 2;
            float2 o0 = {acc[mi][ni][0], acc[mi][ni][1]};
            float2 o1 = {acc[mi][ni][2], acc[mi][ni][3]};
            *(float2*)(g_o + (size_t)(b * L_SZ + row) * D_SZ + col)       = o0;
            *(float2*)(g_o + (size_t)(b * L_SZ + row + 8) * D_SZ + col)  = o1;
        }
    }
}

// ---------------------------------------------------------------------------
// phase_val[bh, l] = tanh(ps * (x[b,l,:] . phase_w[h,:] + phase_b[h]))
// ---------------------------------------------------------------------------
__global__ __launch_bounds__(512) void phase_kernel(
    const float* __restrict__ x, const float* __restrict__ pw,
    const float* __restrict__ pb, const float* __restrict__ ps_ptr)
{
    const int bl = blockIdx.x;
    const int b  = bl >> 11;
    const int l  = bl & 2047;
    __shared__ float xs[1024];
    const int tid = threadIdx.x;
    for (int i = tid; i < 1024; i += 512) xs[i] = x[(size_t)bl * 1024 + i];
    __syncthreads();
    const int h = tid >> 5, lane = tid & 31;
    float s = 0.f;
    const float* w = pw + (size_t)h * 1024;
    for (int d = lane; d < 1024; d += 32) s += xs[d] * w[d];
#pragma unroll
    for (int o = 16; o; o >>= 1) s += __shfl_xor_sync(0xffffffff, s, o);
    if (lane == 0) {
        float ps = *ps_ptr;
        g_phase[(size_t)(b * H_SZ + h) * L_SZ + l] = tanhf(ps * (s + pb[h]));
    }
}

// ---------------------------------------------------------------------------
// In-place row softmax over 2048 elements; one block per row
// ---------------------------------------------------------------------------
__global__ __launch_bounds__(256) void softmax_kernel(float* __restrict__ attn)
{
    float* p = attn + (size_t)blockIdx.x * 2048;
    const int tid = threadIdx.x;
    float4 v0 = *(float4*)(p + tid * 8);
    float4 v1 = *(float4*)(p + tid * 8 + 4);

    __shared__ float red[256];
    float m = fmaxf(fmaxf(fmaxf(v0.x, v0.y), fmaxf(v0.z, v0.w)),
                    fmaxf(fmaxf(v1.x, v1.y), fmaxf(v1.z, v1.w)));
    red[tid] = m;
    __syncthreads();
    for (int s = 128; s > 0; s >>= 1) {
        if (tid < s) red[tid] = fmaxf(red[tid], red[tid + s]);
        __syncthreads();
    }
    const float bm = red[0];
    __syncthreads();

    v0.x = __expf(v0.x - bm); v0.y = __expf(v0.y - bm);
    v0.z = __expf(v0.z - bm); v0.w = __expf(v0.w - bm);
    v1.x = __expf(v1.x - bm); v1.y = __expf(v1.y - bm);
    v1.z = __expf(v1.z - bm); v1.w = __expf(v1.w - bm);
    float s8 = (v0.x + v0.y + v0.z + v0.w) + (v1.x + v1.y + v1.z + v1.w);
    red[tid] = s8;
    __syncthreads();
    for (int s = 128; s > 0; s >>= 1) {
        if (tid < s) red[tid] += red[tid + s];
        __syncthreads();
    }
    const float inv = 1.0f / red[0];

    v0.x *= inv; v0.y *= inv; v0.z *= inv; v0.w *= inv;
    v1.x *= inv; v1.y *= inv; v1.z *= inv; v1.w *= inv;
    *(float4*)(p + tid * 8)     = v0;
    *(float4*)(p + tid * 8 + 4) = v1;
}

// ---------------------------------------------------------------------------
extern "C" void kernel_launch(void* const* d_in, const int* in_sizes, int n_in,
                              void* d_out, int out_size)
{
    const float* x      = (const float*)d_in[0];
    const float* qkv_w  = (const float*)d_in[1];
    const float* qkv_b  = (const float*)d_in[2];
    const float* out_w  = (const float*)d_in[3];
    const float* out_b  = (const float*)d_in[4];
    const float* ph_w   = (const float*)d_in[5];
    const float* ph_b   = (const float*)d_in[6];
    const float* rs_ptr = (const float*)d_in[7];
    const float* ps_ptr = (const float*)d_in[8];

    float* out_proj = (float*)d_out;                       // [2,2048,1024]
    float* attn     = out_proj + (size_t)MTOK * D_SZ;      // [2,16,2048,2048]

    float *qkv_ptr, *o_ptr;
    cudaGetSymbolAddress((void**)&qkv_ptr, g_qkv);
    cudaGetSymbolAddress((void**)&o_ptr,  g_o);

    const int SMEM_GEMM   = 2 * 10240 * 4;            // 81920
    const int SMEM_SCORES = (18432 + 256) * 4;        // 74752
    const int SMEM_AV     = (10240 + 2 * 2304) * 4;   // 59392

    cudaFuncSetAttribute(gemm_mma,   cudaFuncAttributeMaxDynamicSharedMemorySize, SMEM_GEMM);
    cudaFuncSetAttribute(scores_mma, cudaFuncAttributeMaxDynamicSharedMemorySize, SMEM_SCORES);
    cudaFuncSetAttribute(av_mma,     cudaFuncAttributeMaxDynamicSharedMemorySize, SMEM_AV);

    // 1) fused QKV projection
    gemm_mma<<<dim3(E3_SZ / 128, MTOK / 128), 256, SMEM_GEMM>>>(
        x, qkv_w, qkv_b, qkv_ptr, E3_SZ, D_SZ);

    // 2) per-head phase values
    phase_kernel<<<MTOK, 512>>>(x, ph_w, ph_b, ps_ptr);

    // 3) raw biased scores
    scores_mma<<<dim3(L_SZ / 128, L_SZ / 128, BH_SZ), 256, SMEM_SCORES>>>(rs_ptr, attn);

    // 4) row softmax in place
    softmax_kernel<<<BH_SZ * L_SZ, 256>>>(attn);

    // 5) AV -> concat-head O
    av_mma<<<dim3(L_SZ / 128, BH_SZ), 256, SMEM_AV>>>(attn);

    // 6) output projection
    gemm_mma<<<dim3(D_SZ / 128, MTOK / 128), 256, SMEM_GEMM>>>(
        o_ptr, out_w, out_b, out_proj, D_SZ, D_SZ);
}

// round 4
// speedup vs baseline: 2.0357x; 1.1044x over previous
#include <cuda_runtime.h>
#include <math.h>
#include <stdint.h>

// Problem constants
#define B_SZ   2
#define L_SZ   2048
#define D_SZ   1024
#define H_SZ   16
#define E3_SZ  3072
#define MTOK   (B_SZ * L_SZ)        // 4096
#define BH_SZ  (B_SZ * H_SZ)        // 32

// Scratch (device globals; allocation is forbidden)
__device__ float g_qkv[(size_t)MTOK * E3_SZ];    // [4096, 3072]
__device__ float g_phase[(size_t)BH_SZ * L_SZ];  // [bh, l]
__device__ float g_o[(size_t)MTOK * D_SZ];       // [4096, 1024]

// ---------------------------------------------------------------------------
// tf32 mma.sync helpers (arch-portable, sm_80+)
// ---------------------------------------------------------------------------
__device__ __forceinline__ uint32_t tf32r(float f) {
    uint32_t r;
    asm("cvt.rna.tf32.f32 %0, %1;" : "=r"(r) : "f"(f));
    return r;
}
__device__ __forceinline__ void mma_tf32(float c[4], const uint32_t a[4],
                                         const uint32_t b[2]) {
    asm volatile(
        "mma.sync.aligned.m16n8k8.row.col.f32.tf32.tf32.f32 "
        "{%0,%1,%2,%3}, {%4,%5,%6,%7}, {%8,%9}, {%0,%1,%2,%3};"
        : "+f"(c[0]), "+f"(c[1]), "+f"(c[2]), "+f"(c[3])
        : "r"(a[0]), "r"(a[1]), "r"(a[2]), "r"(a[3]), "r"(b[0]), "r"(b[1]));
}

// ===========================================================================
// GEMM: C[M,N] = A[M,K] @ B[N,K]^T + bias[N]
// CTA 128x256, 8 warps (2x4), warp tile 64x64, k-chunk 32, double-buffered.
// SMEM: 32-word rows, XOR-swizzle group' = g ^ (row & 7) -> conflict-free.
// stage s: A @ s*12288 (128x32), B @ s*12288 + 4096 (256x32)
// ===========================================================================
__global__ void __launch_bounds__(256) gemm_mma(
    const float* __restrict__ A, const float* __restrict__ Bm,
    const float* __restrict__ bias, float* __restrict__ C, int N, int K)
{
    extern __shared__ uint32_t sm[];
    const int tid = threadIdx.x, wid = tid >> 5, lane = tid & 31;
    const int gid = lane >> 2, tig = lane & 3;
    const int wy = wid >> 2, wx = wid & 3;
    const int tm = blockIdx.y * 128, tn = blockIdx.x * 256;

    const int ar = tid >> 1, ac = (tid & 1) << 4;
    const float* ag = A  + (size_t)(tm + ar)  * K + ac;
    const float* bg = Bm + (size_t)(tn + tid) * K;

    float acc[4][8][4];
#pragma unroll
    for (int i = 0; i < 4; ++i)
#pragma unroll
        for (int j = 0; j < 8; ++j)
#pragma unroll
            for (int v = 0; v < 4; ++v) acc[i][j][v] = 0.f;

    const int T = K >> 5;

#define G_LOAD(t, s) do {                                                    \
    const float* _ap = ag + (t) * 32;                                        \
    const float* _bp = bg + (t) * 32;                                        \
    uint32_t* _ad = sm + (s) * 12288 + ar * 32;                              \
    uint32_t* _bd = sm + (s) * 12288 + 4096 + tid * 32;                      \
    _Pragma("unroll")                                                        \
    for (int j = 0; j < 4; ++j) {                                            \
        float4 v = *(const float4*)(_ap + j * 4);                            \
        int g = (ac >> 2) + j;                                               \
        uint4 w = {tf32r(v.x), tf32r(v.y), tf32r(v.z), tf32r(v.w)};          \
        *(uint4*)(_ad + ((g ^ (ar & 7)) << 2)) = w;                          \
    }                                                                        \
    _Pragma("unroll")                                                        \
    for (int j = 0; j < 8; ++j) {                                            \
        float4 v = *(const float4*)(_bp + j * 4);                            \
        uint4 w = {tf32r(v.x), tf32r(v.y), tf32r(v.z), tf32r(v.w)};          \
        *(uint4*)(_bd + ((j ^ (tid & 7)) << 2)) = w;                         \
    }                                                                        \
} while (0)

    G_LOAD(0, 0);
    __syncthreads();

    for (int t = 0; t < T; ++t) {
        if (t + 1 < T) G_LOAD(t + 1, (t + 1) & 1);
        const uint32_t* as = sm + (t & 1) * 12288;
        const uint32_t* bs = as + 4096;
#pragma unroll
        for (int k8 = 0; k8 < 32; k8 += 8) {
            const int kg = k8 >> 2;
            const int c1 = (kg ^ gid) << 2, c2 = ((kg + 1) ^ gid) << 2;
            uint32_t a[4][4], b[8][2];
#pragma unroll
            for (int mi = 0; mi < 4; ++mi) {
                int r0 = wy * 64 + mi * 16 + gid;
                const uint32_t* p0 = as + r0 * 32 + tig;
                a[mi][0] = p0[c1];
                a[mi][1] = p0[256 + c1];   // row +8 = +8*32 words
                a[mi][2] = p0[c2];
                a[mi][3] = p0[256 + c2];
            }
#pragma unroll
            for (int ni = 0; ni < 8; ++ni) {
                int c0 = wx * 64 + ni * 8 + gid;
                const uint32_t* q = bs + c0 * 32 + tig;
                b[ni][0] = q[c1];
                b[ni][1] = q[c2];
            }
#pragma unroll
            for (int mi = 0; mi < 4; ++mi)
#pragma unroll
                for (int ni = 0; ni < 8; ++ni)
                    mma_tf32(acc[mi][ni], a[mi], b[ni]);
        }
        __syncthreads();
    }

#pragma unroll
    for (int mi = 0; mi < 4; ++mi) {
        int row = tm + wy * 64 + mi * 16 + gid;
#pragma unroll
        for (int ni = 0; ni < 8; ++ni) {
            int col = tn + wx * 64 + ni * 8 + tig * 2;
            float b0 = bias[col], b1 = bias[col + 1];
            float2 o0 = {acc[mi][ni][0] + b0, acc[mi][ni][1] + b1};
            float2 o1 = {acc[mi][ni][2] + b0, acc[mi][ni][3] + b1};
            *(float2*)(C + (size_t)row * N + col)       = o0;
            *(float2*)(C + (size_t)(row + 8) * N + col) = o1;
        }
    }
}

// ===========================================================================
// Scores: attn_raw[bh,i,j] = (q_i.k_j)/8 - rs*(pv_i-pv_j)^2
// CTA 128x128, 4 warps (2x2), warp tile 64x64, dh=64 fully in SMEM.
// Tiles: two 128x32 sub-tiles each for Q and K, XOR-swizzled.
// ===========================================================================
__global__ void __launch_bounds__(128) scores_mma(
    const float* __restrict__ rs_ptr, float* __restrict__ attn)
{
    extern __shared__ uint32_t sm[];
    uint32_t* Qs = sm;                 // 2 * 4096
    uint32_t* Ks = sm + 8192;          // 2 * 4096
    float* pq = (float*)(sm + 16384);  // 128
    float* pk = pq + 128;              // 128

    const int tid = threadIdx.x, wid = tid >> 5, lane = tid & 31;
    const int gid = lane >> 2, tig = lane & 3;
    const int wy = wid >> 1, wx = wid & 1;
    const int bh = blockIdx.z, b = bh >> 4, h = bh & 15;
    const int tm = blockIdx.y * 128, tn = blockIdx.x * 128;

    const float* qg = g_qkv + (size_t)(b * L_SZ + tm + tid) * E3_SZ + h * 64;
    const float* kg = g_qkv + (size_t)(b * L_SZ + tn + tid) * E3_SZ + D_SZ + h * 64;
#pragma unroll
    for (int j = 0; j < 16; ++j) {
        float4 qv = *(const float4*)(qg + j * 4);
        float4 kv = *(const float4*)(kg + j * 4);
        int off = (j >> 3) * 4096 + tid * 32 + (((j & 7) ^ (tid & 7)) << 2);
        uint4 qt = {tf32r(qv.x), tf32r(qv.y), tf32r(qv.z), tf32r(qv.w)};
        uint4 kt = {tf32r(kv.x), tf32r(kv.y), tf32r(kv.z), tf32r(kv.w)};
        *(uint4*)(Qs + off) = qt;
        *(uint4*)(Ks + off) = kt;
    }
    pq[tid] = g_phase[(size_t)bh * L_SZ + tm + tid];
    pk[tid] = g_phase[(size_t)bh * L_SZ + tn + tid];
    __syncthreads();

    float acc[4][8][4];
#pragma unroll
    for (int i = 0; i < 4; ++i)
#pragma unroll
        for (int j = 0; j < 8; ++j)
#pragma unroll
            for (int v = 0; v < 4; ++v) acc[i][j][v] = 0.f;

#pragma unroll
    for (int k8 = 0; k8 < 64; k8 += 8) {
        const uint32_t* as = Qs + (k8 >> 5) * 4096;
        const uint32_t* bs = Ks + (k8 >> 5) * 4096;
        const int kg = (k8 >> 2) & 7;
        const int c1 = (kg ^ gid) << 2, c2 = ((kg + 1) ^ gid) << 2;
        uint32_t a[4][4], b2[8][2];
#pragma unroll
        for (int mi = 0; mi < 4; ++mi) {
            int r0 = wy * 64 + mi * 16 + gid;
            const uint32_t* p0 = as + r0 * 32 + tig;
            a[mi][0] = p0[c1];
            a[mi][1] = p0[256 + c1];
            a[mi][2] = p0[c2];
            a[mi][3] = p0[256 + c2];
        }
#pragma unroll
        for (int ni = 0; ni < 8; ++ni) {
            int c0 = wx * 64 + ni * 8 + gid;
            const uint32_t* q = bs + c0 * 32 + tig;
            b2[ni][0] = q[c1];
            b2[ni][1] = q[c2];
        }
#pragma unroll
        for (int mi = 0; mi < 4; ++mi)
#pragma unroll
            for (int ni = 0; ni < 8; ++ni)
                mma_tf32(acc[mi][ni], a[mi], b2[ni]);
    }

    const float rs = *rs_ptr;
#pragma unroll
    for (int mi = 0; mi < 4; ++mi) {
        int r0 = wy * 64 + mi * 16 + gid;
        float pq0 = pq[r0], pq1 = pq[r0 + 8];
#pragma unroll
        for (int ni = 0; ni < 8; ++ni) {
            int c0 = wx * 64 + ni * 8 + tig * 2;
            float k0 = pk[c0], k1 = pk[c0 + 1];
            float d00 = pq0 - k0, d01 = pq0 - k1;
            float d10 = pq1 - k0, d11 = pq1 - k1;
            float2 o0 = {acc[mi][ni][0] * 0.125f - rs * d00 * d00,
                         acc[mi][ni][1] * 0.125f - rs * d01 * d01};
            float2 o1 = {acc[mi][ni][2] * 0.125f - rs * d10 * d10,
                         acc[mi][ni][3] * 0.125f - rs * d11 * d11};
            float* base = attn + ((size_t)bh * L_SZ + tm + r0) * L_SZ + tn + c0;
            *(float2*)base                      = o0;
            *(float2*)(base + (size_t)8 * L_SZ) = o1;
        }
    }
}

// ===========================================================================
// AV: O[b, i, h*64+d] = sum_j P[bh,i,j] * V[bh,j,d]
// CTA 256(m) x 64(d), 4 warps, warp tile 64x64, k-chunk 32, double-buffered.
// P tiles XOR-swizzled (256x32); V tiles stride-72 (32x72, fragment-pattern
// conflict-free as validated in R3).
// stage s: P @ s*8192, V @ 16384 + s*2304
// ===========================================================================
__global__ void __launch_bounds__(128) av_mma(const float* __restrict__ attn)
{
    extern __shared__ uint32_t sm[];
    const int tid = threadIdx.x, wid = tid >> 5, lane = tid & 31;
    const int gid = lane >> 2, tig = lane & 3;
    const int bh = blockIdx.y, b = bh >> 4, h = bh & 15;
    const int tm = blockIdx.x * 256;

    const int pr = tid >> 1, ph = tid & 1;
    const float* pg = attn + ((size_t)bh * L_SZ + tm + pr) * L_SZ + ph * 16;
    const float* vg = g_qkv + (size_t)(b * L_SZ + (tid >> 2)) * E3_SZ + 2 * D_SZ
                      + h * 64 + (tid & 3) * 16;

    float acc[4][8][4];
#pragma unroll
    for (int i = 0; i < 4; ++i)
#pragma unroll
        for (int j = 0; j < 8; ++j)
#pragma unroll
            for (int v = 0; v < 4; ++v) acc[i][j][v] = 0.f;

#define AV_LOAD(t, s) do {                                                   \
    _Pragma("unroll")                                                        \
    for (int it = 0; it < 4; ++it) {                                         \
        const float* _pp = pg + (size_t)it * 64 * L_SZ + (t) * 32;           \
        uint32_t* _pd = sm + (s) * 8192 + (pr + it * 64) * 32;               \
        _Pragma("unroll")                                                    \
        for (int j = 0; j < 4; ++j) {                                        \
            float4 v = *(const float4*)(_pp + j * 4);                        \
            int g = ph * 4 + j;                                              \
            uint4 w = {tf32r(v.x), tf32r(v.y), tf32r(v.z), tf32r(v.w)};      \
            *(uint4*)(_pd + ((g ^ (pr & 7)) << 2)) = w;                      \
        }                                                                    \
    }                                                                        \
    {                                                                        \
        const float* _vp = vg + (size_t)(t) * 32 * E3_SZ;                    \
        uint32_t* _vd = sm + 16384 + (s) * 2304 + (tid >> 2) * 72            \
                        + (tid & 3) * 16;                                    \
        _Pragma("unroll")                                                    \
        for (int j = 0; j < 4; ++j) {                                        \
            float4 v = *(const float4*)(_vp + j * 4);                        \
            uint4 w = {tf32r(v.x), tf32r(v.y), tf32r(v.z), tf32r(v.w)};      \
            *(uint4*)(_vd + j * 4) = w;                                      \
        }                                                                    \
    }                                                                        \
} while (0)

    AV_LOAD(0, 0);
    __syncthreads();

    for (int t = 0; t < 64; ++t) {
        if (t + 1 < 64) AV_LOAD(t + 1, (t + 1) & 1);
        const uint32_t* ps = sm + (t & 1) * 8192;
        const uint32_t* vs = sm + 16384 + (t & 1) * 2304;
#pragma unroll
        for (int k8 = 0; k8 < 32; k8 += 8) {
            const int kg = k8 >> 2;
            const int c1 = (kg ^ gid) << 2, c2 = ((kg + 1) ^ gid) << 2;
            uint32_t a[4][4], b2[8][2];
#pragma unroll
            for (int mi = 0; mi < 4; ++mi) {
                int r0 = wid * 64 + mi * 16 + gid;
                const uint32_t* p0 = ps + r0 * 32 + tig;
                a[mi][0] = p0[c1];
                a[mi][1] = p0[256 + c1];
                a[mi][2] = p0[c2];
                a[mi][3] = p0[256 + c2];
            }
#pragma unroll
            for (int ni = 0; ni < 8; ++ni) {
                int c0 = ni * 8 + gid;
                b2[ni][0] = vs[(k8 + tig) * 72 + c0];
                b2[ni][1] = vs[(k8 + tig + 4) * 72 + c0];
            }
#pragma unroll
            for (int mi = 0; mi < 4; ++mi)
#pragma unroll
                for (int ni = 0; ni < 8; ++ni)
                    mma_tf32(acc[mi][ni], a[mi], b2[ni]);
        }
        __syncthreads();
    }

#pragma unroll
    for (int mi = 0; mi < 4; ++mi) {
        int row = tm + wid * 64 + mi * 16 + gid;
#pragma unroll
        for (int ni = 0; ni < 8; ++ni) {
            int col = h * 64 + ni * 8 + tig * 2;
            float2 o0 = {acc[mi][ni][0], acc[mi][ni][1]};
            float2 o1 = {acc[mi][ni][2], acc[mi][ni][3]};
            *(float2*)(g_o + (size_t)(b * L_SZ + row) * D_SZ + col)      = o0;
            *(float2*)(g_o + (size_t)(b * L_SZ + row + 8) * D_SZ + col)  = o1;
        }
    }
}

// ---------------------------------------------------------------------------
// phase_val[bh, l] = tanh(ps * (x[b,l,:] . phase_w[h,:] + phase_b[h]))
// ---------------------------------------------------------------------------
__global__ __launch_bounds__(512) void phase_kernel(
    const float* __restrict__ x, const float* __restrict__ pw,
    const float* __restrict__ pb, const float* __restrict__ ps_ptr)
{
    const int bl = blockIdx.x;
    const int b  = bl >> 11;
    const int l  = bl & 2047;
    __shared__ float xs[1024];
    const int tid = threadIdx.x;
    for (int i = tid; i < 1024; i += 512) xs[i] = x[(size_t)bl * 1024 + i];
    __syncthreads();
    const int h = tid >> 5, lane = tid & 31;
    float s = 0.f;
    const float* w = pw + (size_t)h * 1024;
    for (int d = lane; d < 1024; d += 32) s += xs[d] * w[d];
#pragma unroll
    for (int o = 16; o; o >>= 1) s += __shfl_xor_sync(0xffffffff, s, o);
    if (lane == 0) {
        float ps = *ps_ptr;
        g_phase[(size_t)(b * H_SZ + h) * L_SZ + l] = tanhf(ps * (s + pb[h]));
    }
}

// ---------------------------------------------------------------------------
// In-place row softmax over 2048 elements; one block per row
// ---------------------------------------------------------------------------
__global__ __launch_bounds__(256) void softmax_kernel(float* __restrict__ attn)
{
    float* p = attn + (size_t)blockIdx.x * 2048;
    const int tid = threadIdx.x;
    float4 v0 = *(float4*)(p + tid * 8);
    float4 v1 = *(float4*)(p + tid * 8 + 4);

    __shared__ float red[256];
    float m = fmaxf(fmaxf(fmaxf(v0.x, v0.y), fmaxf(v0.z, v0.w)),
                    fmaxf(fmaxf(v1.x, v1.y), fmaxf(v1.z, v1.w)));
    red[tid] = m;
    __syncthreads();
    for (int s = 128; s > 0; s >>= 1) {
        if (tid < s) red[tid] = fmaxf(red[tid], red[tid + s]);
        __syncthreads();
    }
    const float bm = red[0];
    __syncthreads();

    v0.x = __expf(v0.x - bm); v0.y = __expf(v0.y - bm);
    v0.z = __expf(v0.z - bm); v0.w = __expf(v0.w - bm);
    v1.x = __expf(v1.x - bm); v1.y = __expf(v1.y - bm);
    v1.z = __expf(v1.z - bm); v1.w = __expf(v1.w - bm);
    float s8 = (v0.x + v0.y + v0.z + v0.w) + (v1.x + v1.y + v1.z + v1.w);
    red[tid] = s8;
    __syncthreads();
    for (int s = 128; s > 0; s >>= 1) {
        if (tid < s) red[tid] += red[tid + s];
        __syncthreads();
    }
    const float inv = 1.0f / red[0];

    v0.x *= inv; v0.y *= inv; v0.z *= inv; v0.w *= inv;
    v1.x *= inv; v1.y *= inv; v1.z *= inv; v1.w *= inv;
    *(float4*)(p + tid * 8)     = v0;
    *(float4*)(p + tid * 8 + 4) = v1;
}

// ---------------------------------------------------------------------------
extern "C" void kernel_launch(void* const* d_in, const int* in_sizes, int n_in,
                              void* d_out, int out_size)
{
    const float* x      = (const float*)d_in[0];
    const float* qkv_w  = (const float*)d_in[1];
    const float* qkv_b  = (const float*)d_in[2];
    const float* out_w  = (const float*)d_in[3];
    const float* out_b  = (const float*)d_in[4];
    const float* ph_w   = (const float*)d_in[5];
    const float* ph_b   = (const float*)d_in[6];
    const float* rs_ptr = (const float*)d_in[7];
    const float* ps_ptr = (const float*)d_in[8];

    float* out_proj = (float*)d_out;                       // [2,2048,1024]
    float* attn     = out_proj + (size_t)MTOK * D_SZ;      // [2,16,2048,2048]

    float *qkv_ptr, *o_ptr;
    cudaGetSymbolAddress((void**)&qkv_ptr, g_qkv);
    cudaGetSymbolAddress((void**)&o_ptr,  g_o);

    const int SMEM_GEMM   = 2 * 12288 * 4;          // 98304
    const int SMEM_SCORES = (16384 + 256) * 4;      // 66560
    const int SMEM_AV     = (16384 + 2 * 2304) * 4; // 83968

    cudaFuncSetAttribute(gemm_mma,   cudaFuncAttributeMaxDynamicSharedMemorySize, SMEM_GEMM);
    cudaFuncSetAttribute(scores_mma, cudaFuncAttributeMaxDynamicSharedMemorySize, SMEM_SCORES);
    cudaFuncSetAttribute(av_mma,     cudaFuncAttributeMaxDynamicSharedMemorySize, SMEM_AV);

    // 1) fused QKV projection
    gemm_mma<<<dim3(E3_SZ / 256, MTOK / 128), 256, SMEM_GEMM>>>(
        x, qkv_w, qkv_b, qkv_ptr, E3_SZ, D_SZ);

    // 2) per-head phase values
    phase_kernel<<<MTOK, 512>>>(x, ph_w, ph_b, ps_ptr);

    // 3) raw biased scores
    scores_mma<<<dim3(L_SZ / 128, L_SZ / 128, BH_SZ), 128, SMEM_SCORES>>>(rs_ptr, attn);

    // 4) row softmax in place
    softmax_kernel<<<BH_SZ * L_SZ, 256>>>(attn);

    // 5) AV -> concat-head O
    av_mma<<<dim3(L_SZ / 256, BH_SZ), 128, SMEM_AV>>>(attn);

    // 6) output projection
    gemm_mma<<<dim3(D_SZ / 256, MTOK / 128), 256, SMEM_GEMM>>>(
        o_ptr, out_w, out_b, out_proj, D_SZ, D_SZ);
}

// round 5
// speedup vs baseline: 2.0438x; 1.0040x over previous
#include <cuda_runtime.h>
#include <math.h>
#include <stdint.h>

// Problem constants
#define B_SZ   2
#define L_SZ   2048
#define D_SZ   1024
#define H_SZ   16
#define E3_SZ  3072
#define MTOK   (B_SZ * L_SZ)        // 4096
#define BH_SZ  (B_S_Z_DUMMY + 30)   // placeholder guard (never used)
#undef BH_SZ
#define BH_SZ  32

#define NEG_INF __int_as_float(0xff800000)

// Scratch (device globals; allocation is forbidden)
__device__ float g_qkv[(size_t)MTOK * E3_SZ];    // [4096, 3072]
__device__ float g_phase[(size_t)BH_SZ * L_SZ];  // [bh, l]
__device__ float g_o[(size_t)MTOK * D_SZ];       // [4096, 1024]
__device__ float g_pmax[(size_t)BH_SZ * 16 * L_SZ];  // per-tile row max
__device__ float g_psum[(size_t)BH_SZ * 16 * L_SZ];  // per-tile row sumexp
__device__ float g_rowM[(size_t)BH_SZ * L_SZ];       // per-row global max
__device__ float g_rowI[(size_t)BH_SZ * L_SZ];       // per-row 1/sum

// ---------------------------------------------------------------------------
// tf32 mma.sync helpers (arch-portable, sm_80+)
// ---------------------------------------------------------------------------
__device__ __forceinline__ uint32_t tf32r(float f) {
    uint32_t r;
    asm("cvt.rna.tf32.f32 %0, %1;" : "=r"(r) : "f"(f));
    return r;
}
__device__ __forceinline__ void mma_tf32(float c[4], const uint32_t a[4],
                                         const uint32_t b[2]) {
    asm volatile(
        "mma.sync.aligned.m16n8k8.row.col.f32.tf32.tf32.f32 "
        "{%0,%1,%2,%3}, {%4,%5,%6,%7}, {%8,%9}, {%0,%1,%2,%3};"
        : "+f"(c[0]), "+f"(c[1]), "+f"(c[2]), "+f"(c[3])
        : "r"(a[0]), "r"(a[1]), "r"(a[2]), "r"(a[3]), "r"(b[0]), "r"(b[1]));
}

// ===========================================================================
// GEMM: C[M,N] = A[M,K] @ B[N,K]^T + bias[N]
// CTA 128x256, 8 warps (2x4), warp tile 64x64, k-chunk 32, double-buffered.
// SMEM: 32-word rows, XOR-swizzle group' = g ^ (row & 7) -> conflict-free.
// ===========================================================================
__global__ void __launch_bounds__(256) gemm_mma(
    const float* __restrict__ A, const float* __restrict__ Bm,
    const float* __restrict__ bias, float* __restrict__ C, int N, int K)
{
    extern __shared__ uint32_t sm[];
    const int tid = threadIdx.x, wid = tid >> 5, lane = tid & 31;
    const int gid = lane >> 2, tig = lane & 3;
    const int wy = wid >> 2, wx = wid & 3;
    const int tm = blockIdx.y * 128, tn = blockIdx.x * 256;

    const int ar = tid >> 1, ac = (tid & 1) << 4;
    const float* ag = A  + (size_t)(tm + ar)  * K + ac;
    const float* bg = Bm + (size_t)(tn + tid) * K;

    float acc[4][8][4];
#pragma unroll
    for (int i = 0; i < 4; ++i)
#pragma unroll
        for (int j = 0; j < 8; ++j)
#pragma unroll
            for (int v = 0; v < 4; ++v) acc[i][j][v] = 0.f;

    const int T = K >> 5;

#define G_LOAD(t, s) do {                                                    \
    const float* _ap = ag + (t) * 32;                                        \
    const float* _bp = bg + (t) * 32;                                        \
    uint32_t* _ad = sm + (s) * 12288 + ar * 32;                              \
    uint32_t* _bd = sm + (s) * 12288 + 4096 + tid * 32;                      \
    _Pragma("unroll")                                                        \
    for (int j = 0; j < 4; ++j) {                                            \
        float4 v = *(const float4*)(_ap + j * 4);                            \
        int g = (ac >> 2) + j;                                               \
        uint4 w = {tf32r(v.x), tf32r(v.y), tf32r(v.z), tf32r(v.w)};          \
        *(uint4*)(_ad + ((g ^ (ar & 7)) << 2)) = w;                          \
    }                                                                        \
    _Pragma("unroll")                                                        \
    for (int j = 0; j < 8; ++j) {                                            \
        float4 v = *(const float4*)(_bp + j * 4);                            \
        uint4 w = {tf32r(v.x), tf32r(v.y), tf32r(v.z), tf32r(v.w)};          \
        *(uint4*)(_bd + ((j ^ (tid & 7)) << 2)) = w;                         \
    }                                                                        \
} while (0)

    G_LOAD(0, 0);
    __syncthreads();

    for (int t = 0; t < T; ++t) {
        if (t + 1 < T) G_LOAD(t + 1, (t + 1) & 1);
        const uint32_t* as = sm + (t & 1) * 12288;
        const uint32_t* bs = as + 4096;
#pragma unroll
        for (int k8 = 0; k8 < 32; k8 += 8) {
            const int kg = k8 >> 2;
            const int c1 = (kg ^ gid) << 2, c2 = ((kg + 1) ^ gid) << 2;
            uint32_t a[4][4], b[8][2];
#pragma unroll
            for (int mi = 0; mi < 4; ++mi) {
                int r0 = wy * 64 + mi * 16 + gid;
                const uint32_t* p0 = as + r0 * 32 + tig;
                a[mi][0] = p0[c1];
                a[mi][1] = p0[256 + c1];
                a[mi][2] = p0[c2];
                a[mi][3] = p0[256 + c2];
            }
#pragma unroll
            for (int ni = 0; ni < 8; ++ni) {
                int c0 = wx * 64 + ni * 8 + gid;
                const uint32_t* q = bs + c0 * 32 + tig;
                b[ni][0] = q[c1];
                b[ni][1] = q[c2];
            }
#pragma unroll
            for (int mi = 0; mi < 4; ++mi)
#pragma unroll
                for (int ni = 0; ni < 8; ++ni)
                    mma_tf32(acc[mi][ni], a[mi], b[ni]);
        }
        __syncthreads();
    }

#pragma unroll
    for (int mi = 0; mi < 4; ++mi) {
        int row = tm + wy * 64 + mi * 16 + gid;
#pragma unroll
        for (int ni = 0; ni < 8; ++ni) {
            int col = tn + wx * 64 + ni * 8 + tig * 2;
            float b0 = bias[col], b1 = bias[col + 1];
            float2 o0 = {acc[mi][ni][0] + b0, acc[mi][ni][1] + b1};
            float2 o1 = {acc[mi][ni][2] + b0, acc[mi][ni][3] + b1};
            *(float2*)(C + (size_t)row * N + col)       = o0;
            *(float2*)(C + (size_t)(row + 8) * N + col) = o1;
        }
    }
}

// ===========================================================================
// Scores + per-tile softmax partials.
// attn_raw[bh,i,j] = (q_i.k_j)/8 - rs*(pv_i-pv_j)^2
// Also emits per-(tile,row) max and sumexp(rel. tile max) into g_pmax/g_psum.
// CTA 128x128, 4 warps (2x2), warp tile 64x64.
// ===========================================================================
__global__ void __launch_bounds__(128) scores_mma(
    const float* __restrict__ rs_ptr, float* __restrict__ attn)
{
    extern __shared__ uint32_t sm[];
    uint32_t* Qs = sm;                 // 2 * 4096
    uint32_t* Ks = sm + 8192;          // 2 * 4096
    float* pq = (float*)(sm + 16384);  // 128
    float* pk = pq + 128;              // 128
    float* sm_m = pk + 128;            // 256: [wx][row]
    float* sm_s = sm_m + 256;          // 256

    const int tid = threadIdx.x, wid = tid >> 5, lane = tid & 31;
    const int gid = lane >> 2, tig = lane & 3;
    const int wy = wid >> 1, wx = wid & 1;
    const int bh = blockIdx.z, b = bh >> 4, h = bh & 15;
    const int tm = blockIdx.y * 128, tn = blockIdx.x * 128;

    const float* qg = g_qkv + (size_t)(b * L_SZ + tm + tid) * E3_SZ + h * 64;
    const float* kg = g_qkv + (size_t)(b * L_SZ + tn + tid) * E3_SZ + D_SZ + h * 64;
#pragma unroll
    for (int j = 0; j < 16; ++j) {
        float4 qv = *(const float4*)(qg + j * 4);
        float4 kv = *(const float4*)(kg + j * 4);
        int off = (j >> 3) * 4096 + tid * 32 + (((j & 7) ^ (tid & 7)) << 2);
        uint4 qt = {tf32r(qv.x), tf32r(qv.y), tf32r(qv.z), tf32r(qv.w)};
        uint4 kt = {tf32r(kv.x), tf32r(kv.y), tf32r(kv.z), tf32r(kv.w)};
        *(uint4*)(Qs + off) = qt;
        *(uint4*)(Ks + off) = kt;
    }
    pq[tid] = g_phase[(size_t)bh * L_SZ + tm + tid];
    pk[tid] = g_phase[(size_t)bh * L_SZ + tn + tid];
    __syncthreads();

    float acc[4][8][4];
#pragma unroll
    for (int i = 0; i < 4; ++i)
#pragma unroll
        for (int j = 0; j < 8; ++j)
#pragma unroll
            for (int v = 0; v < 4; ++v) acc[i][j][v] = 0.f;

#pragma unroll
    for (int k8 = 0; k8 < 64; k8 += 8) {
        const uint32_t* as = Qs + (k8 >> 5) * 4096;
        const uint32_t* bs = Ks + (k8 >> 5) * 4096;
        const int kg = (k8 >> 2) & 7;
        const int c1 = (kg ^ gid) << 2, c2 = ((kg + 1) ^ gid) << 2;
        uint32_t a[4][4], b2[8][2];
#pragma unroll
        for (int mi = 0; mi < 4; ++mi) {
            int r0 = wy * 64 + mi * 16 + gid;
            const uint32_t* p0 = as + r0 * 32 + tig;
            a[mi][0] = p0[c1];
            a[mi][1] = p0[256 + c1];
            a[mi][2] = p0[c2];
            a[mi][3] = p0[256 + c2];
        }
#pragma unroll
        for (int ni = 0; ni < 8; ++ni) {
            int c0 = wx * 64 + ni * 8 + gid;
            const uint32_t* q = bs + c0 * 32 + tig;
            b2[ni][0] = q[c1];
            b2[ni][1] = q[c2];
        }
#pragma unroll
        for (int mi = 0; mi < 4; ++mi)
#pragma unroll
            for (int ni = 0; ni < 8; ++ni)
                mma_tf32(acc[mi][ni], a[mi], b2[ni]);
    }

    const float rs = *rs_ptr;
    // compute biased scores in place, write raw to gmem
#pragma unroll
    for (int mi = 0; mi < 4; ++mi) {
        int r0 = wy * 64 + mi * 16 + gid;
        float pq0 = pq[r0], pq1 = pq[r0 + 8];
#pragma unroll
        for (int ni = 0; ni < 8; ++ni) {
            int c0 = wx * 64 + ni * 8 + tig * 2;
            float k0 = pk[c0], k1 = pk[c0 + 1];
            float d00 = pq0 - k0, d01 = pq0 - k1;
            float d10 = pq1 - k0, d11 = pq1 - k1;
            acc[mi][ni][0] = acc[mi][ni][0] * 0.125f - rs * d00 * d00;
            acc[mi][ni][1] = acc[mi][ni][1] * 0.125f - rs * d01 * d01;
            acc[mi][ni][2] = acc[mi][ni][2] * 0.125f - rs * d10 * d10;
            acc[mi][ni][3] = acc[mi][ni][3] * 0.125f - rs * d11 * d11;
            float* base = attn + ((size_t)bh * L_SZ + tm + r0) * L_SZ + tn + c0;
            *(float2*)base                      = make_float2(acc[mi][ni][0], acc[mi][ni][1]);
            *(float2*)(base + (size_t)8 * L_SZ) = make_float2(acc[mi][ni][2], acc[mi][ni][3]);
        }
    }

    // --- per-row tile max ---
#pragma unroll
    for (int mi = 0; mi < 4; ++mi) {
        float mx0 = NEG_INF, mx1 = NEG_INF;
#pragma unroll
        for (int ni = 0; ni < 8; ++ni) {
            mx0 = fmaxf(mx0, fmaxf(acc[mi][ni][0], acc[mi][ni][1]));
            mx1 = fmaxf(mx1, fmaxf(acc[mi][ni][2], acc[mi][ni][3]));
        }
        mx0 = fmaxf(mx0, __shfl_xor_sync(0xffffffff, mx0, 1));
        mx0 = fmaxf(mx0, __shfl_xor_sync(0xffffffff, mx0, 2));
        mx1 = fmaxf(mx1, __shfl_xor_sync(0xffffffff, mx1, 1));
        mx1 = fmaxf(mx1, __shfl_xor_sync(0xffffffff, mx1, 2));
        if (tig == 0) {
            int r0 = wy * 64 + mi * 16 + gid;
            sm_m[wx * 128 + r0]     = mx0;
            sm_m[wx * 128 + r0 + 8] = mx1;
        }
    }
    __syncthreads();

    // --- per-row tile sumexp (relative to tile max) ---
#pragma unroll
    for (int mi = 0; mi < 4; ++mi) {
        int r0 = wy * 64 + mi * 16 + gid;
        float tM0 = fmaxf(sm_m[r0],     sm_m[128 + r0]);
        float tM1 = fmaxf(sm_m[r0 + 8], sm_m[128 + r0 + 8]);
        float s0 = 0.f, s1 = 0.f;
#pragma unroll
        for (int ni = 0; ni < 8; ++ni) {
            s0 += __expf(acc[mi][ni][0] - tM0) + __expf(acc[mi][ni][1] - tM0);
            s1 += __expf(acc[mi][ni][2] - tM1) + __expf(acc[mi][ni][3] - tM1);
        }
        s0 += __shfl_xor_sync(0xffffffff, s0, 1);
        s0 += __shfl_xor_sync(0xffffffff, s0, 2);
        s1 += __shfl_xor_sync(0xffffffff, s1, 1);
        s1 += __shfl_xor_sync(0xffffffff, s1, 2);
        if (tig == 0) {
            sm_s[wx * 128 + r0]     = s0;
            sm_s[wx * 128 + r0 + 8] = s1;
        }
    }
    __syncthreads();

    // thread tid owns row tid of this tile
    {
        float M = fmaxf(sm_m[tid], sm_m[128 + tid]);
        float S = sm_s[tid] + sm_s[128 + tid];
        size_t o = ((size_t)bh * 16 + blockIdx.x) * L_SZ + tm + tid;
        g_pmax[o] = M;
        g_psum[o] = S;
    }
}

// ===========================================================================
// Merge per-tile partials into per-row M and 1/S.
// ===========================================================================
__global__ void __launch_bounds__(256) reduce_stats()
{
    const int idx = blockIdx.x * 256 + threadIdx.x;   // bh*2048 + row
    const int bh = idx >> 11, row = idx & 2047;
    float m[16], M = NEG_INF;
#pragma unroll
    for (int t = 0; t < 16; ++t) {
        m[t] = g_pmax[((size_t)bh * 16 + t) * L_SZ + row];
        M = fmaxf(M, m[t]);
    }
    float S = 0.f;
#pragma unroll
    for (int t = 0; t < 16; ++t)
        S += g_psum[((size_t)bh * 16 + t) * L_SZ + row] * __expf(m[t] - M);
    g_rowM[idx] = M;
    g_rowI[idx] = 1.0f / S;
}

// ===========================================================================
// Fused normalize + attn write + AV.
// Reads raw scores, p = exp(s-M)*invS, writes p to attn (in place),
// accumulates O = P @ V with tf32 mma.
// CTA 256(m) x 64(d), 4 warps, warp tile 64x64, k-chunk 32, double-buffered.
// ===========================================================================
__global__ void __launch_bounds__(128) av_fused(float* __restrict__ attn)
{
    extern __shared__ uint32_t sm[];
    const int tid = threadIdx.x, wid = tid >> 5, lane = tid & 31;
    const int gid = lane >> 2, tig = lane & 3;
    const int bh = blockIdx.y, b = bh >> 4, h = bh & 15;
    const int tm = blockIdx.x * 256;

    const int pr = tid >> 1, ph = tid & 1;
    float* pg = attn + ((size_t)bh * L_SZ + tm + pr) * L_SZ + ph * 16;
    const float* vg = g_qkv + (size_t)(b * L_SZ + (tid >> 2)) * E3_SZ + 2 * D_SZ
                      + h * 64 + (tid & 3) * 16;

    // per-row softmax stats for the 4 rows this thread loads
    float Mreg[4], Ireg[4];
#pragma unroll
    for (int it = 0; it < 4; ++it) {
        int r = bh * L_SZ + tm + pr + it * 64;
        Mreg[it] = g_rowM[r];
        Ireg[it] = g_rowI[r];
    }

    float acc[4][8][4];
#pragma unroll
    for (int i = 0; i < 4; ++i)
#pragma unroll
        for (int j = 0; j < 8; ++j)
#pragma unroll
            for (int v = 0; v < 4; ++v) acc[i][j][v] = 0.f;

#define AV_LOAD(t, s) do {                                                   \
    _Pragma("unroll")                                                        \
    for (int it = 0; it < 4; ++it) {                                         \
        float* _pp = pg + (size_t)it * 64 * L_SZ + (t) * 32;                 \
        uint32_t* _pd = sm + (s) * 8192 + (pr + it * 64) * 32;               \
        _Pragma("unroll")                                                    \
        for (int j = 0; j < 4; ++j) {                                        \
            float4 v = *(const float4*)(_pp + j * 4);                        \
            float4 p;                                                        \
            p.x = __expf(v.x - Mreg[it]) * Ireg[it];                         \
            p.y = __expf(v.y - Mreg[it]) * Ireg[it];                         \
            p.z = __expf(v.z - Mreg[it]) * Ireg[it];                         \
            p.w = __expf(v.w - Mreg[it]) * Ireg[it];                         \
            *(float4*)(_pp + j * 4) = p;                                     \
            int g = ph * 4 + j;                                              \
            uint4 w = {tf32r(p.x), tf32r(p.y), tf32r(p.z), tf32r(p.w)};      \
            *(uint4*)(_pd + ((g ^ (pr & 7)) << 2)) = w;                      \
        }                                                                    \
    }                                                                        \
    {                                                                        \
        const float* _vp = vg + (size_t)(t) * 32 * E3_SZ;                    \
        uint32_t* _vd = sm + 16384 + (s) * 2304 + (tid >> 2) * 72            \
                        + (tid & 3) * 16;                                    \
        _Pragma("unroll")                                                    \
        for (int j = 0; j < 4; ++j) {                                        \
            float4 v = *(const float4*)(_vp + j * 4);                        \
            uint4 w = {tf32r(v.x), tf32r(v.y), tf32r(v.z), tf32r(v.w)};      \
            *(uint4*)(_vd + j * 4) = w;                                      \
        }                                                                    \
    }                                                                        \
} while (0)

    AV_LOAD(0, 0);
    __syncthreads();

    for (int t = 0; t < 64; ++t) {
        if (t + 1 < 64) AV_LOAD(t + 1, (t + 1) & 1);
        const uint32_t* ps = sm + (t & 1) * 8192;
        const uint32_t* vs = sm + 16384 + (t & 1) * 2304;
#pragma unroll
        for (int k8 = 0; k8 < 32; k8 += 8) {
            const int kg = k8 >> 2;
            const int c1 = (kg ^ gid) << 2, c2 = ((kg + 1) ^ gid) << 2;
            uint32_t a[4][4], b2[8][2];
#pragma unroll
            for (int mi = 0; mi < 4; ++mi) {
                int r0 = wid * 64 + mi * 16 + gid;
                const uint32_t* p0 = ps + r0 * 32 + tig;
                a[mi][0] = p0[c1];
                a[mi][1] = p0[256 + c1];
                a[mi][2] = p0[c2];
                a[mi][3] = p0[256 + c2];
            }
#pragma unroll
            for (int ni = 0; ni < 8; ++ni) {
                int c0 = ni * 8 + gid;
                b2[ni][0] = vs[(k8 + tig) * 72 + c0];
                b2[ni][1] = vs[(k8 + tig + 4) * 72 + c0];
            }
#pragma unroll
            for (int mi = 0; mi < 4; ++mi)
#pragma unroll
                for (int ni = 0; ni < 8; ++ni)
                    mma_tf32(acc[mi][ni], a[mi], b2[ni]);
        }
        __syncthreads();
    }

#pragma unroll
    for (int mi = 0; mi < 4; ++mi) {
        int row = tm + wid * 64 + mi * 16 + gid;
#pragma unroll
        for (int ni = 0; ni < 8; ++ni) {
            int col = h * 64 + ni * 8 + tig * 2;
            float2 o0 = {acc[mi][ni][0], acc[mi][ni][1]};
            float2 o1 = {acc[mi][ni][2], acc[mi][ni][3]};
            *(float2*)(g_o + (size_t)(b * L_SZ + row) * D_SZ + col)      = o0;
            *(float2*)(g_o + (size_t)(b * L_SZ + row + 8) * D_SZ + col)  = o1;
        }
    }
}

// ---------------------------------------------------------------------------
// phase_val[bh, l] = tanh(ps * (x[b,l,:] . phase_w[h,:] + phase_b[h]))
// ---------------------------------------------------------------------------
__global__ __launch_bounds__(512) void phase_kernel(
    const float* __restrict__ x, const float* __restrict__ pw,
    const float* __restrict__ pb, const float* __restrict__ ps_ptr)
{
    const int bl = blockIdx.x;
    const int b  = bl >> 11;
    const int l  = bl & 2047;
    __shared__ float xs[1024];
    const int tid = threadIdx.x;
    for (int i = tid; i < 1024; i += 512) xs[i] = x[(size_t)bl * 1024 + i];
    __syncthreads();
    const int h = tid >> 5, lane = tid & 31;
    float s = 0.f;
    const float* w = pw + (size_t)h * 1024;
    for (int d = lane; d < 1024; d += 32) s += xs[d] * w[d];
#pragma unroll
    for (int o = 16; o; o >>= 1) s += __shfl_xor_sync(0xffffffff, s, o);
    if (lane == 0) {
        float ps = *ps_ptr;
        g_phase[(size_t)(b * H_SZ + h) * L_SZ + l] = tanhf(ps * (s + pb[h]));
    }
}

// ---------------------------------------------------------------------------
extern "C" void kernel_launch(void* const* d_in, const int* in_sizes, int n_in,
                              void* d_out, int out_size)
{
    const float* x      = (const float*)d_in[0];
    const float* qkv_w  = (const float*)d_in[1];
    const float* qkv_b  = (const float*)d_in[2];
    const float* out_w  = (const float*)d_in[3];
    const float* out_b  = (const float*)d_in[4];
    const float* ph_w   = (const float*)d_in[5];
    const float* ph_b   = (const float*)d_in[6];
    const float* rs_ptr = (const float*)d_in[7];
    const float* ps_ptr = (const float*)d_in[8];

    float* out_proj = (float*)d_out;                       // [2,2048,1024]
    float* attn     = out_proj + (size_t)MTOK * D_SZ;      // [2,16,2048,2048]

    float *qkv_ptr, *o_ptr;
    cudaGetSymbolAddress((void**)&qkv_ptr, g_qkv);
    cudaGetSymbolAddress((void**)&o_ptr,  g_o);

    const int SMEM_GEMM   = 2 * 12288 * 4;              // 98304
    const int SMEM_SCORES = (16384 + 256 + 512) * 4;    // 68608
    const int SMEM_AV     = (16384 + 2 * 2304) * 4;     // 83968

    cudaFuncSetAttribute(gemm_mma,   cudaFuncAttributeMaxDynamicSharedMemorySize, SMEM_GEMM);
    cudaFuncSetAttribute(scores_mma, cudaFuncAttributeMaxDynamicSharedMemorySize, SMEM_SCORES);
    cudaFuncSetAttribute(av_fused,   cudaFuncAttributeMaxDynamicSharedMemorySize, SMEM_AV);

    // 1) fused QKV projection
    gemm_mma<<<dim3(E3_SZ / 256, MTOK / 128), 256, SMEM_GEMM>>>(
        x, qkv_w, qkv_b, qkv_ptr, E3_SZ, D_SZ);

    // 2) per-head phase values
    phase_kernel<<<MTOK, 512>>>(x, ph_w, ph_b, ps_ptr);

    // 3) raw biased scores + per-tile softmax partials
    scores_mma<<<dim3(L_SZ / 128, L_SZ / 128, BH_SZ), 128, SMEM_SCORES>>>(rs_ptr, attn);

    // 4) merge partials -> per-row M, 1/S
    reduce_stats<<<BH_SZ * L_SZ / 256, 256>>>();

    // 5) fused normalize + attn write + AV
    av_fused<<<dim3(L_SZ / 256, BH_SZ), 128, SMEM_AV>>>(attn);

    // 6) output projection
    gemm_mma<<<dim3(D_SZ / 256, MTOK / 128), 256, SMEM_GEMM>>>(
        o_ptr, out_w, out_b, out_proj, D_SZ, D_SZ);
}

// round 6
// speedup vs baseline: 2.0746x; 1.0151x over previous
#include <cuda_runtime.h>
#include <math.h>
#include <stdint.h>

// Problem constants
#define B_SZ   2
#define L_SZ   2048
#define D_SZ   1024
#define H_SZ   16
#define E3_SZ  3072
#define MTOK   (B_SZ * L_SZ)        // 4096
#define BH_SZ  32

#define NEG_INF __int_as_float(0xff800000)

// Scratch (device globals; allocation is forbidden)
__device__ float g_qkv[(size_t)MTOK * E3_SZ];    // [4096, 3072]
__device__ float g_phase[(size_t)BH_SZ * L_SZ];  // [bh, l]
__device__ float g_o[(size_t)MTOK * D_SZ];       // [4096, 1024]
__device__ float g_pmax[(size_t)BH_SZ * 16 * L_SZ];  // per-tile row max
__device__ float g_psum[(size_t)BH_SZ * 16 * L_SZ];  // per-tile row sumexp
__device__ float g_corr[(size_t)BH_SZ * 16 * L_SZ];  // exp(m_t - M) / S

// ---------------------------------------------------------------------------
// tf32 mma.sync helpers (arch-portable, sm_80+)
// ---------------------------------------------------------------------------
__device__ __forceinline__ uint32_t tf32r(float f) {
    uint32_t r;
    asm("cvt.rna.tf32.f32 %0, %1;" : "=r"(r) : "f"(f));
    return r;
}
__device__ __forceinline__ void mma_tf32(float c[4], const uint32_t a[4],
                                         const uint32_t b[2]) {
    asm volatile(
        "mma.sync.aligned.m16n8k8.row.col.f32.tf32.tf32.f32 "
        "{%0,%1,%2,%3}, {%4,%5,%6,%7}, {%8,%9}, {%0,%1,%2,%3};"
        : "+f"(c[0]), "+f"(c[1]), "+f"(c[2]), "+f"(c[3])
        : "r"(a[0]), "r"(a[1]), "r"(a[2]), "r"(a[3]), "r"(b[0]), "r"(b[1]));
}

// ===========================================================================
// GEMM: C[M,N] = A[M,K] @ B[N,K]^T + bias[N]
// CTA 128x256, 8 warps (2x4), warp tile 64x64, k-chunk 32, double-buffered.
// SMEM: 32-word rows, XOR-swizzle group' = g ^ (row & 7) -> conflict-free.
// ===========================================================================
__global__ void __launch_bounds__(256) gemm_mma(
    const float* __restrict__ A, const float* __restrict__ Bm,
    const float* __restrict__ bias, float* __restrict__ C, int N, int K)
{
    extern __shared__ uint32_t sm[];
    const int tid = threadIdx.x, wid = tid >> 5, lane = tid & 31;
    const int gid = lane >> 2, tig = lane & 3;
    const int wy = wid >> 2, wx = wid & 3;
    const int tm = blockIdx.y * 128, tn = blockIdx.x * 256;

    const int ar = tid >> 1, ac = (tid & 1) << 4;
    const float* ag = A  + (size_t)(tm + ar)  * K + ac;
    const float* bg = Bm + (size_t)(tn + tid) * K;

    float acc[4][8][4];
#pragma unroll
    for (int i = 0; i < 4; ++i)
#pragma unroll
        for (int j = 0; j < 8; ++j)
#pragma unroll
            for (int v = 0; v < 4; ++v) acc[i][j][v] = 0.f;

    const int T = K >> 5;

#define G_LOAD(t, s) do {                                                    \
    const float* _ap = ag + (t) * 32;                                        \
    const float* _bp = bg + (t) * 32;                                        \
    uint32_t* _ad = sm + (s) * 12288 + ar * 32;                              \
    uint32_t* _bd = sm + (s) * 12288 + 4096 + tid * 32;                      \
    _Pragma("unroll")                                                        \
    for (int j = 0; j < 4; ++j) {                                            \
        float4 v = *(const float4*)(_ap + j * 4);                            \
        int g = (ac >> 2) + j;                                               \
        uint4 w = {tf32r(v.x), tf32r(v.y), tf32r(v.z), tf32r(v.w)};          \
        *(uint4*)(_ad + ((g ^ (ar & 7)) << 2)) = w;                          \
    }                                                                        \
    _Pragma("unroll")                                                        \
    for (int j = 0; j < 8; ++j) {                                            \
        float4 v = *(const float4*)(_bp + j * 4);                            \
        uint4 w = {tf32r(v.x), tf32r(v.y), tf32r(v.z), tf32r(v.w)};          \
        *(uint4*)(_bd + ((j ^ (tid & 7)) << 2)) = w;                         \
    }                                                                        \
} while (0)

    G_LOAD(0, 0);
    __syncthreads();

    for (int t = 0; t < T; ++t) {
        if (t + 1 < T) G_LOAD(t + 1, (t + 1) & 1);
        const uint32_t* as = sm + (t & 1) * 12288;
        const uint32_t* bs = as + 4096;
#pragma unroll
        for (int k8 = 0; k8 < 32; k8 += 8) {
            const int kg = k8 >> 2;
            const int c1 = (kg ^ gid) << 2, c2 = ((kg + 1) ^ gid) << 2;
            uint32_t a[4][4], b[8][2];
#pragma unroll
            for (int mi = 0; mi < 4; ++mi) {
                int r0 = wy * 64 + mi * 16 + gid;
                const uint32_t* p0 = as + r0 * 32 + tig;
                a[mi][0] = p0[c1];
                a[mi][1] = p0[256 + c1];
                a[mi][2] = p0[c2];
                a[mi][3] = p0[256 + c2];
            }
#pragma unroll
            for (int ni = 0; ni < 8; ++ni) {
                int c0 = wx * 64 + ni * 8 + gid;
                const uint32_t* q = bs + c0 * 32 + tig;
                b[ni][0] = q[c1];
                b[ni][1] = q[c2];
            }
#pragma unroll
            for (int mi = 0; mi < 4; ++mi)
#pragma unroll
                for (int ni = 0; ni < 8; ++ni)
                    mma_tf32(acc[mi][ni], a[mi], b[ni]);
        }
        __syncthreads();
    }

#pragma unroll
    for (int mi = 0; mi < 4; ++mi) {
        int row = tm + wy * 64 + mi * 16 + gid;
#pragma unroll
        for (int ni = 0; ni < 8; ++ni) {
            int col = tn + wx * 64 + ni * 8 + tig * 2;
            float b0 = bias[col], b1 = bias[col + 1];
            float2 o0 = {acc[mi][ni][0] + b0, acc[mi][ni][1] + b1};
            float2 o1 = {acc[mi][ni][2] + b0, acc[mi][ni][3] + b1};
            *(float2*)(C + (size_t)row * N + col)       = o0;
            *(float2*)(C + (size_t)(row + 8) * N + col) = o1;
        }
    }
}

// ===========================================================================
// Scores pass: computes s = (q.k)/8 - rs*(pv_i-pv_j)^2, then writes
// t = exp(s - tileMax) to attn, plus per-(tile,row) max & sumexp partials.
// The SINGLE exp of the whole pipeline happens here.
// CTA 128x128, 4 warps (2x2), warp tile 64x64.
// ===========================================================================
__global__ void __launch_bounds__(128) scores_mma(
    const float* __restrict__ rs_ptr, float* __restrict__ attn)
{
    extern __shared__ uint32_t sm[];
    uint32_t* Qs = sm;                 // 2 * 4096
    uint32_t* Ks = sm + 8192;          // 2 * 4096
    float* pq = (float*)(sm + 16384);  // 128
    float* pk = pq + 128;              // 128
    float* sm_m = pk + 128;            // 256: [wx][row]
    float* sm_s = sm_m + 256;          // 256

    const int tid = threadIdx.x, wid = tid >> 5, lane = tid & 31;
    const int gid = lane >> 2, tig = lane & 3;
    const int wy = wid >> 1, wx = wid & 1;
    const int bh = blockIdx.z, b = bh >> 4, h = bh & 15;
    const int tm = blockIdx.y * 128, tn = blockIdx.x * 128;

    const float* qg = g_qkv + (size_t)(b * L_SZ + tm + tid) * E3_SZ + h * 64;
    const float* kg = g_qkv + (size_t)(b * L_SZ + tn + tid) * E3_SZ + D_SZ + h * 64;
#pragma unroll
    for (int j = 0; j < 16; ++j) {
        float4 qv = *(const float4*)(qg + j * 4);
        float4 kv = *(const float4*)(kg + j * 4);
        int off = (j >> 3) * 4096 + tid * 32 + (((j & 7) ^ (tid & 7)) << 2);
        uint4 qt = {tf32r(qv.x), tf32r(qv.y), tf32r(qv.z), tf32r(qv.w)};
        uint4 kt = {tf32r(kv.x), tf32r(kv.y), tf32r(kv.z), tf32r(kv.w)};
        *(uint4*)(Qs + off) = qt;
        *(uint4*)(Ks + off) = kt;
    }
    pq[tid] = g_phase[(size_t)bh * L_SZ + tm + tid];
    pk[tid] = g_phase[(size_t)bh * L_SZ + tn + tid];
    __syncthreads();

    float acc[4][8][4];
#pragma unroll
    for (int i = 0; i < 4; ++i)
#pragma unroll
        for (int j = 0; j < 8; ++j)
#pragma unroll
            for (int v = 0; v < 4; ++v) acc[i][j][v] = 0.f;

#pragma unroll
    for (int k8 = 0; k8 < 64; k8 += 8) {
        const uint32_t* as = Qs + (k8 >> 5) * 4096;
        const uint32_t* bs = Ks + (k8 >> 5) * 4096;
        const int kg = (k8 >> 2) & 7;
        const int c1 = (kg ^ gid) << 2, c2 = ((kg + 1) ^ gid) << 2;
        uint32_t a[4][4], b2[8][2];
#pragma unroll
        for (int mi = 0; mi < 4; ++mi) {
            int r0 = wy * 64 + mi * 16 + gid;
            const uint32_t* p0 = as + r0 * 32 + tig;
            a[mi][0] = p0[c1];
            a[mi][1] = p0[256 + c1];
            a[mi][2] = p0[c2];
            a[mi][3] = p0[256 + c2];
        }
#pragma unroll
        for (int ni = 0; ni < 8; ++ni) {
            int c0 = wx * 64 + ni * 8 + gid;
            const uint32_t* q = bs + c0 * 32 + tig;
            b2[ni][0] = q[c1];
            b2[ni][1] = q[c2];
        }
#pragma unroll
        for (int mi = 0; mi < 4; ++mi)
#pragma unroll
            for (int ni = 0; ni < 8; ++ni)
                mma_tf32(acc[mi][ni], a[mi], b2[ni]);
    }

    const float rs = *rs_ptr;
    // biased scores in registers
#pragma unroll
    for (int mi = 0; mi < 4; ++mi) {
        int r0 = wy * 64 + mi * 16 + gid;
        float pq0 = pq[r0], pq1 = pq[r0 + 8];
#pragma unroll
        for (int ni = 0; ni < 8; ++ni) {
            int c0 = wx * 64 + ni * 8 + tig * 2;
            float k0 = pk[c0], k1 = pk[c0 + 1];
            float d00 = pq0 - k0, d01 = pq0 - k1;
            float d10 = pq1 - k0, d11 = pq1 - k1;
            acc[mi][ni][0] = acc[mi][ni][0] * 0.125f - rs * d00 * d00;
            acc[mi][ni][1] = acc[mi][ni][1] * 0.125f - rs * d01 * d01;
            acc[mi][ni][2] = acc[mi][ni][2] * 0.125f - rs * d10 * d10;
            acc[mi][ni][3] = acc[mi][ni][3] * 0.125f - rs * d11 * d11;
        }
    }

    // --- per-row tile max (per warp-half) ---
#pragma unroll
    for (int mi = 0; mi < 4; ++mi) {
        float mx0 = NEG_INF, mx1 = NEG_INF;
#pragma unroll
        for (int ni = 0; ni < 8; ++ni) {
            mx0 = fmaxf(mx0, fmaxf(acc[mi][ni][0], acc[mi][ni][1]));
            mx1 = fmaxf(mx1, fmaxf(acc[mi][ni][2], acc[mi][ni][3]));
        }
        mx0 = fmaxf(mx0, __shfl_xor_sync(0xffffffff, mx0, 1));
        mx0 = fmaxf(mx0, __shfl_xor_sync(0xffffffff, mx0, 2));
        mx1 = fmaxf(mx1, __shfl_xor_sync(0xffffffff, mx1, 1));
        mx1 = fmaxf(mx1, __shfl_xor_sync(0xffffffff, mx1, 2));
        if (tig == 0) {
            int r0 = wy * 64 + mi * 16 + gid;
            sm_m[wx * 128 + r0]     = mx0;
            sm_m[wx * 128 + r0 + 8] = mx1;
        }
    }
    __syncthreads();

    // --- t = exp(s - tileMax); write t; accumulate per-row sums ---
#pragma unroll
    for (int mi = 0; mi < 4; ++mi) {
        int r0 = wy * 64 + mi * 16 + gid;
        float tM0 = fmaxf(sm_m[r0],     sm_m[128 + r0]);
        float tM1 = fmaxf(sm_m[r0 + 8], sm_m[128 + r0 + 8]);
        float s0 = 0.f, s1 = 0.f;
#pragma unroll
        for (int ni = 0; ni < 8; ++ni) {
            int c0 = wx * 64 + ni * 8 + tig * 2;
            float t00 = __expf(acc[mi][ni][0] - tM0);
            float t01 = __expf(acc[mi][ni][1] - tM0);
            float t10 = __expf(acc[mi][ni][2] - tM1);
            float t11 = __expf(acc[mi][ni][3] - tM1);
            s0 += t00 + t01;
            s1 += t10 + t11;
            float* base = attn + ((size_t)bh * L_SZ + tm + r0) * L_SZ + tn + c0;
            *(float2*)base                      = make_float2(t00, t01);
            *(float2*)(base + (size_t)8 * L_SZ) = make_float2(t10, t11);
        }
        s0 += __shfl_xor_sync(0xffffffff, s0, 1);
        s0 += __shfl_xor_sync(0xffffffff, s0, 2);
        s1 += __shfl_xor_sync(0xffffffff, s1, 1);
        s1 += __shfl_xor_sync(0xffffffff, s1, 2);
        if (tig == 0) {
            sm_s[wx * 128 + r0]     = s0;
            sm_s[wx * 128 + r0 + 8] = s1;
        }
    }
    __syncthreads();

    {
        float M = fmaxf(sm_m[tid], sm_m[128 + tid]);
        float S = sm_s[tid] + sm_s[128 + tid];
        size_t o = ((size_t)bh * 16 + blockIdx.x) * L_SZ + tm + tid;
        g_pmax[o] = M;
        g_psum[o] = S;
    }
}

// ===========================================================================
// Merge per-tile partials into per-(row,tile) correction:
//   corr[bh,t,row] = exp(m_t - M) / S
// ===========================================================================
__global__ void __launch_bounds__(256) reduce_stats()
{
    const int idx = blockIdx.x * 256 + threadIdx.x;   // bh*2048 + row
    const int bh = idx >> 11, row = idx & 2047;
    float m[16], M = NEG_INF;
#pragma unroll
    for (int t = 0; t < 16; ++t) {
        m[t] = g_pmax[((size_t)bh * 16 + t) * L_SZ + row];
        M = fmaxf(M, m[t]);
    }
    float S = 0.f;
    float e[16];
#pragma unroll
    for (int t = 0; t < 16; ++t) {
        e[t] = __expf(m[t] - M);
        S += g_psum[((size_t)bh * 16 + t) * L_SZ + row] * e[t];
    }
    const float invS = 1.0f / S;
#pragma unroll
    for (int t = 0; t < 16; ++t)
        g_corr[((size_t)bh * 16 + t) * L_SZ + row] = e[t] * invS;
}

// ===========================================================================
// Fused normalize + attn write + AV (exp-free).
// p = t * corr[row, ktile]; writes p in place; O = P @ V via tf32 mma.
// CTA 256(m) x 64(d), 4 warps, warp tile 64x64, k-chunk 32, double-buffered.
// ===========================================================================
__global__ void __launch_bounds__(128) av_fused(float* __restrict__ attn)
{
    extern __shared__ uint32_t sm[];
    const int tid = threadIdx.x, wid = tid >> 5, lane = tid & 31;
    const int gid = lane >> 2, tig = lane & 3;
    const int bh = blockIdx.y, b = bh >> 4, h = bh & 15;
    const int tm = blockIdx.x * 256;

    const int pr = tid >> 1, ph = tid & 1;
    float* pg = attn + ((size_t)bh * L_SZ + tm + pr) * L_SZ + ph * 16;
    const float* vg = g_qkv + (size_t)(b * L_SZ + (tid >> 2)) * E3_SZ + 2 * D_SZ
                      + h * 64 + (tid & 3) * 16;
    const float* cg = g_corr + (size_t)bh * 16 * L_SZ + tm + pr;

    float acc[4][8][4];
#pragma unroll
    for (int i = 0; i < 4; ++i)
#pragma unroll
        for (int j = 0; j < 8; ++j)
#pragma unroll
            for (int v = 0; v < 4; ++v) acc[i][j][v] = 0.f;

#define AV_LOAD(t, s) do {                                                   \
    const float* _cb = cg + ((t) >> 2) * L_SZ;                               \
    _Pragma("unroll")                                                        \
    for (int it = 0; it < 4; ++it) {                                         \
        float corr = _cb[it * 64];                                           \
        float* _pp = pg + (size_t)it * 64 * L_SZ + (t) * 32;                 \
        uint32_t* _pd = sm + (s) * 8192 + (pr + it * 64) * 32;               \
        _Pragma("unroll")                                                    \
        for (int j = 0; j < 4; ++j) {                                        \
            float4 v = *(const float4*)(_pp + j * 4);                        \
            float4 p;                                                        \
            p.x = v.x * corr; p.y = v.y * corr;                              \
            p.z = v.z * corr; p.w = v.w * corr;                              \
            *(float4*)(_pp + j * 4) = p;                                     \
            int g = ph * 4 + j;                                              \
            uint4 w = {tf32r(p.x), tf32r(p.y), tf32r(p.z), tf32r(p.w)};      \
            *(uint4*)(_pd + ((g ^ (pr & 7)) << 2)) = w;                      \
        }                                                                    \
    }                                                                        \
    {                                                                        \
        const float* _vp = vg + (size_t)(t) * 32 * E3_SZ;                    \
        uint32_t* _vd = sm + 16384 + (s) * 2304 + (tid >> 2) * 72            \
                        + (tid & 3) * 16;                                    \
        _Pragma("unroll")                                                    \
        for (int j = 0; j < 4; ++j) {                                        \
            float4 v = *(const float4*)(_vp + j * 4);                        \
            uint4 w = {tf32r(v.x), tf32r(v.y), tf32r(v.z), tf32r(v.w)};      \
            *(uint4*)(_vd + j * 4) = w;                                      \
        }                                                                    \
    }                                                                        \
} while (0)

    AV_LOAD(0, 0);
    __syncthreads();

    for (int t = 0; t < 64; ++t) {
        if (t + 1 < 64) AV_LOAD(t + 1, (t + 1) & 1);
        const uint32_t* ps = sm + (t & 1) * 8192;
        const uint32_t* vs = sm + 16384 + (t & 1) * 2304;
#pragma unroll
        for (int k8 = 0; k8 < 32; k8 += 8) {
            const int kg = k8 >> 2;
            const int c1 = (kg ^ gid) << 2, c2 = ((kg + 1) ^ gid) << 2;
            uint32_t a[4][4], b2[8][2];
#pragma unroll
            for (int mi = 0; mi < 4; ++mi) {
                int r0 = wid * 64 + mi * 16 + gid;
                const uint32_t* p0 = ps + r0 * 32 + tig;
                a[mi][0] = p0[c1];
                a[mi][1] = p0[256 + c1];
                a[mi][2] = p0[c2];
                a[mi][3] = p0[256 + c2];
            }
#pragma unroll
            for (int ni = 0; ni < 8; ++ni) {
                int c0 = ni * 8 + gid;
                b2[ni][0] = vs[(k8 + tig) * 72 + c0];
                b2[ni][1] = vs[(k8 + tig + 4) * 72 + c0];
            }
#pragma unroll
            for (int mi = 0; mi < 4; ++mi)
#pragma unroll
                for (int ni = 0; ni < 8; ++ni)
                    mma_tf32(acc[mi][ni], a[mi], b2[ni]);
        }
        __syncthreads();
    }

#pragma unroll
    for (int mi = 0; mi < 4; ++mi) {
        int row = tm + wid * 64 + mi * 16 + gid;
#pragma unroll
        for (int ni = 0; ni < 8; ++ni) {
            int col = h * 64 + ni * 8 + tig * 2;
            float2 o0 = {acc[mi][ni][0], acc[mi][ni][1]};
            float2 o1 = {acc[mi][ni][2], acc[mi][ni][3]};
            *(float2*)(g_o + (size_t)(b * L_SZ + row) * D_SZ + col)      = o0;
            *(float2*)(g_o + (size_t)(b * L_SZ + row + 8) * D_SZ + col)  = o1;
        }
    }
}

// ---------------------------------------------------------------------------
// phase_val[bh, l] = tanh(ps * (x[b,l,:] . phase_w[h,:] + phase_b[h]))
// ---------------------------------------------------------------------------
__global__ __launch_bounds__(512) void phase_kernel(
    const float* __restrict__ x, const float* __restrict__ pw,
    const float* __restrict__ pb, const float* __restrict__ ps_ptr)
{
    const int bl = blockIdx.x;
    const int b  = bl >> 11;
    const int l  = bl & 2047;
    __shared__ float xs[1024];
    const int tid = threadIdx.x;
    for (int i = tid; i < 1024; i += 512) xs[i] = x[(size_t)bl * 1024 + i];
    __syncthreads();
    const int h = tid >> 5, lane = tid & 31;
    float s = 0.f;
    const float* w = pw + (size_t)h * 1024;
    for (int d = lane; d < 1024; d += 32) s += xs[d] * w[d];
#pragma unroll
    for (int o = 16; o; o >>= 1) s += __shfl_xor_sync(0xffffffff, s, o);
    if (lane == 0) {
        float ps = *ps_ptr;
        g_phase[(size_t)(b * H_SZ + h) * L_SZ + l] = tanhf(ps * (s + pb[h]));
    }
}

// ---------------------------------------------------------------------------
extern "C" void kernel_launch(void* const* d_in, const int* in_sizes, int n_in,
                              void* d_out, int out_size)
{
    const float* x      = (const float*)d_in[0];
    const float* qkv_w  = (const float*)d_in[1];
    const float* qkv_b  = (const float*)d_in[2];
    const float* out_w  = (const float*)d_in[3];
    const float* out_b  = (const float*)d_in[4];
    const float* ph_w   = (const float*)d_in[5];
    const float* ph_b   = (const float*)d_in[6];
    const float* rs_ptr = (const float*)d_in[7];
    const float* ps_ptr = (const float*)d_in[8];

    float* out_proj = (float*)d_out;                       // [2,2048,1024]
    float* attn     = out_proj + (size_t)MTOK * D_SZ;      // [2,16,2048,2048]

    float *qkv_ptr, *o_ptr;
    cudaGetSymbolAddress((void**)&qkv_ptr, g_qkv);
    cudaGetSymbolAddress((void**)&o_ptr,  g_o);

    const int SMEM_GEMM   = 2 * 12288 * 4;              // 98304
    const int SMEM_SCORES = (16384 + 256 + 512) * 4;    // 68608
    const int SMEM_AV     = (16384 + 2 * 2304) * 4;     // 83968

    cudaFuncSetAttribute(gemm_mma,   cudaFuncAttributeMaxDynamicSharedMemorySize, SMEM_GEMM);
    cudaFuncSetAttribute(scores_mma, cudaFuncAttributeMaxDynamicSharedMemorySize, SMEM_SCORES);
    cudaFuncSetAttribute(av_fused,   cudaFuncAttributeMaxDynamicSharedMemorySize, SMEM_AV);

    // 1) fused QKV projection
    gemm_mma<<<dim3(E3_SZ / 256, MTOK / 128), 256, SMEM_GEMM>>>(
        x, qkv_w, qkv_b, qkv_ptr, E3_SZ, D_SZ);

    // 2) per-head phase values
    phase_kernel<<<MTOK, 512>>>(x, ph_w, ph_b, ps_ptr);

    // 3) t = exp(s - tileMax) + partials (the only exp pass)
    scores_mma<<<dim3(L_SZ / 128, L_SZ / 128, BH_SZ), 128, SMEM_SCORES>>>(rs_ptr, attn);

    // 4) merge partials -> per-(row,tile) corr
    reduce_stats<<<BH_SZ * L_SZ / 256, 256>>>();

    // 5) fused normalize (1 mult) + attn write + AV
    av_fused<<<dim3(L_SZ / 256, BH_SZ), 128, SMEM_AV>>>(attn);

    // 6) output projection
    gemm_mma<<<dim3(D_SZ / 256, MTOK / 128), 256, SMEM_GEMM>>>(
        o_ptr, out_w, out_b, out_proj, D_SZ, D_SZ);
}

// round 7
// speedup vs baseline: 2.3623x; 1.1387x over previous
#include <cuda_runtime.h>
#include <cuda_fp16.h>
#include <math.h>
#include <stdint.h>

// Problem constants
#define B_SZ   2
#define L_SZ   2048
#define D_SZ   1024
#define H_SZ   16
#define E3_SZ  3072
#define MTOK   (B_SZ * L_SZ)        // 4096
#define BH_SZ  32

#define NEG_INF __int_as_float(0xff800000)

// Scratch (device globals; allocation is forbidden)
__device__ float  g_qkv[(size_t)MTOK * E3_SZ];        // [4096, 3072]
__device__ float  g_phase[(size_t)BH_SZ * L_SZ];      // [bh, l]
__device__ float  g_o[(size_t)MTOK * D_SZ];           // [4096, 1024]
__device__ __half g_t[(size_t)BH_SZ * L_SZ * L_SZ];   // unnormalized exp tiles (fp16)
__device__ float  g_pmax[(size_t)BH_SZ * 16 * L_SZ];  // per-tile row max
__device__ float  g_psum[(size_t)BH_SZ * 16 * L_SZ];  // per-tile row sumexp
__device__ float  g_corr[(size_t)BH_SZ * 16 * L_SZ];  // exp(m_t - M) / S

// ---------------------------------------------------------------------------
// fp16 mma.sync helpers (arch-portable, sm_80+); fp32 accumulate.
// ---------------------------------------------------------------------------
__device__ __forceinline__ uint32_t f2h2(float lo, float hi) {
    __half2 h = __floats2half2_rn(lo, hi);
    return *reinterpret_cast<uint32_t*>(&h);
}
__device__ __forceinline__ float2 h22f2(uint32_t w) {
    __half2 h = *reinterpret_cast<__half2*>(&w);
    return __half22float2(h);
}
__device__ __forceinline__ void mma_f16(float c[4], const uint32_t a[4],
                                        const uint32_t b[2]) {
    asm volatile(
        "mma.sync.aligned.m16n8k16.row.col.f32.f16.f16.f32 "
        "{%0,%1,%2,%3}, {%4,%5,%6,%7}, {%8,%9}, {%0,%1,%2,%3};"
        : "+f"(c[0]), "+f"(c[1]), "+f"(c[2]), "+f"(c[3])
        : "r"(a[0]), "r"(a[1]), "r"(a[2]), "r"(a[3]), "r"(b[0]), "r"(b[1]));
}

// ===========================================================================
// GEMM: C[M,N] = A[M,K] @ B[N,K]^T + bias[N]    (fp16 mma, fp32 acc)
// CTA 128x256, 8 warps (2x4), warp tile 64x64, k-chunk 64, double-buffered.
// SMEM rows = 32 half2-words (64 halves); XOR swizzle group' = g ^ (row&7).
// stage s: A @ s*12288 (128x32w), B @ s*12288 + 4096 (256x32w)
// ===========================================================================
__global__ void __launch_bounds__(256) gemm_mma(
    const float* __restrict__ A, const float* __restrict__ Bm,
    const float* __restrict__ bias, float* __restrict__ C, int N, int K)
{
    extern __shared__ uint32_t sm[];
    const int tid = threadIdx.x, wid = tid >> 5, lane = tid & 31;
    const int gid = lane >> 2, tig = lane & 3;
    const int wy = wid >> 2, wx = wid & 3;
    const int tm = blockIdx.y * 128, tn = blockIdx.x * 256;

    const int ar = tid >> 1, ah = tid & 1;
    const float* ag = A  + (size_t)(tm + ar)  * K + ah * 32;
    const float* bg = Bm + (size_t)(tn + tid) * K;

    float acc[4][8][4];
#pragma unroll
    for (int i = 0; i < 4; ++i)
#pragma unroll
        for (int j = 0; j < 8; ++j)
#pragma unroll
            for (int v = 0; v < 4; ++v) acc[i][j][v] = 0.f;

    const int T = K >> 6;

#define G_LOAD(t, s) do {                                                    \
    const float* _ap = ag + (t) * 64;                                        \
    const float* _bp = bg + (t) * 64;                                        \
    uint32_t* _ad = sm + (s) * 12288 + ar * 32;                              \
    uint32_t* _bd = sm + (s) * 12288 + 4096 + tid * 32;                      \
    _Pragma("unroll")                                                        \
    for (int j = 0; j < 4; ++j) {                                            \
        float4 v0 = *(const float4*)(_ap + j * 8);                           \
        float4 v1 = *(const float4*)(_ap + j * 8 + 4);                       \
        int g = ah * 4 + j;                                                  \
        uint4 w = {f2h2(v0.x, v0.y), f2h2(v0.z, v0.w),                       \
                   f2h2(v1.x, v1.y), f2h2(v1.z, v1.w)};                      \
        *(uint4*)(_ad + ((g ^ (ar & 7)) << 2)) = w;                          \
    }                                                                        \
    _Pragma("unroll")                                                        \
    for (int j = 0; j < 8; ++j) {                                            \
        float4 v0 = *(const float4*)(_bp + j * 8);                           \
        float4 v1 = *(const float4*)(_bp + j * 8 + 4);                       \
        uint4 w = {f2h2(v0.x, v0.y), f2h2(v0.z, v0.w),                       \
                   f2h2(v1.x, v1.y), f2h2(v1.z, v1.w)};                      \
        *(uint4*)(_bd + ((j ^ (tid & 7)) << 2)) = w;                         \
    }                                                                        \
} while (0)

    G_LOAD(0, 0);
    __syncthreads();

    for (int t = 0; t < T; ++t) {
        if (t + 1 < T) G_LOAD(t + 1, (t + 1) & 1);
        const uint32_t* as = sm + (t & 1) * 12288;
        const uint32_t* bs = as + 4096;
#pragma unroll
        for (int j = 0; j < 4; ++j) {
            const int c1 = ((2 * j) ^ gid) << 2, c2 = ((2 * j + 1) ^ gid) << 2;
            uint32_t a[4][4], b[8][2];
#pragma unroll
            for (int mi = 0; mi < 4; ++mi) {
                int r0 = wy * 64 + mi * 16 + gid;
                const uint32_t* p0 = as + r0 * 32 + tig;
                a[mi][0] = p0[c1];
                a[mi][1] = p0[256 + c1];
                a[mi][2] = p0[c2];
                a[mi][3] = p0[256 + c2];
            }
#pragma unroll
            for (int ni = 0; ni < 8; ++ni) {
                int c0 = wx * 64 + ni * 8 + gid;
                const uint32_t* q = bs + c0 * 32 + tig;
                b[ni][0] = q[c1];
                b[ni][1] = q[c2];
            }
#pragma unroll
            for (int mi = 0; mi < 4; ++mi)
#pragma unroll
                for (int ni = 0; ni < 8; ++ni)
                    mma_f16(acc[mi][ni], a[mi], b[ni]);
        }
        __syncthreads();
    }

#pragma unroll
    for (int mi = 0; mi < 4; ++mi) {
        int row = tm + wy * 64 + mi * 16 + gid;
#pragma unroll
        for (int ni = 0; ni < 8; ++ni) {
            int col = tn + wx * 64 + ni * 8 + tig * 2;
            float b0 = bias[col], b1 = bias[col + 1];
            float2 o0 = {acc[mi][ni][0] + b0, acc[mi][ni][1] + b1};
            float2 o1 = {acc[mi][ni][2] + b0, acc[mi][ni][3] + b1};
            *(float2*)(C + (size_t)row * N + col)       = o0;
            *(float2*)(C + (size_t)(row + 8) * N + col) = o1;
        }
    }
}

// ===========================================================================
// Scores: s = (q.k)/8 - rs*(pv_i-pv_j)^2; writes t = exp(s - tileMax) as FP16
// to g_t, plus per-(tile,row) max & sumexp partials. The only exp pass.
// CTA 128x128, 4 warps (2x2), warp tile 64x64, dh=64 single stage.
// ===========================================================================
__global__ void __launch_bounds__(128) scores_mma(
    const float* __restrict__ rs_ptr)
{
    extern __shared__ uint32_t sm[];
    uint32_t* Qs = sm;                 // 4096 words
    uint32_t* Ks = sm + 4096;          // 4096 words
    float* pq = (float*)(sm + 8192);   // 128
    float* pk = pq + 128;              // 128
    float* sm_m = pk + 128;            // 256
    float* sm_s = sm_m + 256;          // 256

    const int tid = threadIdx.x, wid = tid >> 5, lane = tid & 31;
    const int gid = lane >> 2, tig = lane & 3;
    const int wy = wid >> 1, wx = wid & 1;
    const int bh = blockIdx.z, b = bh >> 4, h = bh & 15;
    const int tm = blockIdx.y * 128, tn = blockIdx.x * 128;

    const float* qg = g_qkv + (size_t)(b * L_SZ + tm + tid) * E3_SZ + h * 64;
    const float* kg = g_qkv + (size_t)(b * L_SZ + tn + tid) * E3_SZ + D_SZ + h * 64;
#pragma unroll
    for (int j = 0; j < 8; ++j) {
        float4 q0 = *(const float4*)(qg + j * 8);
        float4 q1 = *(const float4*)(qg + j * 8 + 4);
        float4 k0 = *(const float4*)(kg + j * 8);
        float4 k1 = *(const float4*)(kg + j * 8 + 4);
        int off = tid * 32 + ((j ^ (tid & 7)) << 2);
        uint4 qw = {f2h2(q0.x, q0.y), f2h2(q0.z, q0.w),
                    f2h2(q1.x, q1.y), f2h2(q1.z, q1.w)};
        uint4 kw = {f2h2(k0.x, k0.y), f2h2(k0.z, k0.w),
                    f2h2(k1.x, k1.y), f2h2(k1.z, k1.w)};
        *(uint4*)(Qs + off) = qw;
        *(uint4*)(Ks + off) = kw;
    }
    pq[tid] = g_phase[(size_t)bh * L_SZ + tm + tid];
    pk[tid] = g_phase[(size_t)bh * L_SZ + tn + tid];
    __syncthreads();

    float acc[4][8][4];
#pragma unroll
    for (int i = 0; i < 4; ++i)
#pragma unroll
        for (int j = 0; j < 8; ++j)
#pragma unroll
            for (int v = 0; v < 4; ++v) acc[i][j][v] = 0.f;

#pragma unroll
    for (int j = 0; j < 4; ++j) {
        const int c1 = ((2 * j) ^ gid) << 2, c2 = ((2 * j + 1) ^ gid) << 2;
        uint32_t a[4][4], b2[8][2];
#pragma unroll
        for (int mi = 0; mi < 4; ++mi) {
            int r0 = wy * 64 + mi * 16 + gid;
            const uint32_t* p0 = Qs + r0 * 32 + tig;
            a[mi][0] = p0[c1];
            a[mi][1] = p0[256 + c1];
            a[mi][2] = p0[c2];
            a[mi][3] = p0[256 + c2];
        }
#pragma unroll
        for (int ni = 0; ni < 8; ++ni) {
            int c0 = wx * 64 + ni * 8 + gid;
            const uint32_t* q = Ks + c0 * 32 + tig;
            b2[ni][0] = q[c1];
            b2[ni][1] = q[c2];
        }
#pragma unroll
        for (int mi = 0; mi < 4; ++mi)
#pragma unroll
            for (int ni = 0; ni < 8; ++ni)
                mma_f16(acc[mi][ni], a[mi], b2[ni]);
    }

    const float rs = *rs_ptr;
#pragma unroll
    for (int mi = 0; mi < 4; ++mi) {
        int r0 = wy * 64 + mi * 16 + gid;
        float pq0 = pq[r0], pq1 = pq[r0 + 8];
#pragma unroll
        for (int ni = 0; ni < 8; ++ni) {
            int c0 = wx * 64 + ni * 8 + tig * 2;
            float k0 = pk[c0], k1 = pk[c0 + 1];
            float d00 = pq0 - k0, d01 = pq0 - k1;
            float d10 = pq1 - k0, d11 = pq1 - k1;
            acc[mi][ni][0] = acc[mi][ni][0] * 0.125f - rs * d00 * d00;
            acc[mi][ni][1] = acc[mi][ni][1] * 0.125f - rs * d01 * d01;
            acc[mi][ni][2] = acc[mi][ni][2] * 0.125f - rs * d10 * d10;
            acc[mi][ni][3] = acc[mi][ni][3] * 0.125f - rs * d11 * d11;
        }
    }

    // per-row tile max
#pragma unroll
    for (int mi = 0; mi < 4; ++mi) {
        float mx0 = NEG_INF, mx1 = NEG_INF;
#pragma unroll
        for (int ni = 0; ni < 8; ++ni) {
            mx0 = fmaxf(mx0, fmaxf(acc[mi][ni][0], acc[mi][ni][1]));
            mx1 = fmaxf(mx1, fmaxf(acc[mi][ni][2], acc[mi][ni][3]));
        }
        mx0 = fmaxf(mx0, __shfl_xor_sync(0xffffffff, mx0, 1));
        mx0 = fmaxf(mx0, __shfl_xor_sync(0xffffffff, mx0, 2));
        mx1 = fmaxf(mx1, __shfl_xor_sync(0xffffffff, mx1, 1));
        mx1 = fmaxf(mx1, __shfl_xor_sync(0xffffffff, mx1, 2));
        if (tig == 0) {
            int r0 = wy * 64 + mi * 16 + gid;
            sm_m[wx * 128 + r0]     = mx0;
            sm_m[wx * 128 + r0 + 8] = mx1;
        }
    }
    __syncthreads();

    // t = exp(s - tileMax); fp16 store to g_t; per-row sums
#pragma unroll
    for (int mi = 0; mi < 4; ++mi) {
        int r0 = wy * 64 + mi * 16 + gid;
        float tM0 = fmaxf(sm_m[r0],     sm_m[128 + r0]);
        float tM1 = fmaxf(sm_m[r0 + 8], sm_m[128 + r0 + 8]);
        float s0 = 0.f, s1 = 0.f;
#pragma unroll
        for (int ni = 0; ni < 8; ++ni) {
            int c0 = wx * 64 + ni * 8 + tig * 2;
            float t00 = __expf(acc[mi][ni][0] - tM0);
            float t01 = __expf(acc[mi][ni][1] - tM0);
            float t10 = __expf(acc[mi][ni][2] - tM1);
            float t11 = __expf(acc[mi][ni][3] - tM1);
            s0 += t00 + t01;
            s1 += t10 + t11;
            size_t base = ((size_t)bh * L_SZ + tm + r0) * L_SZ + tn + c0;
            *(uint32_t*)(g_t + base)                      = f2h2(t00, t01);
            *(uint32_t*)(g_t + base + (size_t)8 * L_SZ)   = f2h2(t10, t11);
        }
        s0 += __shfl_xor_sync(0xffffffff, s0, 1);
        s0 += __shfl_xor_sync(0xffffffff, s0, 2);
        s1 += __shfl_xor_sync(0xffffffff, s1, 1);
        s1 += __shfl_xor_sync(0xffffffff, s1, 2);
        if (tig == 0) {
            sm_s[wx * 128 + r0]     = s0;
            sm_s[wx * 128 + r0 + 8] = s1;
        }
    }
    __syncthreads();

    {
        float M = fmaxf(sm_m[tid], sm_m[128 + tid]);
        float S = sm_s[tid] + sm_s[128 + tid];
        size_t o = ((size_t)bh * 16 + blockIdx.x) * L_SZ + tm + tid;
        g_pmax[o] = M;
        g_psum[o] = S;
    }
}

// ===========================================================================
// Merge per-tile partials into corr[bh,t,row] = exp(m_t - M) / S
// ===========================================================================
__global__ void __launch_bounds__(256) reduce_stats()
{
    const int idx = blockIdx.x * 256 + threadIdx.x;   // bh*2048 + row
    const int bh = idx >> 11, row = idx & 2047;
    float m[16], M = NEG_INF;
#pragma unroll
    for (int t = 0; t < 16; ++t) {
        m[t] = g_pmax[((size_t)bh * 16 + t) * L_SZ + row];
        M = fmaxf(M, m[t]);
    }
    float S = 0.f;
    float e[16];
#pragma unroll
    for (int t = 0; t < 16; ++t) {
        e[t] = __expf(m[t] - M);
        S += g_psum[((size_t)bh * 16 + t) * L_SZ + row] * e[t];
    }
    const float invS = 1.0f / S;
#pragma unroll
    for (int t = 0; t < 16; ++t)
        g_corr[((size_t)bh * 16 + t) * L_SZ + row] = e[t] * invS;
}

// ===========================================================================
// Fused normalize + attn write + AV (fp16 mma).
// Reads fp16 t, p = t*corr -> fp32 attn (final output) and fp16 SMEM for mma.
// V transposed to SMEM [d][kpair] stride 36 (conflict-free).
// CTA 256(m) x 64(d), 4 warps, k-chunk 64, double-buffered.
// stage s: P @ s*10496 (256x32w), V @ s*10496 + 8192 (64x36w)
// ===========================================================================
__global__ void __launch_bounds__(128) av_fused(float* __restrict__ attn)
{
    extern __shared__ uint32_t sm[];
    const int tid = threadIdx.x, wid = tid >> 5, lane = tid & 31;
    const int gid = lane >> 2, tig = lane & 3;
    const int bh = blockIdx.y, b = bh >> 4, h = bh & 15;
    const int tm = blockIdx.x * 256;

    const int pr = tid >> 1, ph = tid & 1;
    const __half* tg = g_t + ((size_t)bh * L_SZ + tm + pr) * L_SZ + ph * 32;
    float* ag = attn + ((size_t)bh * L_SZ + tm + pr) * L_SZ + ph * 32;
    const float* vbase = g_qkv + (size_t)b * L_SZ * E3_SZ + 2 * D_SZ + h * 64;
    const float* cg = g_corr + (size_t)bh * 16 * L_SZ + tm + pr;

    float acc[4][8][4];
#pragma unroll
    for (int i = 0; i < 4; ++i)
#pragma unroll
        for (int j = 0; j < 8; ++j)
#pragma unroll
            for (int v = 0; v < 4; ++v) acc[i][j][v] = 0.f;

#define AV_LOAD(t, s) do {                                                   \
    const float* _cb = cg + ((t) >> 1) * L_SZ;                               \
    _Pragma("unroll")                                                        \
    for (int it = 0; it < 4; ++it) {                                         \
        float corr = _cb[it * 64];                                           \
        const __half* _tp = tg + (size_t)it * 64 * L_SZ + (t) * 64;          \
        float* _aw = ag + (size_t)it * 64 * L_SZ + (t) * 64;                 \
        uint32_t* _pd = sm + (s) * 10496 + (pr + it * 64) * 32;              \
        _Pragma("unroll")                                                    \
        for (int j = 0; j < 4; ++j) {                                        \
            uint4 w = *(const uint4*)(_tp + j * 8);                          \
            float2 f0 = h22f2(w.x), f1 = h22f2(w.y);                         \
            float2 f2 = h22f2(w.z), f3 = h22f2(w.w);                         \
            f0.x *= corr; f0.y *= corr; f1.x *= corr; f1.y *= corr;          \
            f2.x *= corr; f2.y *= corr; f3.x *= corr; f3.y *= corr;          \
            float4 o0 = {f0.x, f0.y, f1.x, f1.y};                            \
            float4 o1 = {f2.x, f2.y, f3.x, f3.y};                            \
            *(float4*)(_aw + j * 8)     = o0;                                \
            *(float4*)(_aw + j * 8 + 4) = o1;                                \
            int g = ph * 4 + j;                                              \
            uint4 pw = {f2h2(f0.x, f0.y), f2h2(f1.x, f1.y),                  \
                        f2h2(f2.x, f2.y), f2h2(f3.x, f3.y)};                 \
            *(uint4*)(_pd + ((g ^ (pr & 7)) << 2)) = pw;                     \
        }                                                                    \
    }                                                                        \
    _Pragma("unroll")                                                        \
    for (int c = 0; c < 4; ++c) {                                            \
        int id = tid + c * 128;                                              \
        int kp = id & 31, d4 = id >> 5;                                      \
        const float* _vp = vbase + (size_t)((t) * 64 + 2 * kp) * E3_SZ       \
                           + d4 * 4;                                         \
        float4 v0 = *(const float4*)_vp;                                     \
        float4 v1 = *(const float4*)(_vp + E3_SZ);                           \
        uint32_t* _vd = sm + (s) * 10496 + 8192 + kp;                        \
        _vd[(d4 * 4 + 0) * 36] = f2h2(v0.x, v1.x);                           \
        _vd[(d4 * 4 + 1) * 36] = f2h2(v0.y, v1.y);                           \
        _vd[(d4 * 4 + 2) * 36] = f2h2(v0.z, v1.z);                           \
        _vd[(d4 * 4 + 3) * 36] = f2h2(v0.w, v1.w);                           \
    }                                                                        \
} while (0)

    AV_LOAD(0, 0);
    __syncthreads();

    for (int t = 0; t < 32; ++t) {
        if (t + 1 < 32) AV_LOAD(t + 1, (t + 1) & 1);
        const uint32_t* ps = sm + (t & 1) * 10496;
        const uint32_t* vs = ps + 8192;
#pragma unroll
        for (int j = 0; j < 4; ++j) {
            const int c1 = ((2 * j) ^ gid) << 2, c2 = ((2 * j + 1) ^ gid) << 2;
            uint32_t a[4][4], b2[8][2];
#pragma unroll
            for (int mi = 0; mi < 4; ++mi) {
                int r0 = wid * 64 + mi * 16 + gid;
                const uint32_t* p0 = ps + r0 * 32 + tig;
                a[mi][0] = p0[c1];
                a[mi][1] = p0[256 + c1];
                a[mi][2] = p0[c2];
                a[mi][3] = p0[256 + c2];
            }
#pragma unroll
            for (int ni = 0; ni < 8; ++ni) {
                int c0 = ni * 8 + gid;
                b2[ni][0] = vs[c0 * 36 + 8 * j + tig];
                b2[ni][1] = vs[c0 * 36 + 8 * j + 4 + tig];
            }
#pragma unroll
            for (int mi = 0; mi < 4; ++mi)
#pragma unroll
                for (int ni = 0; ni < 8; ++ni)
                    mma_f16(acc[mi][ni], a[mi], b2[ni]);
        }
        __syncthreads();
    }

#pragma unroll
    for (int mi = 0; mi < 4; ++mi) {
        int row = tm + wid * 64 + mi * 16 + gid;
#pragma unroll
        for (int ni = 0; ni < 8; ++ni) {
            int col = h * 64 + ni * 8 + tig * 2;
            float2 o0 = {acc[mi][ni][0], acc[mi][ni][1]};
            float2 o1 = {acc[mi][ni][2], acc[mi][ni][3]};
            *(float2*)(g_o + (size_t)(b * L_SZ + row) * D_SZ + col)      = o0;
            *(float2*)(g_o + (size_t)(b * L_SZ + row + 8) * D_SZ + col)  = o1;
        }
    }
}

// ---------------------------------------------------------------------------
// phase_val[bh, l] = tanh(ps * (x[b,l,:] . phase_w[h,:] + phase_b[h]))
// ---------------------------------------------------------------------------
__global__ __launch_bounds__(512) void phase_kernel(
    const float* __restrict__ x, const float* __restrict__ pw,
    const float* __restrict__ pb, const float* __restrict__ ps_ptr)
{
    const int bl = blockIdx.x;
    const int b  = bl >> 11;
    const int l  = bl & 2047;
    __shared__ float xs[1024];
    const int tid = threadIdx.x;
    for (int i = tid; i < 1024; i += 512) xs[i] = x[(size_t)bl * 1024 + i];
    __syncthreads();
    const int h = tid >> 5, lane = tid & 31;
    float s = 0.f;
    const float* w = pw + (size_t)h * 1024;
    for (int d = lane; d < 1024; d += 32) s += xs[d] * w[d];
#pragma unroll
    for (int o = 16; o; o >>= 1) s += __shfl_xor_sync(0xffffffff, s, o);
    if (lane == 0) {
        float ps = *ps_ptr;
        g_phase[(size_t)(b * H_SZ + h) * L_SZ + l] = tanhf(ps * (s + pb[h]));
    }
}

// ---------------------------------------------------------------------------
extern "C" void kernel_launch(void* const* d_in, const int* in_sizes, int n_in,
                              void* d_out, int out_size)
{
    const float* x      = (const float*)d_in[0];
    const float* qkv_w  = (const float*)d_in[1];
    const float* qkv_b  = (const float*)d_in[2];
    const float* out_w  = (const float*)d_in[3];
    const float* out_b  = (const float*)d_in[4];
    const float* ph_w   = (const float*)d_in[5];
    const float* ph_b   = (const float*)d_in[6];
    const float* rs_ptr = (const float*)d_in[7];
    const float* ps_ptr = (const float*)d_in[8];

    float* out_proj = (float*)d_out;                       // [2,2048,1024]
    float* attn     = out_proj + (size_t)MTOK * D_SZ;      // [2,16,2048,2048]

    float *qkv_ptr, *o_ptr;
    cudaGetSymbolAddress((void**)&qkv_ptr, g_qkv);
    cudaGetSymbolAddress((void**)&o_ptr,  g_o);

    const int SMEM_GEMM   = 2 * 12288 * 4;             // 98304
    const int SMEM_SCORES = (8192 + 768) * 4;          // 35840
    const int SMEM_AV     = 2 * 10496 * 4;             // 83968

    cudaFuncSetAttribute(gemm_mma,   cudaFuncAttributeMaxDynamicSharedMemorySize, SMEM_GEMM);
    cudaFuncSetAttribute(scores_mma, cudaFuncAttributeMaxDynamicSharedMemorySize, SMEM_SCORES);
    cudaFuncSetAttribute(av_fused,   cudaFuncAttributeMaxDynamicSharedMemorySize, SMEM_AV);

    // 1) fused QKV projection (fp16 mma)
    gemm_mma<<<dim3(E3_SZ / 256, MTOK / 128), 256, SMEM_GEMM>>>(
        x, qkv_w, qkv_b, qkv_ptr, E3_SZ, D_SZ);

    // 2) per-head phase values
    phase_kernel<<<MTOK, 512>>>(x, ph_w, ph_b, ps_ptr);

    // 3) t = exp(s - tileMax) -> fp16 g_t + partials (only exp pass)
    scores_mma<<<dim3(L_SZ / 128, L_SZ / 128, BH_SZ), 128, SMEM_SCORES>>>(rs_ptr);

    // 4) merge partials -> per-(row,tile) corr
    reduce_stats<<<BH_SZ * L_SZ / 256, 256>>>();

    // 5) fused normalize + fp32 attn write + AV (fp16 mma)
    av_fused<<<dim3(L_SZ / 256, BH_SZ), 128, SMEM_AV>>>(attn);

    // 6) output projection (fp16 mma)
    gemm_mma<<<dim3(D_SZ / 256, MTOK / 128), 256, SMEM_GEMM>>>(
        o_ptr, out_w, out_b, out_proj, D_SZ, D_SZ);
}

// round 8
// speedup vs baseline: 2.5520x; 1.0803x over previous
#include <cuda_runtime.h>
#include <cuda_fp16.h>
#include <math.h>
#include <stdint.h>

// Problem constants
#define B_SZ   2
#define L_SZ   2048
#define D_SZ   1024
#define H_SZ   16
#define E3_SZ  3072
#define MTOK   (B_SZ * L_SZ)        // 4096
#define BH_SZ  32

#define NEG_INF __int_as_float(0xff800000)

// Scratch (device globals; allocation is forbidden)
__device__ float  g_qkv[(size_t)MTOK * E3_SZ];        // [4096, 3072]
__device__ float  g_phase[(size_t)BH_SZ * L_SZ];      // [bh, l]
__device__ float  g_o[(size_t)MTOK * D_SZ];           // [4096, 1024]

// ---------------------------------------------------------------------------
// fp16 mma.sync helpers (arch-portable, sm_80+); fp32 accumulate.
// ---------------------------------------------------------------------------
__device__ __forceinline__ uint32_t f2h2(float lo, float hi) {
    __half2 h = __floats2half2_rn(lo, hi);
    return *reinterpret_cast<uint32_t*>(&h);
}
__device__ __forceinline__ void mma_f16(float c[4], const uint32_t a[4],
                                        const uint32_t b[2]) {
    asm volatile(
        "mma.sync.aligned.m16n8k16.row.col.f32.f16.f16.f32 "
        "{%0,%1,%2,%3}, {%4,%5,%6,%7}, {%8,%9}, {%0,%1,%2,%3};"
        : "+f"(c[0]), "+f"(c[1]), "+f"(c[2]), "+f"(c[3])
        : "r"(a[0]), "r"(a[1]), "r"(a[2]), "r"(a[3]), "r"(b[0]), "r"(b[1]));
}

// ===========================================================================
// GEMM: C[M,N] = A[M,K] @ B[N,K]^T + bias[N]    (fp16 mma, fp32 acc)
// CTA 128x256, 8 warps (2x4), warp tile 64x64, k-chunk 64, double-buffered.
// ===========================================================================
__global__ void __launch_bounds__(256) gemm_mma(
    const float* __restrict__ A, const float* __restrict__ Bm,
    const float* __restrict__ bias, float* __restrict__ C, int N, int K)
{
    extern __shared__ uint32_t sm[];
    const int tid = threadIdx.x, wid = tid >> 5, lane = tid & 31;
    const int gid = lane >> 2, tig = lane & 3;
    const int wy = wid >> 2, wx = wid & 3;
    const int tm = blockIdx.y * 128, tn = blockIdx.x * 256;

    const int ar = tid >> 1, ah = tid & 1;
    const float* ag = A  + (size_t)(tm + ar)  * K + ah * 32;
    const float* bg = Bm + (size_t)(tn + tid) * K;

    float acc[4][8][4];
#pragma unroll
    for (int i = 0; i < 4; ++i)
#pragma unroll
        for (int j = 0; j < 8; ++j)
#pragma unroll
            for (int v = 0; v < 4; ++v) acc[i][j][v] = 0.f;

    const int T = K >> 6;

#define G_LOAD(t, s) do {                                                    \
    const float* _ap = ag + (t) * 64;                                        \
    const float* _bp = bg + (t) * 64;                                        \
    uint32_t* _ad = sm + (s) * 12288 + ar * 32;                              \
    uint32_t* _bd = sm + (s) * 12288 + 4096 + tid * 32;                      \
    _Pragma("unroll")                                                        \
    for (int j = 0; j < 4; ++j) {                                            \
        float4 v0 = *(const float4*)(_ap + j * 8);                           \
        float4 v1 = *(const float4*)(_ap + j * 8 + 4);                       \
        int g = ah * 4 + j;                                                  \
        uint4 w = {f2h2(v0.x, v0.y), f2h2(v0.z, v0.w),                       \
                   f2h2(v1.x, v1.y), f2h2(v1.z, v1.w)};                      \
        *(uint4*)(_ad + ((g ^ (ar & 7)) << 2)) = w;                          \
    }                                                                        \
    _Pragma("unroll")                                                        \
    for (int j = 0; j < 8; ++j) {                                            \
        float4 v0 = *(const float4*)(_bp + j * 8);                           \
        float4 v1 = *(const float4*)(_bp + j * 8 + 4);                       \
        uint4 w = {f2h2(v0.x, v0.y), f2h2(v0.z, v0.w),                       \
                   f2h2(v1.x, v1.y), f2h2(v1.z, v1.w)};                      \
        *(uint4*)(_bd + ((j ^ (tid & 7)) << 2)) = w;                         \
    }                                                                        \
} while (0)

    G_LOAD(0, 0);
    __syncthreads();

    for (int t = 0; t < T; ++t) {
        if (t + 1 < T) G_LOAD(t + 1, (t + 1) & 1);
        const uint32_t* as = sm + (t & 1) * 12288;
        const uint32_t* bs = as + 4096;
#pragma unroll
        for (int j = 0; j < 4; ++j) {
            const int c1 = ((2 * j) ^ gid) << 2, c2 = ((2 * j + 1) ^ gid) << 2;
            uint32_t a[4][4], b[8][2];
#pragma unroll
            for (int mi = 0; mi < 4; ++mi) {
                int r0 = wy * 64 + mi * 16 + gid;
                const uint32_t* p0 = as + r0 * 32 + tig;
                a[mi][0] = p0[c1];
                a[mi][1] = p0[256 + c1];
                a[mi][2] = p0[c2];
                a[mi][3] = p0[256 + c2];
            }
#pragma unroll
            for (int ni = 0; ni < 8; ++ni) {
                int c0 = wx * 64 + ni * 8 + gid;
                const uint32_t* q = bs + c0 * 32 + tig;
                b[ni][0] = q[c1];
                b[ni][1] = q[c2];
            }
#pragma unroll
            for (int mi = 0; mi < 4; ++mi)
#pragma unroll
                for (int ni = 0; ni < 8; ++ni)
                    mma_f16(acc[mi][ni], a[mi], b[ni]);
        }
        __syncthreads();
    }

#pragma unroll
    for (int mi = 0; mi < 4; ++mi) {
        int row = tm + wy * 64 + mi * 16 + gid;
#pragma unroll
        for (int ni = 0; ni < 8; ++ni) {
            int col = tn + wx * 64 + ni * 8 + tig * 2;
            float b0 = bias[col], b1 = bias[col + 1];
            float2 o0 = {acc[mi][ni][0] + b0, acc[mi][ni][1] + b1};
            float2 o1 = {acc[mi][ni][2] + b0, acc[mi][ni][3] + b1};
            *(float2*)(C + (size_t)row * N + col)       = o0;
            *(float2*)(C + (size_t)(row + 8) * N + col) = o1;
        }
    }
}

// ===========================================================================
// Fused attention: scores + softmax + attn write + AV in ONE kernel.
// CTA = (q-tile of 128 rows, bh). 256 threads = 8 warps.
// Pass A: per k-tile QK^T mma + bias -> per-(tile,row) max & sumexp in SMEM.
// Pass B: recompute s (bitwise identical), p = exp(s-M)*invS, write fp32
//         attn, stage p fp16 in SMEM, AV mma accumulates O.
// SMEM (words): Qs@0(4096) Ks@4096(2x4096) Vs@12288(2x4352) Ps@20992(8704)
//   pk@29696(2048) pq@31744(128) m_all@31872(2048) s_all@33920(2048)
//   Mrow@35968(128) Irow@36096(128) redm@36224(512) reds@36736(512)
//   total 37248 words = 148992 B
// ===========================================================================
#define FST 68
__global__ void __launch_bounds__(256) attn_fused(
    const float* __restrict__ rs_ptr, float* __restrict__ attn)
{
    extern __shared__ uint32_t sm[];
    uint32_t* Qs = sm;
    uint32_t* Ks = sm + 4096;
    uint32_t* Vs = sm + 12288;
    uint32_t* Ps = sm + 20992;
    float* pk_all = (float*)(sm + 29696);
    float* pq     = (float*)(sm + 31744);
    float* m_all  = (float*)(sm + 31872);
    float* s_all  = (float*)(sm + 33920);
    float* Mrow   = (float*)(sm + 35968);
    float* Irow   = (float*)(sm + 36096);
    float* redm   = (float*)(sm + 36224);
    float* reds   = (float*)(sm + 36736);

    const int tid = threadIdx.x, wid = tid >> 5, lane = tid & 31;
    const int gid = lane >> 2, tig = lane & 3;
    const int wy = wid >> 2, wx = wid & 3;      // QK layout: 2x4, s-tile 64x32
    const int wyB = wid >> 1, wxB = wid & 1;    // AV layout: 4x2, O-tile 32x32
    const int bh = blockIdx.y, b = bh >> 4, h = bh & 15;
    const int tm = blockIdx.x * 128;
    const float rs = *rs_ptr;

    const int ar = tid >> 1, ah = tid & 1;

    // --- Q tile (persistent), phase values ---
    {
        const float* qg = g_qkv + (size_t)(b * L_SZ + tm + ar) * E3_SZ + h * 64 + ah * 32;
#pragma unroll
        for (int j = 0; j < 4; ++j) {
            float4 v0 = *(const float4*)(qg + j * 8);
            float4 v1 = *(const float4*)(qg + j * 8 + 4);
            int g = ah * 4 + j;
            uint4 w = {f2h2(v0.x, v0.y), f2h2(v0.z, v0.w),
                       f2h2(v1.x, v1.y), f2h2(v1.z, v1.w)};
            *(uint4*)(Qs + ar * 32 + ((g ^ (ar & 7)) << 2)) = w;
        }
    }
    if (tid < 128) pq[tid] = g_phase[(size_t)bh * L_SZ + tm + tid];
#pragma unroll
    for (int i = 0; i < 8; ++i)
        pk_all[tid + i * 256] = g_phase[(size_t)bh * L_SZ + tid + i * 256];

#define LOAD_K(j, s) do {                                                    \
    const float* _kg = g_qkv + (size_t)(b * L_SZ + (j) * 128 + ar) * E3_SZ   \
                       + D_SZ + h * 64 + ah * 32;                            \
    uint32_t* _kd = Ks + (s) * 4096 + ar * 32;                               \
    _Pragma("unroll")                                                        \
    for (int jj = 0; jj < 4; ++jj) {                                         \
        float4 v0 = *(const float4*)(_kg + jj * 8);                          \
        float4 v1 = *(const float4*)(_kg + jj * 8 + 4);                      \
        int g = ah * 4 + jj;                                                 \
        uint4 w = {f2h2(v0.x, v0.y), f2h2(v0.z, v0.w),                       \
                   f2h2(v1.x, v1.y), f2h2(v1.z, v1.w)};                      \
        *(uint4*)(_kd + ((g ^ (ar & 7)) << 2)) = w;                          \
    }                                                                        \
} while (0)

#define LOAD_V(j, s) do {                                                    \
    int _kp = tid & 63, _dg = tid >> 6;                                      \
    const float* _vp = g_qkv + (size_t)(b * L_SZ + (j) * 128 + 2 * _kp)      \
                       * E3_SZ + 2 * D_SZ + h * 64 + _dg * 16;               \
    uint32_t* _vd = Vs + (s) * 4352 + _kp;                                   \
    _Pragma("unroll")                                                        \
    for (int it = 0; it < 4; ++it) {                                         \
        float4 v0 = *(const float4*)(_vp + it * 4);                          \
        float4 v1 = *(const float4*)(_vp + E3_SZ + it * 4);                  \
        int d = _dg * 16 + it * 4;                                           \
        _vd[(d + 0) * FST] = f2h2(v0.x, v1.x);                               \
        _vd[(d + 1) * FST] = f2h2(v0.y, v1.y);                               \
        _vd[(d + 2) * FST] = f2h2(v0.z, v1.z);                               \
        _vd[(d + 3) * FST] = f2h2(v0.w, v1.w);                               \
    }                                                                        \
} while (0)

// QK mma for one 128x128 tile from Ks buffer (s), result in acc, then bias.
#define QK_TILE(s, jt) do {                                                  \
    _Pragma("unroll")                                                        \
    for (int i = 0; i < 4; ++i)                                              \
        _Pragma("unroll")                                                    \
        for (int n = 0; n < 4; ++n)                                          \
            _Pragma("unroll")                                                \
            for (int v = 0; v < 4; ++v) acc[i][n][v] = 0.f;                  \
    _Pragma("unroll")                                                        \
    for (int j4 = 0; j4 < 4; ++j4) {                                         \
        const int c1 = ((2 * j4) ^ gid) << 2, c2 = ((2 * j4 + 1) ^ gid) << 2;\
        uint32_t a[4][4], bb[4][2];                                          \
        _Pragma("unroll")                                                    \
        for (int mi = 0; mi < 4; ++mi) {                                     \
            int r0 = wy * 64 + mi * 16 + gid;                                \
            const uint32_t* p0 = Qs + r0 * 32 + tig;                         \
            a[mi][0] = p0[c1]; a[mi][1] = p0[256 + c1];                      \
            a[mi][2] = p0[c2]; a[mi][3] = p0[256 + c2];                      \
        }                                                                    \
        _Pragma("unroll")                                                    \
        for (int ni = 0; ni < 4; ++ni) {                                     \
            int c0 = wx * 32 + ni * 8 + gid;                                 \
            const uint32_t* q = Ks + (s) * 4096 + c0 * 32 + tig;             \
            bb[ni][0] = q[c1]; bb[ni][1] = q[c2];                            \
        }                                                                    \
        _Pragma("unroll")                                                    \
        for (int mi = 0; mi < 4; ++mi)                                       \
            _Pragma("unroll")                                                \
            for (int ni = 0; ni < 4; ++ni)                                   \
                mma_f16(acc[mi][ni], a[mi], bb[ni]);                         \
    }                                                                        \
    _Pragma("unroll")                                                        \
    for (int mi = 0; mi < 4; ++mi) {                                         \
        int r0 = wy * 64 + mi * 16 + gid;                                    \
        float pq0 = pq[r0], pq1 = pq[r0 + 8];                                \
        _Pragma("unroll")                                                    \
        for (int ni = 0; ni < 4; ++ni) {                                     \
            int c0f = wx * 32 + ni * 8 + tig * 2;                            \
            float k0 = pk_all[(jt) * 128 + c0f];                             \
            float k1 = pk_all[(jt) * 128 + c0f + 1];                         \
            float d00 = pq0 - k0, d01 = pq0 - k1;                            \
            float d10 = pq1 - k0, d11 = pq1 - k1;                            \
            acc[mi][ni][0] = acc[mi][ni][0] * 0.125f - rs * d00 * d00;       \
            acc[mi][ni][1] = acc[mi][ni][1] * 0.125f - rs * d01 * d01;       \
            acc[mi][ni][2] = acc[mi][ni][2] * 0.125f - rs * d10 * d10;       \
            acc[mi][ni][3] = acc[mi][ni][3] * 0.125f - rs * d11 * d11;       \
        }                                                                    \
    }                                                                        \
} while (0)

    float acc[4][4][4];

    // ===================== Pass A: stats only =====================
    LOAD_K(0, 0);
    __syncthreads();
    for (int j = 0; j < 16; ++j) {
        if (j + 1 < 16) LOAD_K(j + 1, (j + 1) & 1);
        QK_TILE(j & 1, j);

        // per-warp per-row max & sumexp over this warp's 32 cols
#pragma unroll
        for (int mi = 0; mi < 4; ++mi) {
            float mx0 = NEG_INF, mx1 = NEG_INF;
#pragma unroll
            for (int ni = 0; ni < 4; ++ni) {
                mx0 = fmaxf(mx0, fmaxf(acc[mi][ni][0], acc[mi][ni][1]));
                mx1 = fmaxf(mx1, fmaxf(acc[mi][ni][2], acc[mi][ni][3]));
            }
            mx0 = fmaxf(mx0, __shfl_xor_sync(0xffffffff, mx0, 1));
            mx0 = fmaxf(mx0, __shfl_xor_sync(0xffffffff, mx0, 2));
            mx1 = fmaxf(mx1, __shfl_xor_sync(0xffffffff, mx1, 1));
            mx1 = fmaxf(mx1, __shfl_xor_sync(0xffffffff, mx1, 2));
            float s0 = 0.f, s1 = 0.f;
#pragma unroll
            for (int ni = 0; ni < 4; ++ni) {
                s0 += __expf(acc[mi][ni][0] - mx0) + __expf(acc[mi][ni][1] - mx0);
                s1 += __expf(acc[mi][ni][2] - mx1) + __expf(acc[mi][ni][3] - mx1);
            }
            s0 += __shfl_xor_sync(0xffffffff, s0, 1);
            s0 += __shfl_xor_sync(0xffffffff, s0, 2);
            s1 += __shfl_xor_sync(0xffffffff, s1, 1);
            s1 += __shfl_xor_sync(0xffffffff, s1, 2);
            if (tig == 0) {
                int r0 = wy * 64 + mi * 16 + gid;
                redm[wx * 128 + r0]     = mx0;
                reds[wx * 128 + r0]     = s0;
                redm[wx * 128 + r0 + 8] = mx1;
                reds[wx * 128 + r0 + 8] = s1;
            }
        }
        __syncthreads();
        if (tid < 128) {
            float m0 = redm[tid],       m1 = redm[128 + tid];
            float m2 = redm[256 + tid], m3 = redm[384 + tid];
            float mj = fmaxf(fmaxf(m0, m1), fmaxf(m2, m3));
            float sj = reds[tid]       * __expf(m0 - mj)
                     + reds[128 + tid] * __expf(m1 - mj)
                     + reds[256 + tid] * __expf(m2 - mj)
                     + reds[384 + tid] * __expf(m3 - mj);
            m_all[j * 128 + tid] = mj;
            s_all[j * 128 + tid] = sj;
        }
        __syncthreads();
    }

    // global row stats
    if (tid < 128) {
        float M = NEG_INF;
#pragma unroll
        for (int j = 0; j < 16; ++j) M = fmaxf(M, m_all[j * 128 + tid]);
        float S = 0.f;
#pragma unroll
        for (int j = 0; j < 16; ++j)
            S += s_all[j * 128 + tid] * __expf(m_all[j * 128 + tid] - M);
        Mrow[tid] = M;
        Irow[tid] = 1.0f / S;
    }
    __syncthreads();

    // ===================== Pass B: attn write + AV =====================
    float oacc[2][4][4];
#pragma unroll
    for (int i = 0; i < 2; ++i)
#pragma unroll
        for (int j = 0; j < 4; ++j)
#pragma unroll
            for (int v = 0; v < 4; ++v) oacc[i][j][v] = 0.f;

    LOAD_K(0, 0);
    LOAD_V(0, 0);
    __syncthreads();
    for (int j = 0; j < 16; ++j) {
        if (j + 1 < 16) {
            LOAD_K(j + 1, (j + 1) & 1);
            LOAD_V(j + 1, (j + 1) & 1);
        }
        QK_TILE(j & 1, j);

        // p = exp(s - M) * invS; write fp32 attn; stage fp16 p
#pragma unroll
        for (int mi = 0; mi < 4; ++mi) {
            int r0 = wy * 64 + mi * 16 + gid;
            float M0 = Mrow[r0], I0 = Irow[r0];
            float M1 = Mrow[r0 + 8], I1 = Irow[r0 + 8];
            float* arow = attn + ((size_t)(bh * L_SZ + tm + r0)) * L_SZ + j * 128;
#pragma unroll
            for (int ni = 0; ni < 4; ++ni) {
                int c0f = wx * 32 + ni * 8 + tig * 2;
                float p00 = __expf(acc[mi][ni][0] - M0) * I0;
                float p01 = __expf(acc[mi][ni][1] - M0) * I0;
                float p10 = __expf(acc[mi][ni][2] - M1) * I1;
                float p11 = __expf(acc[mi][ni][3] - M1) * I1;
                *(float2*)(arow + c0f)              = make_float2(p00, p01);
                *(float2*)(arow + 8 * L_SZ + c0f)   = make_float2(p10, p11);
                int wc = wx * 16 + ni * 4 + tig;
                Ps[r0 * FST + wc]       = f2h2(p00, p01);
                Ps[(r0 + 8) * FST + wc] = f2h2(p10, p11);
            }
        }
        __syncthreads();

        // AV mma: O += P(128x128) @ V(128x64)
        const uint32_t* vsb = Vs + (j & 1) * 4352;
#pragma unroll
        for (int ks = 0; ks < 8; ++ks) {
            const int kw = ks * 8;
            uint32_t a[2][4], bb[4][2];
#pragma unroll
            for (int mi2 = 0; mi2 < 2; ++mi2) {
                int r = wyB * 32 + mi2 * 16 + gid;
                a[mi2][0] = Ps[r * FST + kw + tig];
                a[mi2][1] = Ps[(r + 8) * FST + kw + tig];
                a[mi2][2] = Ps[r * FST + kw + 4 + tig];
                a[mi2][3] = Ps[(r + 8) * FST + kw + 4 + tig];
            }
#pragma unroll
            for (int ni2 = 0; ni2 < 4; ++ni2) {
                int n = wxB * 32 + ni2 * 8 + gid;
                bb[ni2][0] = vsb[n * FST + kw + tig];
                bb[ni2][1] = vsb[n * FST + kw + 4 + tig];
            }
#pragma unroll
            for (int mi2 = 0; mi2 < 2; ++mi2)
#pragma unroll
                for (int ni2 = 0; ni2 < 4; ++ni2)
                    mma_f16(oacc[mi2][ni2], a[mi2], bb[ni2]);
        }
        __syncthreads();
    }

    // O epilogue
#pragma unroll
    for (int mi2 = 0; mi2 < 2; ++mi2) {
        int row = tm + wyB * 32 + mi2 * 16 + gid;
#pragma unroll
        for (int ni2 = 0; ni2 < 4; ++ni2) {
            int col = h * 64 + wxB * 32 + ni2 * 8 + tig * 2;
            float2 o0 = {oacc[mi2][ni2][0], oacc[mi2][ni2][1]};
            float2 o1 = {oacc[mi2][ni2][2], oacc[mi2][ni2][3]};
            *(float2*)(g_o + (size_t)(b * L_SZ + row) * D_SZ + col)     = o0;
            *(float2*)(g_o + (size_t)(b * L_SZ + row + 8) * D_SZ + col) = o1;
        }
    }
}

// ---------------------------------------------------------------------------
// phase_val[bh, l] = tanh(ps * (x[b,l,:] . phase_w[h,:] + phase_b[h]))
// ---------------------------------------------------------------------------
__global__ __launch_bounds__(512) void phase_kernel(
    const float* __restrict__ x, const float* __restrict__ pw,
    const float* __restrict__ pb, const float* __restrict__ ps_ptr)
{
    const int bl = blockIdx.x;
    const int b  = bl >> 11;
    const int l  = bl & 2047;
    __shared__ float xs[1024];
    const int tid = threadIdx.x;
    for (int i = tid; i < 1024; i += 512) xs[i] = x[(size_t)bl * 1024 + i];
    __syncthreads();
    const int h = tid >> 5, lane = tid & 31;
    float s = 0.f;
    const float* w = pw + (size_t)h * 1024;
    for (int d = lane; d < 1024; d += 32) s += xs[d] * w[d];
#pragma unroll
    for (int o = 16; o; o >>= 1) s += __shfl_xor_sync(0xffffffff, s, o);
    if (lane == 0) {
        float ps = *ps_ptr;
        g_phase[(size_t)(b * H_SZ + h) * L_SZ + l] = tanhf(ps * (s + pb[h]));
    }
}

// ---------------------------------------------------------------------------
extern "C" void kernel_launch(void* const* d_in, const int* in_sizes, int n_in,
                              void* d_out, int out_size)
{
    const float* x      = (const float*)d_in[0];
    const float* qkv_w  = (const float*)d_in[1];
    const float* qkv_b  = (const float*)d_in[2];
    const float* out_w  = (const float*)d_in[3];
    const float* out_b  = (const float*)d_in[4];
    const float* ph_w   = (const float*)d_in[5];
    const float* ph_b   = (const float*)d_in[6];
    const float* rs_ptr = (const float*)d_in[7];
    const float* ps_ptr = (const float*)d_in[8];

    float* out_proj = (float*)d_out;                       // [2,2048,1024]
    float* attn     = out_proj + (size_t)MTOK * D_SZ;      // [2,16,2048,2048]

    float *qkv_ptr, *o_ptr;
    cudaGetSymbolAddress((void**)&qkv_ptr, g_qkv);
    cudaGetSymbolAddress((void**)&o_ptr,  g_o);

    const int SMEM_GEMM  = 2 * 12288 * 4;    // 98304
    const int SMEM_ATTN  = 37248 * 4;        // 148992

    cudaFuncSetAttribute(gemm_mma,   cudaFuncAttributeMaxDynamicSharedMemorySize, SMEM_GEMM);
    cudaFuncSetAttribute(attn_fused, cudaFuncAttributeMaxDynamicSharedMemorySize, SMEM_ATTN);

    // 1) fused QKV projection (fp16 mma)
    gemm_mma<<<dim3(E3_SZ / 256, MTOK / 128), 256, SMEM_GEMM>>>(
        x, qkv_w, qkv_b, qkv_ptr, E3_SZ, D_SZ);

    // 2) per-head phase values
    phase_kernel<<<MTOK, 512>>>(x, ph_w, ph_b, ps_ptr);

    // 3) fused scores + softmax + attn write + AV
    attn_fused<<<dim3(L_SZ / 128, BH_SZ), 256, SMEM_ATTN>>>(rs_ptr, attn);

    // 4) output projection (fp16 mma)
    gemm_mma<<<dim3(D_SZ / 256, MTOK / 128), 256, SMEM_GEMM>>>(
        o_ptr, out_w, out_b, out_proj, D_SZ, D_SZ);
}

// round 9
// speedup vs baseline: 2.5780x; 1.0102x over previous
#include <cuda_runtime.h>
#include <cuda_fp16.h>
#include <math.h>
#include <stdint.h>

// Problem constants
#define B_SZ   2
#define L_SZ   2048
#define D_SZ   1024
#define H_SZ   16
#define E3_SZ  3072
#define MTOK   (B_SZ * L_SZ)        // 4096
#define BH_SZ  32

#define NEG_INF __int_as_float(0xff800000)

// Scratch (device globals; allocation is forbidden)
__device__ float  g_qkv[(size_t)MTOK * E3_SZ];        // [4096, 3072]
__device__ float  g_phase[(size_t)BH_SZ * L_SZ];      // [bh, l]
__device__ float  g_o[(size_t)MTOK * D_SZ];           // [4096, 1024]

// ---------------------------------------------------------------------------
// fp16 mma.sync helpers (arch-portable, sm_80+); fp32 accumulate.
// ---------------------------------------------------------------------------
__device__ __forceinline__ uint32_t f2h2(float lo, float hi) {
    __half2 h = __floats2half2_rn(lo, hi);
    return *reinterpret_cast<uint32_t*>(&h);
}
__device__ __forceinline__ void mma_f16(float c[4], const uint32_t a[4],
                                        const uint32_t b[2]) {
    asm volatile(
        "mma.sync.aligned.m16n8k16.row.col.f32.f16.f16.f32 "
        "{%0,%1,%2,%3}, {%4,%5,%6,%7}, {%8,%9}, {%0,%1,%2,%3};"
        : "+f"(c[0]), "+f"(c[1]), "+f"(c[2]), "+f"(c[3])
        : "r"(a[0]), "r"(a[1]), "r"(a[2]), "r"(a[3]), "r"(b[0]), "r"(b[1]));
}

// ===========================================================================
// GEMM: C[M,N] = A[M,K] @ B[N,K]^T + bias[N]    (fp16 mma, fp32 acc)
// CTA 128x256, 8 warps (2x4), warp tile 64x64, k-chunk 64, double-buffered.
// ===========================================================================
__global__ void __launch_bounds__(256) gemm_mma(
    const float* __restrict__ A, const float* __restrict__ Bm,
    const float* __restrict__ bias, float* __restrict__ C, int N, int K)
{
    extern __shared__ uint32_t sm[];
    const int tid = threadIdx.x, wid = tid >> 5, lane = tid & 31;
    const int gid = lane >> 2, tig = lane & 3;
    const int wy = wid >> 2, wx = wid & 3;
    const int tm = blockIdx.y * 128, tn = blockIdx.x * 256;

    const int ar = tid >> 1, ah = tid & 1;
    const float* ag = A  + (size_t)(tm + ar)  * K + ah * 32;
    const float* bg = Bm + (size_t)(tn + tid) * K;

    float acc[4][8][4];
#pragma unroll
    for (int i = 0; i < 4; ++i)
#pragma unroll
        for (int j = 0; j < 8; ++j)
#pragma unroll
            for (int v = 0; v < 4; ++v) acc[i][j][v] = 0.f;

    const int T = K >> 6;

#define G_LOAD(t, s) do {                                                    \
    const float* _ap = ag + (t) * 64;                                        \
    const float* _bp = bg + (t) * 64;                                        \
    uint32_t* _ad = sm + (s) * 12288 + ar * 32;                              \
    uint32_t* _bd = sm + (s) * 12288 + 4096 + tid * 32;                      \
    _Pragma("unroll")                                                        \
    for (int j = 0; j < 4; ++j) {                                            \
        float4 v0 = *(const float4*)(_ap + j * 8);                           \
        float4 v1 = *(const float4*)(_ap + j * 8 + 4);                       \
        int g = ah * 4 + j;                                                  \
        uint4 w = {f2h2(v0.x, v0.y), f2h2(v0.z, v0.w),                       \
                   f2h2(v1.x, v1.y), f2h2(v1.z, v1.w)};                      \
        *(uint4*)(_ad + ((g ^ (ar & 7)) << 2)) = w;                          \
    }                                                                        \
    _Pragma("unroll")                                                        \
    for (int j = 0; j < 8; ++j) {                                            \
        float4 v0 = *(const float4*)(_bp + j * 8);                           \
        float4 v1 = *(const float4*)(_bp + j * 8 + 4);                       \
        uint4 w = {f2h2(v0.x, v0.y), f2h2(v0.z, v0.w),                       \
                   f2h2(v1.x, v1.y), f2h2(v1.z, v1.w)};                      \
        *(uint4*)(_bd + ((j ^ (tid & 7)) << 2)) = w;                         \
    }                                                                        \
} while (0)

    G_LOAD(0, 0);
    __syncthreads();

    for (int t = 0; t < T; ++t) {
        if (t + 1 < T) G_LOAD(t + 1, (t + 1) & 1);
        const uint32_t* as = sm + (t & 1) * 12288;
        const uint32_t* bs = as + 4096;
#pragma unroll
        for (int j = 0; j < 4; ++j) {
            const int c1 = ((2 * j) ^ gid) << 2, c2 = ((2 * j + 1) ^ gid) << 2;
            uint32_t a[4][4], b[8][2];
#pragma unroll
            for (int mi = 0; mi < 4; ++mi) {
                int r0 = wy * 64 + mi * 16 + gid;
                const uint32_t* p0 = as + r0 * 32 + tig;
                a[mi][0] = p0[c1];
                a[mi][1] = p0[256 + c1];
                a[mi][2] = p0[c2];
                a[mi][3] = p0[256 + c2];
            }
#pragma unroll
            for (int ni = 0; ni < 8; ++ni) {
                int c0 = wx * 64 + ni * 8 + gid;
                const uint32_t* q = bs + c0 * 32 + tig;
                b[ni][0] = q[c1];
                b[ni][1] = q[c2];
            }
#pragma unroll
            for (int mi = 0; mi < 4; ++mi)
#pragma unroll
                for (int ni = 0; ni < 8; ++ni)
                    mma_f16(acc[mi][ni], a[mi], b[ni]);
        }
        __syncthreads();
    }

#pragma unroll
    for (int mi = 0; mi < 4; ++mi) {
        int row = tm + wy * 64 + mi * 16 + gid;
#pragma unroll
        for (int ni = 0; ni < 8; ++ni) {
            int col = tn + wx * 64 + ni * 8 + tig * 2;
            float b0 = bias[col], b1 = bias[col + 1];
            float2 o0 = {acc[mi][ni][0] + b0, acc[mi][ni][1] + b1};
            float2 o1 = {acc[mi][ni][2] + b0, acc[mi][ni][3] + b1};
            *(float2*)(C + (size_t)row * N + col)       = o0;
            *(float2*)(C + (size_t)(row + 8) * N + col) = o1;
        }
    }
}

// ===========================================================================
// Fused attention v2: scores + softmax + attn write + AV, register P reuse.
// CTA = (q-tile of 128 rows, bh), 256 threads = 8 warps, 4x2 warp layout:
//   wy = wid>>1 (rows wy*32..+32), wx = wid&1 (score cols wx*64..+64).
// Pass A: QK^T mma + bias -> per-(tile,wx,row) max/sumexp slots; fold once.
// Pass B: recompute s, p = exp(s-M)*invS in regs, write fp32 attn from regs,
//         pack p to half2 A-fragments IN REGISTERS, AV mma over warp k-slice,
//         O partials summed across wx at the end.
// SMEM (words): Qs@0(4096) Ks@4096(2x4096) Vs@12288(2x4352) pk@20992(2048)
//   pq@23040(128) m_all@23168(4096) s_all@27264(4096) Mrow@31360 Irow@31488
//   total 31616 w = 126464 B. O-reduce reuses Ks region at the end.
// ===========================================================================
#define FST 68
__global__ void __launch_bounds__(256) attn_fused(
    const float* __restrict__ rs_ptr, float* __restrict__ attn)
{
    extern __shared__ uint32_t sm[];
    uint32_t* Qs = sm;
    uint32_t* Ks = sm + 4096;
    uint32_t* Vs = sm + 12288;
    float* pk_all = (float*)(sm + 20992);
    float* pq     = (float*)(sm + 23040);
    float* m_all  = (float*)(sm + 23168);
    float* s_all  = (float*)(sm + 27264);
    float* Mrow   = (float*)(sm + 31360);
    float* Irow   = (float*)(sm + 31488);

    const int tid = threadIdx.x, wid = tid >> 5, lane = tid & 31;
    const int gid = lane >> 2, tig = lane & 3;
    const int wy = wid >> 1, wx = wid & 1;
    const int bh = blockIdx.y, b = bh >> 4, h = bh & 15;
    const int tm = blockIdx.x * 128;
    const float rs = *rs_ptr;

    const int ar = tid >> 1, ah = tid & 1;

    // Q tile (persistent) + phase values
    {
        const float* qg = g_qkv + (size_t)(b * L_SZ + tm + ar) * E3_SZ + h * 64 + ah * 32;
#pragma unroll
        for (int j = 0; j < 4; ++j) {
            float4 v0 = *(const float4*)(qg + j * 8);
            float4 v1 = *(const float4*)(qg + j * 8 + 4);
            int g = ah * 4 + j;
            uint4 w = {f2h2(v0.x, v0.y), f2h2(v0.z, v0.w),
                       f2h2(v1.x, v1.y), f2h2(v1.z, v1.w)};
            *(uint4*)(Qs + ar * 32 + ((g ^ (ar & 7)) << 2)) = w;
        }
    }
    if (tid < 128) pq[tid] = g_phase[(size_t)bh * L_SZ + tm + tid];
#pragma unroll
    for (int i = 0; i < 8; ++i)
        pk_all[tid + i * 256] = g_phase[(size_t)bh * L_SZ + tid + i * 256];

#define LOAD_K(j, s) do {                                                    \
    const float* _kg = g_qkv + (size_t)(b * L_SZ + (j) * 128 + ar) * E3_SZ   \
                       + D_SZ + h * 64 + ah * 32;                            \
    uint32_t* _kd = Ks + (s) * 4096 + ar * 32;                               \
    _Pragma("unroll")                                                        \
    for (int jj = 0; jj < 4; ++jj) {                                         \
        float4 v0 = *(const float4*)(_kg + jj * 8);                          \
        float4 v1 = *(const float4*)(_kg + jj * 8 + 4);                      \
        int g = ah * 4 + jj;                                                 \
        uint4 w = {f2h2(v0.x, v0.y), f2h2(v0.z, v0.w),                       \
                   f2h2(v1.x, v1.y), f2h2(v1.z, v1.w)};                      \
        *(uint4*)(_kd + ((g ^ (ar & 7)) << 2)) = w;                          \
    }                                                                        \
} while (0)

#define LOAD_V(j, s) do {                                                    \
    int _kp = tid & 63, _dg = tid >> 6;                                      \
    const float* _vp = g_qkv + (size_t)(b * L_SZ + (j) * 128 + 2 * _kp)      \
                       * E3_SZ + 2 * D_SZ + h * 64 + _dg * 16;               \
    uint32_t* _vd = Vs + (s) * 4352 + _kp;                                   \
    _Pragma("unroll")                                                        \
    for (int it = 0; it < 4; ++it) {                                         \
        float4 v0 = *(const float4*)(_vp + it * 4);                          \
        float4 v1 = *(const float4*)(_vp + E3_SZ + it * 4);                  \
        int d = _dg * 16 + it * 4;                                           \
        _vd[(d + 0) * FST] = f2h2(v0.x, v1.x);                               \
        _vd[(d + 1) * FST] = f2h2(v0.y, v1.y);                               \
        _vd[(d + 2) * FST] = f2h2(v0.z, v1.z);                               \
        _vd[(d + 3) * FST] = f2h2(v0.w, v1.w);                               \
    }                                                                        \
} while (0)

// QK mma for this warp's 32x64 sub-tile + phase bias. acc[2][8][4].
#define QK_TILE(s, jt) do {                                                  \
    _Pragma("unroll")                                                        \
    for (int i = 0; i < 2; ++i)                                              \
        _Pragma("unroll")                                                    \
        for (int n = 0; n < 8; ++n)                                          \
            _Pragma("unroll")                                                \
            for (int v = 0; v < 4; ++v) acc[i][n][v] = 0.f;                  \
    _Pragma("unroll")                                                        \
    for (int j4 = 0; j4 < 4; ++j4) {                                         \
        const int c1 = ((2 * j4) ^ gid) << 2, c2 = ((2 * j4 + 1) ^ gid) << 2;\
        uint32_t a[2][4], bb[8][2];                                          \
        _Pragma("unroll")                                                    \
        for (int mi = 0; mi < 2; ++mi) {                                     \
            int r0 = wy * 32 + mi * 16 + gid;                                \
            const uint32_t* p0 = Qs + r0 * 32 + tig;                         \
            a[mi][0] = p0[c1]; a[mi][1] = p0[256 + c1];                      \
            a[mi][2] = p0[c2]; a[mi][3] = p0[256 + c2];                      \
        }                                                                    \
        _Pragma("unroll")                                                    \
        for (int ni = 0; ni < 8; ++ni) {                                     \
            int c0 = wx * 64 + ni * 8 + gid;                                 \
            const uint32_t* q = Ks + (s) * 4096 + c0 * 32 + tig;             \
            bb[ni][0] = q[c1]; bb[ni][1] = q[c2];                            \
        }                                                                    \
        _Pragma("unroll")                                                    \
        for (int mi = 0; mi < 2; ++mi)                                       \
            _Pragma("unroll")                                                \
            for (int ni = 0; ni < 8; ++ni)                                   \
                mma_f16(acc[mi][ni], a[mi], bb[ni]);                         \
    }                                                                        \
    _Pragma("unroll")                                                        \
    for (int mi = 0; mi < 2; ++mi) {                                         \
        int r0 = wy * 32 + mi * 16 + gid;                                    \
        float pq0 = pq[r0], pq1 = pq[r0 + 8];                                \
        _Pragma("unroll")                                                    \
        for (int ni = 0; ni < 8; ++ni) {                                     \
            int c0f = wx * 64 + ni * 8 + tig * 2;                            \
            float k0 = pk_all[(jt) * 128 + c0f];                             \
            float k1 = pk_all[(jt) * 128 + c0f + 1];                         \
            float d00 = pq0 - k0, d01 = pq0 - k1;                            \
            float d10 = pq1 - k0, d11 = pq1 - k1;                            \
            acc[mi][ni][0] = acc[mi][ni][0] * 0.125f - rs * d00 * d00;       \
            acc[mi][ni][1] = acc[mi][ni][1] * 0.125f - rs * d01 * d01;       \
            acc[mi][ni][2] = acc[mi][ni][2] * 0.125f - rs * d10 * d10;       \
            acc[mi][ni][3] = acc[mi][ni][3] * 0.125f - rs * d11 * d11;       \
        }                                                                    \
    }                                                                        \
} while (0)

    float acc[2][8][4];

    // ===================== Pass A: stats only =====================
    LOAD_K(0, 0);
    __syncthreads();
    for (int j = 0; j < 16; ++j) {
        if (j + 1 < 16) LOAD_K(j + 1, (j + 1) & 1);
        QK_TILE(j & 1, j);
#pragma unroll
        for (int mi = 0; mi < 2; ++mi) {
            float mx0 = NEG_INF, mx1 = NEG_INF;
#pragma unroll
            for (int ni = 0; ni < 8; ++ni) {
                mx0 = fmaxf(mx0, fmaxf(acc[mi][ni][0], acc[mi][ni][1]));
                mx1 = fmaxf(mx1, fmaxf(acc[mi][ni][2], acc[mi][ni][3]));
            }
            mx0 = fmaxf(mx0, __shfl_xor_sync(0xffffffff, mx0, 1));
            mx0 = fmaxf(mx0, __shfl_xor_sync(0xffffffff, mx0, 2));
            mx1 = fmaxf(mx1, __shfl_xor_sync(0xffffffff, mx1, 1));
            mx1 = fmaxf(mx1, __shfl_xor_sync(0xffffffff, mx1, 2));
            float s0 = 0.f, s1 = 0.f;
#pragma unroll
            for (int ni = 0; ni < 8; ++ni) {
                s0 += __expf(acc[mi][ni][0] - mx0) + __expf(acc[mi][ni][1] - mx0);
                s1 += __expf(acc[mi][ni][2] - mx1) + __expf(acc[mi][ni][3] - mx1);
            }
            s0 += __shfl_xor_sync(0xffffffff, s0, 1);
            s0 += __shfl_xor_sync(0xffffffff, s0, 2);
            s1 += __shfl_xor_sync(0xffffffff, s1, 1);
            s1 += __shfl_xor_sync(0xffffffff, s1, 2);
            if (tig == 0) {
                int r0 = wy * 32 + mi * 16 + gid;
                int slot = (j * 2 + wx) * 128;
                m_all[slot + r0]     = mx0;
                s_all[slot + r0]     = s0;
                m_all[slot + r0 + 8] = mx1;
                s_all[slot + r0 + 8] = s1;
            }
        }
        __syncthreads();
    }

    // fold 32 slots -> per-row M, 1/S
    if (tid < 128) {
        float M = NEG_INF;
#pragma unroll
        for (int s = 0; s < 32; ++s) M = fmaxf(M, m_all[s * 128 + tid]);
        float S = 0.f;
#pragma unroll
        for (int s = 0; s < 32; ++s)
            S += s_all[s * 128 + tid] * __expf(m_all[s * 128 + tid] - M);
        Mrow[tid] = M;
        Irow[tid] = 1.0f / S;
    }
    __syncthreads();

    // ===================== Pass B: attn write + AV =====================
    float oacc[2][8][4];
#pragma unroll
    for (int i = 0; i < 2; ++i)
#pragma unroll
        for (int j = 0; j < 8; ++j)
#pragma unroll
            for (int v = 0; v < 4; ++v) oacc[i][j][v] = 0.f;

    // hoist per-row softmax stats (rows wy*32+gid, +8, +16, +24)
    float Mh[2][2], Ih[2][2];
#pragma unroll
    for (int mi = 0; mi < 2; ++mi) {
        int r0 = wy * 32 + mi * 16 + gid;
        Mh[mi][0] = Mrow[r0];     Ih[mi][0] = Irow[r0];
        Mh[mi][1] = Mrow[r0 + 8]; Ih[mi][1] = Irow[r0 + 8];
    }

    LOAD_K(0, 0);
    LOAD_V(0, 0);
    __syncthreads();
    for (int j = 0; j < 16; ++j) {
        if (j + 1 < 16) {
            LOAD_K(j + 1, (j + 1) & 1);
            LOAD_V(j + 1, (j + 1) & 1);
        }
        QK_TILE(j & 1, j);

        // p = exp(s - M) * invS in registers; write fp32 attn
#pragma unroll
        for (int mi = 0; mi < 2; ++mi) {
            int r0 = wy * 32 + mi * 16 + gid;
            float M0 = Mh[mi][0], I0 = Ih[mi][0];
            float M1 = Mh[mi][1], I1 = Ih[mi][1];
            float* arow = attn + ((size_t)(bh * L_SZ + tm + r0)) * L_SZ + j * 128;
#pragma unroll
            for (int ni = 0; ni < 8; ++ni) {
                int c0f = wx * 64 + ni * 8 + tig * 2;
                float p00 = __expf(acc[mi][ni][0] - M0) * I0;
                float p01 = __expf(acc[mi][ni][1] - M0) * I0;
                float p10 = __expf(acc[mi][ni][2] - M1) * I1;
                float p11 = __expf(acc[mi][ni][3] - M1) * I1;
                acc[mi][ni][0] = p00; acc[mi][ni][1] = p01;
                acc[mi][ni][2] = p10; acc[mi][ni][3] = p11;
                *(float2*)(arow + c0f)            = make_float2(p00, p01);
                *(float2*)(arow + 8 * L_SZ + c0f) = make_float2(p10, p11);
            }
        }

        // AV mma: A-fragments straight from registers (flash-v2 reuse).
        // warp k-slice = its 64 score cols; 4 k16 steps (ni pairs).
        const uint32_t* vsb = Vs + (j & 1) * 4352;
#pragma unroll
        for (int ss = 0; ss < 4; ++ss) {
            const int kw = wx * 32 + ss * 8;
            uint32_t a[2][4], bb[8][2];
#pragma unroll
            for (int mi = 0; mi < 2; ++mi) {
                a[mi][0] = f2h2(acc[mi][2 * ss][0],     acc[mi][2 * ss][1]);
                a[mi][1] = f2h2(acc[mi][2 * ss][2],     acc[mi][2 * ss][3]);
                a[mi][2] = f2h2(acc[mi][2 * ss + 1][0], acc[mi][2 * ss + 1][1]);
                a[mi][3] = f2h2(acc[mi][2 * ss + 1][2], acc[mi][2 * ss + 1][3]);
            }
#pragma unroll
            for (int ni2 = 0; ni2 < 8; ++ni2) {
                int d = ni2 * 8 + gid;
                bb[ni2][0] = vsb[d * FST + kw + tig];
                bb[ni2][1] = vsb[d * FST + kw + 4 + tig];
            }
#pragma unroll
            for (int mi = 0; mi < 2; ++mi)
#pragma unroll
                for (int ni2 = 0; ni2 < 8; ++ni2)
                    mma_f16(oacc[mi][ni2], a[mi], bb[ni2]);
        }
        __syncthreads();
    }

    // O reduction across wx pairs (reuse Ks region), then epilogue
    float* Ored = (float*)(sm + 4096);   // stride 65 floats per row
    if (wx == 1) {
#pragma unroll
        for (int mi = 0; mi < 2; ++mi) {
            int rl = wy * 32 + mi * 16 + gid;
#pragma unroll
            for (int ni2 = 0; ni2 < 8; ++ni2) {
                int col = ni2 * 8 + tig * 2;
                Ored[rl * 65 + col]           = oacc[mi][ni2][0];
                Ored[rl * 65 + col + 1]       = oacc[mi][ni2][1];
                Ored[(rl + 8) * 65 + col]     = oacc[mi][ni2][2];
                Ored[(rl + 8) * 65 + col + 1] = oacc[mi][ni2][3];
            }
        }
    }
    __syncthreads();
    if (wx == 0) {
#pragma unroll
        for (int mi = 0; mi < 2; ++mi) {
            int rl = wy * 32 + mi * 16 + gid;
            int row = tm + rl;
#pragma unroll
            for (int ni2 = 0; ni2 < 8; ++ni2) {
                int col = ni2 * 8 + tig * 2;
                float2 o0 = {oacc[mi][ni2][0] + Ored[rl * 65 + col],
                             oacc[mi][ni2][1] + Ored[rl * 65 + col + 1]};
                float2 o1 = {oacc[mi][ni2][2] + Ored[(rl + 8) * 65 + col],
                             oacc[mi][ni2][3] + Ored[(rl + 8) * 65 + col + 1]};
                *(float2*)(g_o + (size_t)(b * L_SZ + row) * D_SZ + h * 64 + col)     = o0;
                *(float2*)(g_o + (size_t)(b * L_SZ + row + 8) * D_SZ + h * 64 + col) = o1;
            }
        }
    }
}

// ---------------------------------------------------------------------------
// phase_val[bh, l] = tanh(ps * (x[b,l,:] . phase_w[h,:] + phase_b[h]))
// ---------------------------------------------------------------------------
__global__ __launch_bounds__(512) void phase_kernel(
    const float* __restrict__ x, const float* __restrict__ pw,
    const float* __restrict__ pb, const float* __restrict__ ps_ptr)
{
    const int bl = blockIdx.x;
    const int b  = bl >> 11;
    const int l  = bl & 2047;
    __shared__ float xs[1024];
    const int tid = threadIdx.x;
    for (int i = tid; i < 1024; i += 512) xs[i] = x[(size_t)bl * 1024 + i];
    __syncthreads();
    const int h = tid >> 5, lane = tid & 31;
    float s = 0.f;
    const float* w = pw + (size_t)h * 1024;
    for (int d = lane; d < 1024; d += 32) s += xs[d] * w[d];
#pragma unroll
    for (int o = 16; o; o >>= 1) s += __shfl_xor_sync(0xffffffff, s, o);
    if (lane == 0) {
        float ps = *ps_ptr;
        g_phase[(size_t)(b * H_SZ + h) * L_SZ + l] = tanhf(ps * (s + pb[h]));
    }
}

// ---------------------------------------------------------------------------
extern "C" void kernel_launch(void* const* d_in, const int* in_sizes, int n_in,
                              void* d_out, int out_size)
{
    const float* x      = (const float*)d_in[0];
    const float* qkv_w  = (const float*)d_in[1];
    const float* qkv_b  = (const float*)d_in[2];
    const float* out_w  = (const float*)d_in[3];
    const float* out_b  = (const float*)d_in[4];
    const float* ph_w   = (const float*)d_in[5];
    const float* ph_b   = (const float*)d_in[6];
    const float* rs_ptr = (const float*)d_in[7];
    const float* ps_ptr = (const float*)d_in[8];

    float* out_proj = (float*)d_out;                       // [2,2048,1024]
    float* attn     = out_proj + (size_t)MTOK * D_SZ;      // [2,16,2048,2048]

    float *qkv_ptr, *o_ptr;
    cudaGetSymbolAddress((void**)&qkv_ptr, g_qkv);
    cudaGetSymbolAddress((void**)&o_ptr,  g_o);

    const int SMEM_GEMM  = 2 * 12288 * 4;    // 98304
    const int SMEM_ATTN  = 31616 * 4;        // 126464

    cudaFuncSetAttribute(gemm_mma,   cudaFuncAttributeMaxDynamicSharedMemorySize, SMEM_GEMM);
    cudaFuncSetAttribute(attn_fused, cudaFuncAttributeMaxDynamicSharedMemorySize, SMEM_ATTN);

    // 1) fused QKV projection (fp16 mma)
    gemm_mma<<<dim3(E3_SZ / 256, MTOK / 128), 256, SMEM_GEMM>>>(
        x, qkv_w, qkv_b, qkv_ptr, E3_SZ, D_SZ);

    // 2) per-head phase values
    phase_kernel<<<MTOK, 512>>>(x, ph_w, ph_b, ps_ptr);

    // 3) fused scores + softmax + attn write + AV (register P reuse)
    attn_fused<<<dim3(L_SZ / 128, BH_SZ), 256, SMEM_ATTN>>>(rs_ptr, attn);

    // 4) output projection (fp16 mma)
    gemm_mma<<<dim3(D_SZ / 256, MTOK / 128), 256, SMEM_GEMM>>>(
        o_ptr, out_w, out_b, out_proj, D_SZ, D_SZ);
}

// round 10
// speedup vs baseline: 3.0481x; 1.1824x over previous
#include <cuda_runtime.h>
#include <cuda_fp16.h>
#include <math.h>
#include <stdint.h>

// Problem constants
#define B_SZ   2
#define L_SZ   2048
#define D_SZ   1024
#define H_SZ   16
#define E3_SZ  3072
#define MTOK   (B_SZ * L_SZ)        // 4096
#define BH_SZ  32

#define NEG_INF __int_as_float(0xff800000)

// Scratch (device globals; allocation is forbidden)
__device__ __half g_qkvh[(size_t)MTOK * E3_SZ];       // fp16 qkv [4096, 3072]
__device__ float  g_phase[(size_t)BH_SZ * L_SZ];      // [bh, l]
__device__ float  g_o[(size_t)MTOK * D_SZ];           // [4096, 1024]

// ---------------------------------------------------------------------------
// helpers
// ---------------------------------------------------------------------------
__device__ __forceinline__ uint32_t f2h2(float lo, float hi) {
    __half2 h = __floats2half2_rn(lo, hi);
    return *reinterpret_cast<uint32_t*>(&h);
}
__device__ __forceinline__ void mma_f16(float c[4], const uint32_t a[4],
                                        const uint32_t b[2]) {
    asm volatile(
        "mma.sync.aligned.m16n8k16.row.col.f32.f16.f16.f32 "
        "{%0,%1,%2,%3}, {%4,%5,%6,%7}, {%8,%9}, {%0,%1,%2,%3};"
        : "+f"(c[0]), "+f"(c[1]), "+f"(c[2]), "+f"(c[3])
        : "r"(a[0]), "r"(a[1]), "r"(a[2]), "r"(a[3]), "r"(b[0]), "r"(b[1]));
}
__device__ __forceinline__ void cp16(uint32_t dst, const void* src) {
    asm volatile("cp.async.cg.shared.global [%0], [%1], 16;"
                 :: "r"(dst), "l"(src) : "memory");
}
#define CP_COMMIT() asm volatile("cp.async.commit_group;" ::: "memory")

// ===========================================================================
// GEMM: C[M,N] = A[M,K] @ B[N,K]^T + bias[N]    (fp16 mma, fp32 acc)
// OUTH=1 -> write __half C (packed half2); OUTH=0 -> write float C.
// CTA 128x256, 8 warps (2x4), warp tile 64x64, k-chunk 64, double-buffered.
// ===========================================================================
template<int OUTH>
__global__ void __launch_bounds__(256) gemm_mma(
    const float* __restrict__ A, const float* __restrict__ Bm,
    const float* __restrict__ bias, void* __restrict__ Cv, int N, int K)
{
    extern __shared__ uint32_t sm[];
    const int tid = threadIdx.x, wid = tid >> 5, lane = tid & 31;
    const int gid = lane >> 2, tig = lane & 3;
    const int wy = wid >> 2, wx = wid & 3;
    const int tm = blockIdx.y * 128, tn = blockIdx.x * 256;

    const int ar = tid >> 1, ah = tid & 1;
    const float* ag = A  + (size_t)(tm + ar)  * K + ah * 32;
    const float* bg = Bm + (size_t)(tn + tid) * K;

    float acc[4][8][4];
#pragma unroll
    for (int i = 0; i < 4; ++i)
#pragma unroll
        for (int j = 0; j < 8; ++j)
#pragma unroll
            for (int v = 0; v < 4; ++v) acc[i][j][v] = 0.f;

    const int T = K >> 6;

#define G_LOAD(t, s) do {                                                    \
    const float* _ap = ag + (t) * 64;                                        \
    const float* _bp = bg + (t) * 64;                                        \
    uint32_t* _ad = sm + (s) * 12288 + ar * 32;                              \
    uint32_t* _bd = sm + (s) * 12288 + 4096 + tid * 32;                      \
    _Pragma("unroll")                                                        \
    for (int j = 0; j < 4; ++j) {                                            \
        float4 v0 = *(const float4*)(_ap + j * 8);                           \
        float4 v1 = *(const float4*)(_ap + j * 8 + 4);                       \
        int g = ah * 4 + j;                                                  \
        uint4 w = {f2h2(v0.x, v0.y), f2h2(v0.z, v0.w),                       \
                   f2h2(v1.x, v1.y), f2h2(v1.z, v1.w)};                      \
        *(uint4*)(_ad + ((g ^ (ar & 7)) << 2)) = w;                          \
    }                                                                        \
    _Pragma("unroll")                                                        \
    for (int j = 0; j < 8; ++j) {                                            \
        float4 v0 = *(const float4*)(_bp + j * 8);                           \
        float4 v1 = *(const float4*)(_bp + j * 8 + 4);                       \
        uint4 w = {f2h2(v0.x, v0.y), f2h2(v0.z, v0.w),                       \
                   f2h2(v1.x, v1.y), f2h2(v1.z, v1.w)};                      \
        *(uint4*)(_bd + ((j ^ (tid & 7)) << 2)) = w;                         \
    }                                                                        \
} while (0)

    G_LOAD(0, 0);
    __syncthreads();

    for (int t = 0; t < T; ++t) {
        if (t + 1 < T) G_LOAD(t + 1, (t + 1) & 1);
        const uint32_t* as = sm + (t & 1) * 12288;
        const uint32_t* bs = as + 4096;
#pragma unroll
        for (int j = 0; j < 4; ++j) {
            const int c1 = ((2 * j) ^ gid) << 2, c2 = ((2 * j + 1) ^ gid) << 2;
            uint32_t a[4][4], b[8][2];
#pragma unroll
            for (int mi = 0; mi < 4; ++mi) {
                int r0 = wy * 64 + mi * 16 + gid;
                const uint32_t* p0 = as + r0 * 32 + tig;
                a[mi][0] = p0[c1];
                a[mi][1] = p0[256 + c1];
                a[mi][2] = p0[c2];
                a[mi][3] = p0[256 + c2];
            }
#pragma unroll
            for (int ni = 0; ni < 8; ++ni) {
                int c0 = wx * 64 + ni * 8 + gid;
                const uint32_t* q = bs + c0 * 32 + tig;
                b[ni][0] = q[c1];
                b[ni][1] = q[c2];
            }
#pragma unroll
            for (int mi = 0; mi < 4; ++mi)
#pragma unroll
                for (int ni = 0; ni < 8; ++ni)
                    mma_f16(acc[mi][ni], a[mi], b[ni]);
        }
        __syncthreads();
    }

#pragma unroll
    for (int mi = 0; mi < 4; ++mi) {
        int row = tm + wy * 64 + mi * 16 + gid;
#pragma unroll
        for (int ni = 0; ni < 8; ++ni) {
            int col = tn + wx * 64 + ni * 8 + tig * 2;
            float b0 = bias[col], b1 = bias[col + 1];
            if (OUTH) {
                __half* Ch = (__half*)Cv;
                *(uint32_t*)(Ch + (size_t)row * N + col) =
                    f2h2(acc[mi][ni][0] + b0, acc[mi][ni][1] + b1);
                *(uint32_t*)(Ch + (size_t)(row + 8) * N + col) =
                    f2h2(acc[mi][ni][2] + b0, acc[mi][ni][3] + b1);
            } else {
                float* Cf = (float*)Cv;
                float2 o0 = {acc[mi][ni][0] + b0, acc[mi][ni][1] + b1};
                float2 o1 = {acc[mi][ni][2] + b0, acc[mi][ni][3] + b1};
                *(float2*)(Cf + (size_t)row * N + col)       = o0;
                *(float2*)(Cf + (size_t)(row + 8) * N + col) = o1;
            }
        }
    }
}

// ===========================================================================
// Fused attention v3: fp16 qkv source, cp.async K/Q loads, 3-stage K ring.
// CTA = (q-tile of 128 rows, bh), 256 threads, 4x2 warp layout.
// ===========================================================================
#define FST 68
__global__ void __launch_bounds__(256) attn_fused(
    const float* __restrict__ rs_ptr, float* __restrict__ attn)
{
    extern __shared__ uint32_t sm[];
    const uint32_t smb = (uint32_t)__cvta_generic_to_shared(sm);
    uint32_t* Qs = sm;                       // 4096 w
    uint32_t* Ks = sm + 4096;                // 3 x 4096 w
    uint32_t* Vs = sm + 16384;               // 2 x 4352 w
    float* pk_all = (float*)(sm + 25088);    // 2048
    float* pq     = (float*)(sm + 27136);    // 128
    float* m_all  = (float*)(sm + 27264);    // 4096
    float* s_all  = (float*)(sm + 31360);    // 4096
    float* Mrow   = (float*)(sm + 35456);    // 128
    float* Irow   = (float*)(sm + 35584);    // 128

    const int tid = threadIdx.x, wid = tid >> 5, lane = tid & 31;
    const int gid = lane >> 2, tig = lane & 3;
    const int wy = wid >> 1, wx = wid & 1;
    const int bh = blockIdx.y, b = bh >> 4, h = bh & 15;
    const int tm = blockIdx.x * 128;
    const float rs = *rs_ptr;

    const int ar = tid >> 1, ah = tid & 1;

#define ISSUE_Q() do {                                                       \
    const __half* _qg = g_qkvh + (size_t)(b * L_SZ + tm + ar) * E3_SZ        \
                        + h * 64 + ah * 32;                                  \
    uint32_t _qd = smb + ((ar * 32) << 2);                                   \
    _Pragma("unroll")                                                        \
    for (int cc = 0; cc < 4; ++cc) {                                         \
        int g = ah * 4 + cc;                                                 \
        cp16(_qd + (((g ^ (ar & 7)) << 2) << 2), _qg + cc * 8);              \
    }                                                                        \
} while (0)

#define ISSUE_K(j, s) do {                                                   \
    const __half* _kg = g_qkvh + (size_t)(b * L_SZ + (j) * 128 + ar) * E3_SZ \
                        + D_SZ + h * 64 + ah * 32;                           \
    uint32_t _kd = smb + ((4096 + (s) * 4096 + ar * 32) << 2);               \
    _Pragma("unroll")                                                        \
    for (int cc = 0; cc < 4; ++cc) {                                         \
        int g = ah * 4 + cc;                                                 \
        cp16(_kd + (((g ^ (ar & 7)) << 2) << 2), _kg + cc * 8);              \
    }                                                                        \
} while (0)

#define LOAD_V(j, s) do {                                                    \
    int _kp = tid & 63, _dg = tid >> 6;                                      \
    const __half* _vp = g_qkvh + (size_t)(b * L_SZ + (j) * 128 + 2 * _kp)    \
                        * E3_SZ + 2 * D_SZ + h * 64 + _dg * 16;              \
    uint4 _r0 = *(const uint4*)_vp;                                          \
    uint4 _r1 = *(const uint4*)(_vp + E3_SZ);                                \
    uint4 _r2 = *(const uint4*)(_vp + 8);                                    \
    uint4 _r3 = *(const uint4*)(_vp + E3_SZ + 8);                            \
    uint32_t* _vd = Vs + (s) * 4352 + _kp;                                   \
    const unsigned short* _a0 = (const unsigned short*)&_r0;                 \
    const unsigned short* _a1 = (const unsigned short*)&_r1;                 \
    const unsigned short* _a2 = (const unsigned short*)&_r2;                 \
    const unsigned short* _a3 = (const unsigned short*)&_r3;                 \
    _Pragma("unroll")                                                        \
    for (int i = 0; i < 8; ++i) {                                            \
        _vd[(_dg * 16 + i) * FST]                                            \
            = (uint32_t)_a0[i] | ((uint32_t)_a1[i] << 16);                   \
        _vd[(_dg * 16 + 8 + i) * FST]                                        \
            = (uint32_t)_a2[i] | ((uint32_t)_a3[i] << 16);                   \
    }                                                                        \
} while (0)

// QK mma for this warp's 32x64 sub-tile + phase bias. acc[2][8][4].
#define QK_TILE(s, jt) do {                                                  \
    _Pragma("unroll")                                                        \
    for (int i = 0; i < 2; ++i)                                              \
        _Pragma("unroll")                                                    \
        for (int n = 0; n < 8; ++n)                                          \
            _Pragma("unroll")                                                \
            for (int v = 0; v < 4; ++v) acc[i][n][v] = 0.f;                  \
    _Pragma("unroll")                                                        \
    for (int j4 = 0; j4 < 4; ++j4) {                                         \
        const int c1 = ((2 * j4) ^ gid) << 2, c2 = ((2 * j4 + 1) ^ gid) << 2;\
        uint32_t a[2][4], bb[8][2];                                          \
        _Pragma("unroll")                                                    \
        for (int mi = 0; mi < 2; ++mi) {                                     \
            int r0 = wy * 32 + mi * 16 + gid;                                \
            const uint32_t* p0 = Qs + r0 * 32 + tig;                         \
            a[mi][0] = p0[c1]; a[mi][1] = p0[256 + c1];                      \
            a[mi][2] = p0[c2]; a[mi][3] = p0[256 + c2];                      \
        }                                                                    \
        _Pragma("unroll")                                                    \
        for (int ni = 0; ni < 8; ++ni) {                                     \
            int c0 = wx * 64 + ni * 8 + gid;                                 \
            const uint32_t* q = Ks + (s) * 4096 + c0 * 32 + tig;             \
            bb[ni][0] = q[c1]; bb[ni][1] = q[c2];                            \
        }                                                                    \
        _Pragma("unroll")                                                    \
        for (int mi = 0; mi < 2; ++mi)                                       \
            _Pragma("unroll")                                                \
            for (int ni = 0; ni < 8; ++ni)                                   \
                mma_f16(acc[mi][ni], a[mi], bb[ni]);                         \
    }                                                                        \
    _Pragma("unroll")                                                        \
    for (int mi = 0; mi < 2; ++mi) {                                         \
        int r0 = wy * 32 + mi * 16 + gid;                                    \
        float pq0 = pq[r0], pq1 = pq[r0 + 8];                                \
        _Pragma("unroll")                                                    \
        for (int ni = 0; ni < 8; ++ni) {                                     \
            int c0f = wx * 64 + ni * 8 + tig * 2;                            \
            float k0 = pk_all[(jt) * 128 + c0f];                             \
            float k1 = pk_all[(jt) * 128 + c0f + 1];                         \
            float d00 = pq0 - k0, d01 = pq0 - k1;                            \
            float d10 = pq1 - k0, d11 = pq1 - k1;                            \
            acc[mi][ni][0] = acc[mi][ni][0] * 0.125f - rs * d00 * d00;       \
            acc[mi][ni][1] = acc[mi][ni][1] * 0.125f - rs * d01 * d01;       \
            acc[mi][ni][2] = acc[mi][ni][2] * 0.125f - rs * d10 * d10;       \
            acc[mi][ni][3] = acc[mi][ni][3] * 0.125f - rs * d11 * d11;       \
        }                                                                    \
    }                                                                        \
} while (0)

    float acc[2][8][4];

    // ===================== Pass A: stats only =====================
    ISSUE_Q();
    ISSUE_K(0, 0);
    CP_COMMIT();
    ISSUE_K(1, 1);
    CP_COMMIT();
    if (tid < 128) pq[tid] = g_phase[(size_t)bh * L_SZ + tm + tid];
#pragma unroll
    for (int i = 0; i < 8; ++i)
        pk_all[tid + i * 256] = g_phase[(size_t)bh * L_SZ + tid + i * 256];

    for (int j = 0; j < 16; ++j) {
        if (j < 15) { asm volatile("cp.async.wait_group 1;" ::: "memory"); }
        else        { asm volatile("cp.async.wait_group 0;" ::: "memory"); }
        __syncthreads();
        QK_TILE(j % 3, j);
#pragma unroll
        for (int mi = 0; mi < 2; ++mi) {
            float mx0 = NEG_INF, mx1 = NEG_INF;
#pragma unroll
            for (int ni = 0; ni < 8; ++ni) {
                mx0 = fmaxf(mx0, fmaxf(acc[mi][ni][0], acc[mi][ni][1]));
                mx1 = fmaxf(mx1, fmaxf(acc[mi][ni][2], acc[mi][ni][3]));
            }
            mx0 = fmaxf(mx0, __shfl_xor_sync(0xffffffff, mx0, 1));
            mx0 = fmaxf(mx0, __shfl_xor_sync(0xffffffff, mx0, 2));
            mx1 = fmaxf(mx1, __shfl_xor_sync(0xffffffff, mx1, 1));
            mx1 = fmaxf(mx1, __shfl_xor_sync(0xffffffff, mx1, 2));
            float s0 = 0.f, s1 = 0.f;
#pragma unroll
            for (int ni = 0; ni < 8; ++ni) {
                s0 += __expf(acc[mi][ni][0] - mx0) + __expf(acc[mi][ni][1] - mx0);
                s1 += __expf(acc[mi][ni][2] - mx1) + __expf(acc[mi][ni][3] - mx1);
            }
            s0 += __shfl_xor_sync(0xffffffff, s0, 1);
            s0 += __shfl_xor_sync(0xffffffff, s0, 2);
            s1 += __shfl_xor_sync(0xffffffff, s1, 1);
            s1 += __shfl_xor_sync(0xffffffff, s1, 2);
            if (tig == 0) {
                int r0 = wy * 32 + mi * 16 + gid;
                int slot = (j * 2 + wx) * 128;
                m_all[slot + r0]     = mx0;
                s_all[slot + r0]     = s0;
                m_all[slot + r0 + 8] = mx1;
                s_all[slot + r0 + 8] = s1;
            }
        }
        if (j + 2 < 16) { ISSUE_K(j + 2, (j + 2) % 3); CP_COMMIT(); }
    }
    __syncthreads();

    if (tid < 128) {
        float M = NEG_INF;
#pragma unroll
        for (int s = 0; s < 32; ++s) M = fmaxf(M, m_all[s * 128 + tid]);
        float S = 0.f;
#pragma unroll
        for (int s = 0; s < 32; ++s)
            S += s_all[s * 128 + tid] * __expf(m_all[s * 128 + tid] - M);
        Mrow[tid] = M;
        Irow[tid] = 1.0f / S;
    }
    __syncthreads();

    // ===================== Pass B: attn write + AV =====================
    float oacc[2][8][4];
#pragma unroll
    for (int i = 0; i < 2; ++i)
#pragma unroll
        for (int j = 0; j < 8; ++j)
#pragma unroll
            for (int v = 0; v < 4; ++v) oacc[i][j][v] = 0.f;

    float Mh[2][2], Ih[2][2];
#pragma unroll
    for (int mi = 0; mi < 2; ++mi) {
        int r0 = wy * 32 + mi * 16 + gid;
        Mh[mi][0] = Mrow[r0];     Ih[mi][0] = Irow[r0];
        Mh[mi][1] = Mrow[r0 + 8]; Ih[mi][1] = Irow[r0 + 8];
    }

    ISSUE_K(0, 0);
    CP_COMMIT();
    ISSUE_K(1, 1);
    CP_COMMIT();
    LOAD_V(0, 0);

    for (int j = 0; j < 16; ++j) {
        if (j < 15) { asm volatile("cp.async.wait_group 1;" ::: "memory"); }
        else        { asm volatile("cp.async.wait_group 0;" ::: "memory"); }
        __syncthreads();
        if (j + 1 < 16) LOAD_V(j + 1, (j + 1) & 1);
        QK_TILE(j % 3, j);

        // p = exp(s - M) * invS in registers; write fp32 attn
#pragma unroll
        for (int mi = 0; mi < 2; ++mi) {
            int r0 = wy * 32 + mi * 16 + gid;
            float M0 = Mh[mi][0], I0 = Ih[mi][0];
            float M1 = Mh[mi][1], I1 = Ih[mi][1];
            float* arow = attn + ((size_t)(bh * L_SZ + tm + r0)) * L_SZ + j * 128;
#pragma unroll
            for (int ni = 0; ni < 8; ++ni) {
                int c0f = wx * 64 + ni * 8 + tig * 2;
                float p00 = __expf(acc[mi][ni][0] - M0) * I0;
                float p01 = __expf(acc[mi][ni][1] - M0) * I0;
                float p10 = __expf(acc[mi][ni][2] - M1) * I1;
                float p11 = __expf(acc[mi][ni][3] - M1) * I1;
                acc[mi][ni][0] = p00; acc[mi][ni][1] = p01;
                acc[mi][ni][2] = p10; acc[mi][ni][3] = p11;
                *(float2*)(arow + c0f)            = make_float2(p00, p01);
                *(float2*)(arow + 8 * L_SZ + c0f) = make_float2(p10, p11);
            }
        }

        // AV mma: A-fragments from registers (flash-v2 reuse)
        const uint32_t* vsb = Vs + (j & 1) * 4352;
#pragma unroll
        for (int ss = 0; ss < 4; ++ss) {
            const int kw = wx * 32 + ss * 8;
            uint32_t a[2][4], bb[8][2];
#pragma unroll
            for (int mi = 0; mi < 2; ++mi) {
                a[mi][0] = f2h2(acc[mi][2 * ss][0],     acc[mi][2 * ss][1]);
                a[mi][1] = f2h2(acc[mi][2 * ss][2],     acc[mi][2 * ss][3]);
                a[mi][2] = f2h2(acc[mi][2 * ss + 1][0], acc[mi][2 * ss + 1][1]);
                a[mi][3] = f2h2(acc[mi][2 * ss + 1][2], acc[mi][2 * ss + 1][3]);
            }
#pragma unroll
            for (int ni2 = 0; ni2 < 8; ++ni2) {
                int d = ni2 * 8 + gid;
                bb[ni2][0] = vsb[d * FST + kw + tig];
                bb[ni2][1] = vsb[d * FST + kw + 4 + tig];
            }
#pragma unroll
            for (int mi = 0; mi < 2; ++mi)
#pragma unroll
                for (int ni2 = 0; ni2 < 8; ++ni2)
                    mma_f16(oacc[mi][ni2], a[mi], bb[ni2]);
        }
        if (j + 2 < 16) { ISSUE_K(j + 2, (j + 2) % 3); CP_COMMIT(); }
    }
    __syncthreads();

    // O reduction across wx pairs (reuse Ks region), then epilogue
    float* Ored = (float*)(sm + 4096);
    if (wx == 1) {
#pragma unroll
        for (int mi = 0; mi < 2; ++mi) {
            int rl = wy * 32 + mi * 16 + gid;
#pragma unroll
            for (int ni2 = 0; ni2 < 8; ++ni2) {
                int col = ni2 * 8 + tig * 2;
                Ored[rl * 65 + col]           = oacc[mi][ni2][0];
                Ored[rl * 65 + col + 1]       = oacc[mi][ni2][1];
                Ored[(rl + 8) * 65 + col]     = oacc[mi][ni2][2];
                Ored[(rl + 8) * 65 + col + 1] = oacc[mi][ni2][3];
            }
        }
    }
    __syncthreads();
    if (wx == 0) {
#pragma unroll
        for (int mi = 0; mi < 2; ++mi) {
            int rl = wy * 32 + mi * 16 + gid;
            int row = tm + rl;
#pragma unroll
            for (int ni2 = 0; ni2 < 8; ++ni2) {
                int col = ni2 * 8 + tig * 2;
                float2 o0 = {oacc[mi][ni2][0] + Ored[rl * 65 + col],
                             oacc[mi][ni2][1] + Ored[rl * 65 + col + 1]};
                float2 o1 = {oacc[mi][ni2][2] + Ored[(rl + 8) * 65 + col],
                             oacc[mi][ni2][3] + Ored[(rl + 8) * 65 + col + 1]};
                *(float2*)(g_o + (size_t)(b * L_SZ + row) * D_SZ + h * 64 + col)     = o0;
                *(float2*)(g_o + (size_t)(b * L_SZ + row + 8) * D_SZ + h * 64 + col) = o1;
            }
        }
    }
}

// ---------------------------------------------------------------------------
// phase_val[bh, l] = tanh(ps * (x[b,l,:] . phase_w[h,:] + phase_b[h]))
// ---------------------------------------------------------------------------
__global__ __launch_bounds__(512) void phase_kernel(
    const float* __restrict__ x, const float* __restrict__ pw,
    const float* __restrict__ pb, const float* __restrict__ ps_ptr)
{
    const int bl = blockIdx.x;
    const int b  = bl >> 11;
    const int l  = bl & 2047;
    __shared__ float xs[1024];
    const int tid = threadIdx.x;
    for (int i = tid; i < 1024; i += 512) xs[i] = x[(size_t)bl * 1024 + i];
    __syncthreads();
    const int h = tid >> 5, lane = tid & 31;
    float s = 0.f;
    const float* w = pw + (size_t)h * 1024;
    for (int d = lane; d < 1024; d += 32) s += xs[d] * w[d];
#pragma unroll
    for (int o = 16; o; o >>= 1) s += __shfl_xor_sync(0xffffffff, s, o);
    if (lane == 0) {
        float ps = *ps_ptr;
        g_phase[(size_t)(b * H_SZ + h) * L_SZ + l] = tanhf(ps * (s + pb[h]));
    }
}

// ---------------------------------------------------------------------------
extern "C" void kernel_launch(void* const* d_in, const int* in_sizes, int n_in,
                              void* d_out, int out_size)
{
    const float* x      = (const float*)d_in[0];
    const float* qkv_w  = (const float*)d_in[1];
    const float* qkv_b  = (const float*)d_in[2];
    const float* out_w  = (const float*)d_in[3];
    const float* out_b  = (const float*)d_in[4];
    const float* ph_w   = (const float*)d_in[5];
    const float* ph_b   = (const float*)d_in[6];
    const float* rs_ptr = (const float*)d_in[7];
    const float* ps_ptr = (const float*)d_in[8];

    float* out_proj = (float*)d_out;                       // [2,2048,1024]
    float* attn     = out_proj + (size_t)MTOK * D_SZ;      // [2,16,2048,2048]

    __half* qkvh_ptr;
    float*  o_ptr;
    cudaGetSymbolAddress((void**)&qkvh_ptr, g_qkvh);
    cudaGetSymbolAddress((void**)&o_ptr,    g_o);

    const int SMEM_GEMM  = 2 * 12288 * 4;    // 98304
    const int SMEM_ATTN  = 35712 * 4;        // 142848

    cudaFuncSetAttribute(gemm_mma<1>, cudaFuncAttributeMaxDynamicSharedMemorySize, SMEM_GEMM);
    cudaFuncSetAttribute(gemm_mma<0>, cudaFuncAttributeMaxDynamicSharedMemorySize, SMEM_GEMM);
    cudaFuncSetAttribute(attn_fused,  cudaFuncAttributeMaxDynamicSharedMemorySize, SMEM_ATTN);

    // 1) fused QKV projection -> fp16 qkv
    gemm_mma<1><<<dim3(E3_SZ / 256, MTOK / 128), 256, SMEM_GEMM>>>(
        x, qkv_w, qkv_b, qkvh_ptr, E3_SZ, D_SZ);

    // 2) per-head phase values
    phase_kernel<<<MTOK, 512>>>(x, ph_w, ph_b, ps_ptr);

    // 3) fused scores + softmax + attn write + AV (cp.async K/Q, fp16 V)
    attn_fused<<<dim3(L_SZ / 128, BH_SZ), 256, SMEM_ATTN>>>(rs_ptr, attn);

    // 4) output projection (fp32 out)
    gemm_mma<0><<<dim3(D_SZ / 256, MTOK / 128), 256, SMEM_GEMM>>>(
        o_ptr, out_w, out_b, out_proj, D_SZ, D_SZ);
}